// round 1
// baseline (speedup 1.0000x reference)
#include <cuda_runtime.h>
#include <math.h>

// Problem dims (fixed by the reference)
#define Bv   4
#define Nv   4096
#define Dv   512
#define Hv   8
#define DHv  64
#define Mv   128
#define BNv  (Bv*Nv)       // 16384 rows
#define Rv   (BNv*Hv)      // 131072 (b,n,h) rows
#define M2v  (2*Mv)        // 256

#define DN_CONST    0.35355339059327373f   // 64^-0.25
#define RATIO_CONST 0.08838834764831845f   // 1/sqrt(128)

// ---------------- scratch (device globals: no allocation allowed) ----------
__device__ float g_value[(size_t)BNv*Dv];   // [bn][h*64+dh]
__device__ float g_pproj[(size_t)BNv*Dv];   // [r=bn*8+h][64]
__device__ float g_sproj[(size_t)BNv*Dv];
__device__ float g_av   [(size_t)BNv*Dv];
__device__ float g_norms[(size_t)Rv];
__device__ float g_kvs  [(size_t)Bv*Hv*M2v*DHv];   // [bh][m2][dh]
// fallback q'/k' scratch if d_out only holds the first tuple element
__device__ float g_qp[(size_t)Rv*M2v];
__device__ float g_kp[(size_t)Rv*M2v];

// ---------------- 128x128 SGEMM tile, K=512, N=512, row-major --------------
__device__ __forceinline__ void sgemm_512(const float* __restrict__ A,
                                          const float* __restrict__ W,
                                          float* __restrict__ C)
{
    __shared__ float As[8][128];
    __shared__ float Bs[8][128];
    const int tid = threadIdx.x;
    const int tx = tid & 15;          // col group (16 x 8)
    const int ty = tid >> 4;          // row group (16 x 8)
    const int r0 = blockIdx.y * 128;
    const int c0 = blockIdx.x * 128;

    const int arow = tid >> 1;        // 0..127
    const int akp  = (tid & 1) * 4;   // 0 or 4
    const int bi   = tid >> 5;        // 0..7
    const int bj   = (tid & 31) * 4;  // 0..124

    float acc[8][8];
#pragma unroll
    for (int i = 0; i < 8; i++)
#pragma unroll
        for (int j = 0; j < 8; j++) acc[i][j] = 0.0f;

    for (int kk = 0; kk < 512; kk += 8) {
        float4 a4 = *(const float4*)(A + (size_t)(r0 + arow) * 512 + kk + akp);
        float4 b4 = *(const float4*)(W + (size_t)(kk + bi) * 512 + c0 + bj);
        __syncthreads();
        As[akp + 0][arow] = a4.x;
        As[akp + 1][arow] = a4.y;
        As[akp + 2][arow] = a4.z;
        As[akp + 3][arow] = a4.w;
        *(float4*)&Bs[bi][bj] = b4;
        __syncthreads();
#pragma unroll
        for (int k = 0; k < 8; k++) {
            float a[8], b[8];
            *(float4*)(a)     = *(const float4*)&As[k][ty * 8];
            *(float4*)(a + 4) = *(const float4*)&As[k][ty * 8 + 4];
            *(float4*)(b)     = *(const float4*)&Bs[k][tx * 8];
            *(float4*)(b + 4) = *(const float4*)&Bs[k][tx * 8 + 4];
#pragma unroll
            for (int i = 0; i < 8; i++)
#pragma unroll
                for (int j = 0; j < 8; j++)
                    acc[i][j] = fmaf(a[i], b[j], acc[i][j]);
        }
    }
#pragma unroll
    for (int i = 0; i < 8; i++) {
        float* crow = C + (size_t)(r0 + ty * 8 + i) * 512 + c0 + tx * 8;
        *(float4*)(crow)     = *(float4*)&acc[i][0];
        *(float4*)(crow + 4) = *(float4*)&acc[i][4];
    }
}

// z=0: value = src@Wv ; z=1: pproj = pos@Wp ; z=2: sproj = slopes@Wp
__global__ __launch_bounds__(256)
void proj_gemm_kernel(const float* __restrict__ src,
                      const float* __restrict__ pos,
                      const float* __restrict__ slopes,
                      const float* __restrict__ Wv,
                      const float* __restrict__ Wp)
{
    const float* A; const float* W; float* C;
    if (blockIdx.z == 0)      { A = src;    W = Wv; C = g_value; }
    else if (blockIdx.z == 1) { A = pos;    W = Wp; C = g_pproj; }
    else                      { A = slopes; W = Wp; C = g_sproj; }
    sgemm_512(A, W, C);
}

__global__ __launch_bounds__(256)
void out_gemm_kernel(const float* __restrict__ Wout, float* __restrict__ out)
{
    sgemm_512(g_av, Wout, out);
}

// ---------------- norms (+ zero g_kvs for the atomic reduction) ------------
__global__ __launch_bounds__(256)
void norms_kernel()
{
    const int t = blockIdx.x * 256 + threadIdx.x;   // 131072 threads total
    // zero kvs: 524288 floats == 131072 float4, exact
    ((float4*)g_kvs)[t] = make_float4(0.f, 0.f, 0.f, 0.f);

    const float4* sp = (const float4*)(g_sproj + (size_t)t * 64);
    float acc = 0.0f;
#pragma unroll
    for (int i = 0; i < 16; i++) {
        float4 v = sp[i];
        acc = fmaf(v.x, v.x, acc);
        acc = fmaf(v.y, v.y, acc);
        acc = fmaf(v.z, v.z, acc);
        acc = fmaf(v.w, v.w, acc);
    }
    g_norms[t] = sqrtf(acc) * (1.0f / (float)Nv);
}

// ---------------- fourier features: GEMM [R,64]x[64,128] + sincos ----------
// z=0 -> q' from pproj ; z=1 -> k' from pproj + off*sproj
__global__ __launch_bounds__(256)
void fourier_kernel(const float* __restrict__ proj,
                    const float* __restrict__ scale,
                    const float* __restrict__ offs,
                    float* __restrict__ outq,
                    float* __restrict__ outk)
{
    __shared__ float As[8][128];   // [d][row]
    __shared__ float Ps[8][128];   // [d][m]
    const int tid = threadIdx.x;
    const int tx = tid & 15;
    const int ty = tid >> 4;
    const int r0 = blockIdx.y * 128;
    const bool is_k = (blockIdx.z != 0);
    float* outp = is_k ? outk : outq;

    const int arow = tid >> 1;
    const int akp  = (tid & 1) * 4;
    const int r    = r0 + arow;
    const int h    = r & 7;
    const float sc = scale[h] * DN_CONST;
    const float of = offs[h];

    float acc[8][8];
#pragma unroll
    for (int i = 0; i < 8; i++)
#pragma unroll
        for (int j = 0; j < 8; j++) acc[i][j] = 0.0f;

    for (int kk = 0; kk < 64; kk += 8) {
        float4 p4 = *(const float4*)(g_pproj + (size_t)r * 64 + kk + akp);
        float4 x4;
        if (is_k) {
            float4 s4 = *(const float4*)(g_sproj + (size_t)r * 64 + kk + akp);
            x4.x = sc * fmaf(of, s4.x, p4.x);
            x4.y = sc * fmaf(of, s4.y, p4.y);
            x4.z = sc * fmaf(of, s4.z, p4.z);
            x4.w = sc * fmaf(of, s4.w, p4.w);
        } else {
            x4.x = sc * p4.x; x4.y = sc * p4.y; x4.z = sc * p4.z; x4.w = sc * p4.w;
        }
        // proj tile: Ps[d][m] = proj[m][d]
        float4 pr4 = *(const float4*)(proj + (size_t)arow * 64 + kk + akp);
        __syncthreads();
        As[akp + 0][arow] = x4.x;
        As[akp + 1][arow] = x4.y;
        As[akp + 2][arow] = x4.z;
        As[akp + 3][arow] = x4.w;
        Ps[akp + 0][arow] = pr4.x;
        Ps[akp + 1][arow] = pr4.y;
        Ps[akp + 2][arow] = pr4.z;
        Ps[akp + 3][arow] = pr4.w;
        __syncthreads();
#pragma unroll
        for (int k = 0; k < 8; k++) {
            float a[8], b[8];
            *(float4*)(a)     = *(const float4*)&As[k][ty * 8];
            *(float4*)(a + 4) = *(const float4*)&As[k][ty * 8 + 4];
            *(float4*)(b)     = *(const float4*)&Ps[k][tx * 8];
            *(float4*)(b + 4) = *(const float4*)&Ps[k][tx * 8 + 4];
#pragma unroll
            for (int i = 0; i < 8; i++)
#pragma unroll
                for (int j = 0; j < 8; j++)
                    acc[i][j] = fmaf(a[i], b[j], acc[i][j]);
        }
    }
    // epilogue: [ratio*sin(dd) | ratio*cos(dd)]
#pragma unroll
    for (int i = 0; i < 8; i++) {
        const int rr = r0 + ty * 8 + i;
        float* orow = outp + (size_t)rr * 256;
        float s[8], c[8];
#pragma unroll
        for (int j = 0; j < 8; j++) {
            sincosf(acc[i][j], &s[j], &c[j]);
            s[j] *= RATIO_CONST;
            c[j] *= RATIO_CONST;
        }
        *(float4*)(orow + tx * 8)           = *(float4*)&s[0];
        *(float4*)(orow + tx * 8 + 4)       = *(float4*)&s[4];
        *(float4*)(orow + 128 + tx * 8)     = *(float4*)&c[0];
        *(float4*)(orow + 128 + tx * 8 + 4) = *(float4*)&c[4];
    }
}

// ---------------- kvs: per (b,h) [256 x 4096] x [4096 x 64], split-K -------
__global__ __launch_bounds__(256)
void kvs_kernel(const float* __restrict__ kprime)
{
    __shared__ float Ks[8][256];   // [n][m2]
    __shared__ float Vs[8][64];    // [n][dh]
    const int tid = threadIdx.x;
    const int bh = blockIdx.y;          // 0..31
    const int b = bh >> 3, h = bh & 7;
    const int n0 = blockIdx.x * 512;    // 8 chunks of 512
    const int tx = tid & 7;             // dh group (8 x 8)
    const int ty = tid >> 3;            // m group (32 x 8)

    const int kni = tid >> 6;           // 0..3
    const int km4 = (tid & 63) * 4;     // m offset
    const int vni = tid >> 4;           // 0..7 (tid<128)
    const int vd4 = (tid & 15) * 4;

    float acc[8][8];
#pragma unroll
    for (int i = 0; i < 8; i++)
#pragma unroll
        for (int j = 0; j < 8; j++) acc[i][j] = 0.0f;

    for (int nn = 0; nn < 512; nn += 8) {
        const size_t nbase = (size_t)(b * Nv + n0 + nn);
        float4 k0 = *(const float4*)(kprime + ((nbase + kni)     * 8 + h) * 256 + km4);
        float4 k1 = *(const float4*)(kprime + ((nbase + kni + 4) * 8 + h) * 256 + km4);
        float4 v0 = make_float4(0.f, 0.f, 0.f, 0.f);
        if (tid < 128)
            v0 = *(const float4*)(g_value + (nbase + vni) * 512 + h * 64 + vd4);
        __syncthreads();
        *(float4*)&Ks[kni][km4]     = k0;
        *(float4*)&Ks[kni + 4][km4] = k1;
        if (tid < 128) *(float4*)&Vs[vni][vd4] = v0;
        __syncthreads();
#pragma unroll
        for (int ni = 0; ni < 8; ni++) {
            float a[8], v[8];
            *(float4*)(a)     = *(const float4*)&Ks[ni][ty * 8];
            *(float4*)(a + 4) = *(const float4*)&Ks[ni][ty * 8 + 4];
            *(float4*)(v)     = *(const float4*)&Vs[ni][tx * 8];
            *(float4*)(v + 4) = *(const float4*)&Vs[ni][tx * 8 + 4];
#pragma unroll
            for (int i = 0; i < 8; i++)
#pragma unroll
                for (int j = 0; j < 8; j++)
                    acc[i][j] = fmaf(a[i], v[j], acc[i][j]);
        }
    }
    float* dst = g_kvs + ((size_t)bh * 256 + ty * 8) * 64 + tx * 8;
#pragma unroll
    for (int i = 0; i < 8; i++)
#pragma unroll
        for (int j = 0; j < 8; j++)
            atomicAdd(dst + (size_t)i * 64 + j, acc[i][j]);
}

// ---------------- av: per (b,h) [4096 x 256] x [256 x 64], norm epilogue ---
__global__ __launch_bounds__(256)
void av_kernel(const float* __restrict__ qprime)
{
    __shared__ float As[16][128];   // [k][row]
    __shared__ float Bs[16][64];    // [k][dh]
    const int tid = threadIdx.x;
    const int bh = blockIdx.y;
    const int b = bh >> 3, h = bh & 7;
    const int n0 = blockIdx.x * 128;
    const int tx = tid & 15;        // dh group (16 x 4)
    const int ty = tid >> 4;        // row group (16 x 8)

    const int ar  = tid >> 2;          // 0..63
    const int ak4 = (tid & 3) * 4;     // k offset
    const int bi  = tid >> 4;          // 0..15
    const int bj4 = (tid & 15) * 4;

    float acc[8][4];
#pragma unroll
    for (int i = 0; i < 8; i++)
#pragma unroll
        for (int j = 0; j < 4; j++) acc[i][j] = 0.0f;

    for (int kk = 0; kk < 256; kk += 16) {
        float4 a0 = *(const float4*)(qprime + ((size_t)(b * Nv + n0 + ar)      * 8 + h) * 256 + kk + ak4);
        float4 a1 = *(const float4*)(qprime + ((size_t)(b * Nv + n0 + ar + 64) * 8 + h) * 256 + kk + ak4);
        float4 b0 = *(const float4*)(g_kvs + ((size_t)bh * 256 + kk + bi) * 64 + bj4);
        __syncthreads();
        As[ak4 + 0][ar] = a0.x; As[ak4 + 1][ar] = a0.y;
        As[ak4 + 2][ar] = a0.z; As[ak4 + 3][ar] = a0.w;
        As[ak4 + 0][ar + 64] = a1.x; As[ak4 + 1][ar + 64] = a1.y;
        As[ak4 + 2][ar + 64] = a1.z; As[ak4 + 3][ar + 64] = a1.w;
        *(float4*)&Bs[bi][bj4] = b0;
        __syncthreads();
#pragma unroll
        for (int k = 0; k < 16; k++) {
            float a[8], bb[4];
            *(float4*)(a)     = *(const float4*)&As[k][ty * 8];
            *(float4*)(a + 4) = *(const float4*)&As[k][ty * 8 + 4];
            *(float4*)(bb)    = *(const float4*)&Bs[k][tx * 4];
#pragma unroll
            for (int i = 0; i < 8; i++)
#pragma unroll
                for (int j = 0; j < 4; j++)
                    acc[i][j] = fmaf(a[i], bb[j], acc[i][j]);
        }
    }
#pragma unroll
    for (int i = 0; i < 8; i++) {
        const int n = n0 + ty * 8 + i;
        const float nm = g_norms[(size_t)(b * Nv + n) * 8 + h];
        float4 v;
        v.x = acc[i][0] * nm; v.y = acc[i][1] * nm;
        v.z = acc[i][2] * nm; v.w = acc[i][3] * nm;
        *(float4*)(g_av + (size_t)(b * Nv + n) * 512 + h * 64 + tx * 4) = v;
    }
}

// ---------------------------------------------------------------------------
extern "C" void kernel_launch(void* const* d_in, const int* in_sizes, int n_in,
                              void* d_out, int out_size)
{
    const float* src    = (const float*)d_in[0];
    const float* pos    = (const float*)d_in[1];
    const float* slopes = (const float*)d_in[2];
    const float* Wv     = (const float*)d_in[3];
    const float* Wp     = (const float*)d_in[4];
    const float* scale  = (const float*)d_in[5];
    const float* offs   = (const float*)d_in[6];
    const float* Wout   = (const float*)d_in[7];
    const float* proj   = (const float*)d_in[8];

    float* out = (float*)d_out;

    // tuple output: (out[BN*D], q'[R*2M], k'[R*2M]) flattened
    const size_t OUT0 = (size_t)BNv * Dv;                 //  8388608
    const size_t QPN  = (size_t)Rv * M2v;                 // 33554432
    float* qdst;
    float* kdst;
    if ((size_t)out_size >= OUT0 + 2 * QPN) {
        qdst = out + OUT0;
        kdst = out + OUT0 + QPN;
    } else {
        void* p;
        cudaGetSymbolAddress(&p, g_qp); qdst = (float*)p;
        cudaGetSymbolAddress(&p, g_kp); kdst = (float*)p;
    }

    proj_gemm_kernel<<<dim3(4, 128, 3), 256>>>(src, pos, slopes, Wv, Wp);
    norms_kernel<<<Rv / 256, 256>>>();                       // also zeros g_kvs
    fourier_kernel<<<dim3(1, Rv / 128, 2), 256>>>(proj, scale, offs, qdst, kdst);
    kvs_kernel<<<dim3(8, Bv * Hv), 256>>>(kdst);
    av_kernel<<<dim3(Nv / 128, Bv * Hv), 256>>>(qdst);
    out_gemm_kernel<<<dim3(4, 128, 1), 256>>>(Wout, out);
}

// round 3
// speedup vs baseline: 1.4431x; 1.4431x over previous
#include <cuda_runtime.h>
#include <cuda_bf16.h>
#include <math.h>
#include <stdint.h>

// Problem dims (fixed by the reference)
#define Bv   4
#define Nv   4096
#define Dv   512
#define Hv   8
#define DHv  64
#define Mv   128
#define BNv  (Bv*Nv)       // 16384 rows
#define Rv   (BNv*Hv)      // 131072 (b,n,h) rows
#define M2v  (2*Mv)        // 256
#define K3   1536          // split K' = 3*512

#define DN_CONST    0.35355339059327373f   // 64^-0.25
#define RATIO_CONST 0.08838834764831845f   // 1/sqrt(128)

// ---------------- scratch (device globals: no allocation allowed) ----------
__device__ float g_value[(size_t)BNv*Dv];   // [bn][h*64+dh]
__device__ float g_pproj[(size_t)BNv*Dv];   // [r=bn*8+h][64]
__device__ float g_sproj[(size_t)BNv*Dv];
__device__ float g_norms[(size_t)Rv];
__device__ float g_kvs  [(size_t)Bv*Hv*M2v*DHv];   // [bh][m2][dh]
// split-transposed weights: [n=512][k'=1536] bf16 (= B^T row-major)
__device__ __nv_bfloat16 g_WvT[(size_t)Dv*K3];
__device__ __nv_bfloat16 g_WpT[(size_t)Dv*K3];
__device__ __nv_bfloat16 g_WoT[(size_t)Dv*K3];
// split A matrices: [m=16384][k'=1536] bf16  ([hi|lo|hi])
__device__ __nv_bfloat16 g_Asp0[(size_t)BNv*K3];
__device__ __nv_bfloat16 g_Asp1[(size_t)BNv*K3];
__device__ __nv_bfloat16 g_Asp2[(size_t)BNv*K3];
__device__ __nv_bfloat16 g_avsp[(size_t)BNv*K3];
// fallback q'/k' scratch if d_out only holds the first tuple element
__device__ float g_qp[(size_t)Rv*M2v];
__device__ float g_kp[(size_t)Rv*M2v];

// =================== HMMA helpers (sm_80-era PTX, valid on sm_103 base) ====
__device__ __forceinline__ void ldsm_x4(uint32_t& r0, uint32_t& r1,
                                        uint32_t& r2, uint32_t& r3, uint32_t addr) {
    asm volatile("ldmatrix.sync.aligned.m8n8.x4.shared.b16 {%0,%1,%2,%3}, [%4];"
                 : "=r"(r0), "=r"(r1), "=r"(r2), "=r"(r3) : "r"(addr));
}

__device__ __forceinline__ void mma16816(float* c, const uint32_t* a,
                                         uint32_t b0, uint32_t b1) {
    asm volatile("mma.sync.aligned.m16n8k16.row.col.f32.bf16.bf16.f32 "
                 "{%0,%1,%2,%3}, {%4,%5,%6,%7}, {%8,%9}, {%0,%1,%2,%3};"
                 : "+f"(c[0]), "+f"(c[1]), "+f"(c[2]), "+f"(c[3])
                 : "r"(a[0]), "r"(a[1]), "r"(a[2]), "r"(a[3]), "r"(b0), "r"(b1));
}

__device__ __forceinline__ void cpa16(uint32_t dst, const void* src) {
    asm volatile("cp.async.cg.shared.global [%0], [%1], 16;"
                 :: "r"(dst), "l"(src));
}

// =================== W transpose + hi/lo split ==============================
// W [512][512] row-major (k, n)  ->  T [n][1536]: [0:512)=hi, [512:1024)=hi, [1024:1536)=lo
__global__ __launch_bounds__(256)
void wsplit_kernel(const float* __restrict__ Wv, const float* __restrict__ Wp,
                   const float* __restrict__ Wo)
{
    const float* W; __nv_bfloat16* T;
    if (blockIdx.z == 0)      { W = Wv; T = g_WvT; }
    else if (blockIdx.z == 1) { W = Wp; T = g_WpT; }
    else                      { W = Wo; T = g_WoT; }
    int idx = blockIdx.x * 256 + threadIdx.x;   // 0..262143
    int k = idx >> 9, n = idx & 511;
    float x = W[idx];
    __nv_bfloat16 hi = __float2bfloat16_rn(x);
    __nv_bfloat16 lo = __float2bfloat16_rn(x - __bfloat162float(hi));
    T[(size_t)n*K3 + k]        = hi;
    T[(size_t)n*K3 + 512 + k]  = hi;
    T[(size_t)n*K3 + 1024 + k] = lo;
}

// A [16384][512] fp32 -> Asp [16384][1536] bf16: [hi|lo|hi]
__global__ __launch_bounds__(256)
void asplit_kernel(const float* __restrict__ A0, const float* __restrict__ A1,
                   const float* __restrict__ A2)
{
    const float* A; __nv_bfloat16* T;
    if (blockIdx.z == 0)      { A = A0; T = g_Asp0; }
    else if (blockIdx.z == 1) { A = A1; T = g_Asp1; }
    else                      { A = A2; T = g_Asp2; }
    size_t idx = (size_t)blockIdx.x * 256 + threadIdx.x;   // 0..8388607
    size_t m = idx >> 9; int k = (int)(idx & 511);
    float x = A[idx];
    __nv_bfloat16 hi = __float2bfloat16_rn(x);
    __nv_bfloat16 lo = __float2bfloat16_rn(x - __bfloat162float(hi));
    T[m*K3 + k]        = hi;
    T[m*K3 + 512 + k]  = lo;
    T[m*K3 + 1024 + k] = hi;
}

// =================== HMMA GEMM: C[16384x512] = Asp[16384x1536] * T[512x1536]^T
// Block tile 128x128, 512 thr (4x4 warps, 32x32 warp tile), BK=32, 3 stages.
#define ASTR  40                        // smem row stride (elements): 80B
#define STG_B 20480                     // bytes per stage: A 10240 + B 10240
#define NSTG  3
#define SMEM_GEMM (NSTG*STG_B)

__global__ __launch_bounds__(512)
void hmma_gemm_kernel(const __nv_bfloat16* A0, const __nv_bfloat16* A1, const __nv_bfloat16* A2,
                      const __nv_bfloat16* B0, const __nv_bfloat16* B1, const __nv_bfloat16* B2,
                      float* C0, float* C1, float* C2)
{
    const __nv_bfloat16* A; const __nv_bfloat16* Bt; float* C;
    if (blockIdx.z == 0)      { A = A0; Bt = B0; C = C0; }
    else if (blockIdx.z == 1) { A = A1; Bt = B1; C = C1; }
    else                      { A = A2; Bt = B2; C = C2; }

    extern __shared__ __align__(16) char smem[];
    const uint32_t sbase = (uint32_t)__cvta_generic_to_shared(smem);
    const int tid = threadIdx.x;
    const int lane = tid & 31, wid = tid >> 5;
    const int r0 = blockIdx.y * 128;
    const int n0 = blockIdx.x * 128;
    const int wm = wid >> 2, wn = wid & 3;

    const int lrow = tid >> 2;           // 0..127
    const int lchk = (tid & 3) * 8;      // element offset 0/8/16/24

    float acc[2][4][4];
#pragma unroll
    for (int mi = 0; mi < 2; mi++)
#pragma unroll
        for (int ni = 0; ni < 4; ni++)
#pragma unroll
            for (int q = 0; q < 4; q++) acc[mi][ni][q] = 0.0f;

    // prologue: stages 0,1 <- k-iters 0,1
#pragma unroll
    for (int p = 0; p < 2; p++) {
        uint32_t sA = sbase + p * STG_B + (lrow * ASTR + lchk) * 2;
        cpa16(sA,         A  + (size_t)(r0 + lrow) * K3 + p * 32 + lchk);
        cpa16(sA + 10240, Bt + (size_t)(n0 + lrow) * K3 + p * 32 + lchk);
        asm volatile("cp.async.commit_group;" ::: "memory");
    }

    for (int kt = 0; kt < 48; kt++) {
        asm volatile("cp.async.wait_group 1;" ::: "memory");
        __syncthreads();
        if (kt + 2 < 48) {
            uint32_t sA = sbase + ((kt + 2) % NSTG) * STG_B + (lrow * ASTR + lchk) * 2;
            cpa16(sA,         A  + (size_t)(r0 + lrow) * K3 + (kt + 2) * 32 + lchk);
            cpa16(sA + 10240, Bt + (size_t)(n0 + lrow) * K3 + (kt + 2) * 32 + lchk);
            asm volatile("cp.async.commit_group;" ::: "memory");
        }
        const uint32_t stA = sbase + (kt % NSTG) * STG_B;
        const uint32_t stB = stA + 10240;
#pragma unroll
        for (int ks = 0; ks < 2; ks++) {
            const int ko = ks * 16;
            uint32_t a[2][4], b[2][4];
#pragma unroll
            for (int mi = 0; mi < 2; mi++)
                ldsm_x4(a[mi][0], a[mi][1], a[mi][2], a[mi][3],
                        stA + ((wm * 32 + mi * 16 + (lane & 15)) * ASTR
                               + ko + (lane >> 4) * 8) * 2);
#pragma unroll
            for (int pr = 0; pr < 2; pr++)
                ldsm_x4(b[pr][0], b[pr][1], b[pr][2], b[pr][3],
                        stB + ((wn * 32 + pr * 16 + ((lane >> 4) << 3) + (lane & 7)) * ASTR
                               + ko + ((lane >> 3) & 1) * 8) * 2);
#pragma unroll
            for (int mi = 0; mi < 2; mi++) {
                mma16816(acc[mi][0], a[mi], b[0][0], b[0][1]);
                mma16816(acc[mi][1], a[mi], b[0][2], b[0][3]);
                mma16816(acc[mi][2], a[mi], b[1][0], b[1][1]);
                mma16816(acc[mi][3], a[mi], b[1][2], b[1][3]);
            }
        }
    }

    // epilogue
#pragma unroll
    for (int mi = 0; mi < 2; mi++)
#pragma unroll
        for (int ni = 0; ni < 4; ni++) {
            const int row = r0 + wm * 32 + mi * 16 + (lane >> 2);
            const int col = n0 + wn * 32 + ni * 8 + (lane & 3) * 2;
            float2 v0 = make_float2(acc[mi][ni][0], acc[mi][ni][1]);
            float2 v1 = make_float2(acc[mi][ni][2], acc[mi][ni][3]);
            *(float2*)(C + (size_t)row * 512 + col)       = v0;
            *(float2*)(C + (size_t)(row + 8) * 512 + col) = v1;
        }
}

// ---------------- norms (+ zero g_kvs for the atomic reduction) ------------
__global__ __launch_bounds__(256)
void norms_kernel()
{
    const int t = blockIdx.x * 256 + threadIdx.x;   // 131072 threads total
    ((float4*)g_kvs)[t] = make_float4(0.f, 0.f, 0.f, 0.f);

    const float4* sp = (const float4*)(g_sproj + (size_t)t * 64);
    float acc = 0.0f;
#pragma unroll
    for (int i = 0; i < 16; i++) {
        float4 v = sp[i];
        acc = fmaf(v.x, v.x, acc);
        acc = fmaf(v.y, v.y, acc);
        acc = fmaf(v.z, v.z, acc);
        acc = fmaf(v.w, v.w, acc);
    }
    g_norms[t] = sqrtf(acc) * (1.0f / (float)Nv);
}

// ---------------- fourier features: GEMM [R,64]x[64,128] + sincos ----------
__global__ __launch_bounds__(256)
void fourier_kernel(const float* __restrict__ proj,
                    const float* __restrict__ scale,
                    const float* __restrict__ offs,
                    float* __restrict__ outq,
                    float* __restrict__ outk)
{
    __shared__ float As[8][128];
    __shared__ float Ps[8][128];
    const int tid = threadIdx.x;
    const int tx = tid & 15;
    const int ty = tid >> 4;
    const int r0 = blockIdx.y * 128;
    const bool is_k = (blockIdx.z != 0);
    float* outp = is_k ? outk : outq;

    const int arow = tid >> 1;
    const int akp  = (tid & 1) * 4;
    const int r    = r0 + arow;
    const int h    = r & 7;
    const float sc = scale[h] * DN_CONST;
    const float of = offs[h];

    float acc[8][8];
#pragma unroll
    for (int i = 0; i < 8; i++)
#pragma unroll
        for (int j = 0; j < 8; j++) acc[i][j] = 0.0f;

    for (int kk = 0; kk < 64; kk += 8) {
        float4 p4 = *(const float4*)(g_pproj + (size_t)r * 64 + kk + akp);
        float4 x4;
        if (is_k) {
            float4 s4 = *(const float4*)(g_sproj + (size_t)r * 64 + kk + akp);
            x4.x = sc * fmaf(of, s4.x, p4.x);
            x4.y = sc * fmaf(of, s4.y, p4.y);
            x4.z = sc * fmaf(of, s4.z, p4.z);
            x4.w = sc * fmaf(of, s4.w, p4.w);
        } else {
            x4.x = sc * p4.x; x4.y = sc * p4.y; x4.z = sc * p4.z; x4.w = sc * p4.w;
        }
        float4 pr4 = *(const float4*)(proj + (size_t)arow * 64 + kk + akp);
        __syncthreads();
        As[akp + 0][arow] = x4.x;
        As[akp + 1][arow] = x4.y;
        As[akp + 2][arow] = x4.z;
        As[akp + 3][arow] = x4.w;
        Ps[akp + 0][arow] = pr4.x;
        Ps[akp + 1][arow] = pr4.y;
        Ps[akp + 2][arow] = pr4.z;
        Ps[akp + 3][arow] = pr4.w;
        __syncthreads();
#pragma unroll
        for (int k = 0; k < 8; k++) {
            float a[8], b[8];
            *(float4*)(a)     = *(const float4*)&As[k][ty * 8];
            *(float4*)(a + 4) = *(const float4*)&As[k][ty * 8 + 4];
            *(float4*)(b)     = *(const float4*)&Ps[k][tx * 8];
            *(float4*)(b + 4) = *(const float4*)&Ps[k][tx * 8 + 4];
#pragma unroll
            for (int i = 0; i < 8; i++)
#pragma unroll
                for (int j = 0; j < 8; j++)
                    acc[i][j] = fmaf(a[i], b[j], acc[i][j]);
        }
    }
#pragma unroll
    for (int i = 0; i < 8; i++) {
        const int rr = r0 + ty * 8 + i;
        float* orow = outp + (size_t)rr * 256;
        float s[8], c[8];
#pragma unroll
        for (int j = 0; j < 8; j++) {
            sincosf(acc[i][j], &s[j], &c[j]);
            s[j] *= RATIO_CONST;
            c[j] *= RATIO_CONST;
        }
        *(float4*)(orow + tx * 8)           = *(float4*)&s[0];
        *(float4*)(orow + tx * 8 + 4)       = *(float4*)&s[4];
        *(float4*)(orow + 128 + tx * 8)     = *(float4*)&c[0];
        *(float4*)(orow + 128 + tx * 8 + 4) = *(float4*)&c[4];
    }
}

// ---------------- kvs: per (b,h) [256 x 4096] x [4096 x 64], split-K -------
__global__ __launch_bounds__(256)
void kvs_kernel(const float* __restrict__ kprime)
{
    __shared__ float Ks[8][256];
    __shared__ float Vs[8][64];
    const int tid = threadIdx.x;
    const int bh = blockIdx.y;
    const int b = bh >> 3, h = bh & 7;
    const int n0 = blockIdx.x * 512;
    const int tx = tid & 7;
    const int ty = tid >> 3;

    const int kni = tid >> 6;
    const int km4 = (tid & 63) * 4;
    const int vni = tid >> 4;
    const int vd4 = (tid & 15) * 4;

    float acc[8][8];
#pragma unroll
    for (int i = 0; i < 8; i++)
#pragma unroll
        for (int j = 0; j < 8; j++) acc[i][j] = 0.0f;

    for (int nn = 0; nn < 512; nn += 8) {
        const size_t nbase = (size_t)(b * Nv + n0 + nn);
        float4 k0 = *(const float4*)(kprime + ((nbase + kni)     * 8 + h) * 256 + km4);
        float4 k1 = *(const float4*)(kprime + ((nbase + kni + 4) * 8 + h) * 256 + km4);
        float4 v0 = make_float4(0.f, 0.f, 0.f, 0.f);
        if (tid < 128)
            v0 = *(const float4*)(g_value + (nbase + vni) * 512 + h * 64 + vd4);
        __syncthreads();
        *(float4*)&Ks[kni][km4]     = k0;
        *(float4*)&Ks[kni + 4][km4] = k1;
        if (tid < 128) *(float4*)&Vs[vni][vd4] = v0;
        __syncthreads();
#pragma unroll
        for (int ni = 0; ni < 8; ni++) {
            float a[8], v[8];
            *(float4*)(a)     = *(const float4*)&Ks[ni][ty * 8];
            *(float4*)(a + 4) = *(const float4*)&Ks[ni][ty * 8 + 4];
            *(float4*)(v)     = *(const float4*)&Vs[ni][tx * 8];
            *(float4*)(v + 4) = *(const float4*)&Vs[ni][tx * 8 + 4];
#pragma unroll
            for (int i = 0; i < 8; i++)
#pragma unroll
                for (int j = 0; j < 8; j++)
                    acc[i][j] = fmaf(a[i], v[j], acc[i][j]);
        }
    }
    float* dst = g_kvs + ((size_t)bh * 256 + ty * 8) * 64 + tx * 8;
#pragma unroll
    for (int i = 0; i < 8; i++)
#pragma unroll
        for (int j = 0; j < 8; j++)
            atomicAdd(dst + (size_t)i * 64 + j, acc[i][j]);
}

// ---------------- av: per (b,h) [4096 x 256] x [256 x 64] ------------------
// epilogue: multiply by norm, convert to bf16 hi/lo split into g_avsp.
__global__ __launch_bounds__(256)
void av_kernel(const float* __restrict__ qprime)
{
    __shared__ float As[16][128];
    __shared__ float Bs[16][64];
    const int tid = threadIdx.x;
    const int bh = blockIdx.y;
    const int b = bh >> 3, h = bh & 7;
    const int n0 = blockIdx.x * 128;
    const int tx = tid & 15;
    const int ty = tid >> 4;

    const int ar  = tid >> 2;
    const int ak4 = (tid & 3) * 4;
    const int bi  = tid >> 4;
    const int bj4 = (tid & 15) * 4;

    float acc[8][4];
#pragma unroll
    for (int i = 0; i < 8; i++)
#pragma unroll
        for (int j = 0; j < 4; j++) acc[i][j] = 0.0f;

    for (int kk = 0; kk < 256; kk += 16) {
        float4 a0 = *(const float4*)(qprime + ((size_t)(b * Nv + n0 + ar)      * 8 + h) * 256 + kk + ak4);
        float4 a1 = *(const float4*)(qprime + ((size_t)(b * Nv + n0 + ar + 64) * 8 + h) * 256 + kk + ak4);
        float4 b0 = *(const float4*)(g_kvs + ((size_t)bh * 256 + kk + bi) * 64 + bj4);
        __syncthreads();
        As[ak4 + 0][ar] = a0.x; As[ak4 + 1][ar] = a0.y;
        As[ak4 + 2][ar] = a0.z; As[ak4 + 3][ar] = a0.w;
        As[ak4 + 0][ar + 64] = a1.x; As[ak4 + 1][ar + 64] = a1.y;
        As[ak4 + 2][ar + 64] = a1.z; As[ak4 + 3][ar + 64] = a1.w;
        *(float4*)&Bs[bi][bj4] = b0;
        __syncthreads();
#pragma unroll
        for (int k = 0; k < 16; k++) {
            float a[8], bb[4];
            *(float4*)(a)     = *(const float4*)&As[k][ty * 8];
            *(float4*)(a + 4) = *(const float4*)&As[k][ty * 8 + 4];
            *(float4*)(bb)    = *(const float4*)&Bs[k][tx * 4];
#pragma unroll
            for (int i = 0; i < 8; i++)
#pragma unroll
                for (int j = 0; j < 4; j++)
                    acc[i][j] = fmaf(a[i], bb[j], acc[i][j]);
        }
    }
#pragma unroll
    for (int i = 0; i < 8; i++) {
        const int n = n0 + ty * 8 + i;
        const size_t m = (size_t)(b * Nv + n);
        const float nm = g_norms[m * 8 + h];
        const int kcol = h * 64 + tx * 4;
        __nv_bfloat16 hi4[4], lo4[4];
#pragma unroll
        for (int j = 0; j < 4; j++) {
            float v = acc[i][j] * nm;
            hi4[j] = __float2bfloat16_rn(v);
            lo4[j] = __float2bfloat16_rn(v - __bfloat162float(hi4[j]));
        }
        *(uint2*)(g_avsp + m * K3 + kcol)        = *(uint2*)hi4;
        *(uint2*)(g_avsp + m * K3 + 512 + kcol)  = *(uint2*)lo4;
        *(uint2*)(g_avsp + m * K3 + 1024 + kcol) = *(uint2*)hi4;
    }
}

// ---------------------------------------------------------------------------
extern "C" void kernel_launch(void* const* d_in, const int* in_sizes, int n_in,
                              void* d_out, int out_size)
{
    const float* src    = (const float*)d_in[0];
    const float* pos    = (const float*)d_in[1];
    const float* slopes = (const float*)d_in[2];
    const float* Wv     = (const float*)d_in[3];
    const float* Wp     = (const float*)d_in[4];
    const float* scale  = (const float*)d_in[5];
    const float* offs   = (const float*)d_in[6];
    const float* Wout   = (const float*)d_in[7];
    const float* proj   = (const float*)d_in[8];

    float* out = (float*)d_out;

    void* p;
    float *pvalue, *ppproj, *psproj;
    __nv_bfloat16 *pWvT, *pWpT, *pWoT, *pA0, *pA1, *pA2, *pAv;
    cudaGetSymbolAddress(&p, g_value); pvalue = (float*)p;
    cudaGetSymbolAddress(&p, g_pproj); ppproj = (float*)p;
    cudaGetSymbolAddress(&p, g_sproj); psproj = (float*)p;
    cudaGetSymbolAddress(&p, g_WvT);   pWvT   = (__nv_bfloat16*)p;
    cudaGetSymbolAddress(&p, g_WpT);   pWpT   = (__nv_bfloat16*)p;
    cudaGetSymbolAddress(&p, g_WoT);   pWoT   = (__nv_bfloat16*)p;
    cudaGetSymbolAddress(&p, g_Asp0);  pA0    = (__nv_bfloat16*)p;
    cudaGetSymbolAddress(&p, g_Asp1);  pA1    = (__nv_bfloat16*)p;
    cudaGetSymbolAddress(&p, g_Asp2);  pA2    = (__nv_bfloat16*)p;
    cudaGetSymbolAddress(&p, g_avsp);  pAv    = (__nv_bfloat16*)p;

    // tuple output: (out[BN*D], q'[R*2M], k'[R*2M]) flattened
    const size_t OUT0 = (size_t)BNv * Dv;
    const size_t QPN  = (size_t)Rv * M2v;
    float* qdst;
    float* kdst;
    if ((size_t)out_size >= OUT0 + 2 * QPN) {
        qdst = out + OUT0;
        kdst = out + OUT0 + QPN;
    } else {
        cudaGetSymbolAddress(&p, g_qp); qdst = (float*)p;
        cudaGetSymbolAddress(&p, g_kp); kdst = (float*)p;
    }

    static int smem_set = 0;
    if (!smem_set) {
        cudaFuncSetAttribute(hmma_gemm_kernel,
                             cudaFuncAttributeMaxDynamicSharedMemorySize, SMEM_GEMM);
        smem_set = 1;
    }

    wsplit_kernel<<<dim3(1024, 1, 3), 256>>>(Wv, Wp, Wout);
    asplit_kernel<<<dim3(32768, 1, 3), 256>>>(src, pos, slopes);
    hmma_gemm_kernel<<<dim3(4, 128, 3), 512, SMEM_GEMM>>>(
        pA0, pA1, pA2, pWvT, pWpT, pWpT, pvalue, ppproj, psproj);
    norms_kernel<<<Rv / 256, 256>>>();                       // also zeros g_kvs
    fourier_kernel<<<dim3(1, Rv / 128, 2), 256>>>(proj, scale, offs, qdst, kdst);
    kvs_kernel<<<dim3(8, Bv * Hv), 256>>>(kdst);
    av_kernel<<<dim3(Nv / 128, Bv * Hv), 256>>>(qdst);       // writes g_avsp
    hmma_gemm_kernel<<<dim3(4, 128, 1), 512, SMEM_GEMM>>>(
        pAv, pAv, pAv, pWoT, pWoT, pWoT, out, out, out);
}

// round 4
// speedup vs baseline: 1.4727x; 1.0205x over previous
#include <cuda_runtime.h>
#include <cuda_bf16.h>
#include <math.h>
#include <stdint.h>

// Problem dims (fixed by the reference)
#define Bv   4
#define Nv   4096
#define Dv   512
#define Hv   8
#define DHv  64
#define Mv   128
#define BNv  (Bv*Nv)       // 16384 rows
#define Rv   (BNv*Hv)      // 131072 (b,n,h) rows
#define M2v  (2*Mv)        // 256
#define K3   1536          // split K' = 3*512

#define DN_CONST    0.35355339059327373f   // 64^-0.25
#define RATIO_CONST 0.08838834764831845f   // 1/sqrt(128)

// ---------------- scratch (device globals: no allocation allowed) ----------
__device__ float g_value[(size_t)BNv*Dv];   // [bn][h*64+dh]
__device__ float g_pproj[(size_t)BNv*Dv];   // [r=bn*8+h][64]
__device__ float g_sproj[(size_t)BNv*Dv];
__device__ float g_norms[(size_t)Rv];
__device__ float g_kvs  [(size_t)Bv*Hv*M2v*DHv];   // [bh][m2][dh]
// split-transposed weights: [n=512][k'=1536] bf16 (= B^T row-major)
__device__ __nv_bfloat16 g_WvT[(size_t)Dv*K3];
__device__ __nv_bfloat16 g_WpT[(size_t)Dv*K3];
__device__ __nv_bfloat16 g_WoT[(size_t)Dv*K3];
// split A matrices: [m=16384][k'=1536] bf16  ([hi|lo|hi])
__device__ __nv_bfloat16 g_Asp0[(size_t)BNv*K3];
__device__ __nv_bfloat16 g_Asp1[(size_t)BNv*K3];
__device__ __nv_bfloat16 g_Asp2[(size_t)BNv*K3];
__device__ __nv_bfloat16 g_avsp[(size_t)BNv*K3];
// fallback q'/k' scratch if d_out only holds the first tuple element
__device__ float g_qp[(size_t)Rv*M2v];
__device__ float g_kp[(size_t)Rv*M2v];

// =================== HMMA helpers (sm_80-era PTX, valid on sm_103 base) ====
__device__ __forceinline__ void ldsm_x4(uint32_t& r0, uint32_t& r1,
                                        uint32_t& r2, uint32_t& r3, uint32_t addr) {
    asm volatile("ldmatrix.sync.aligned.m8n8.x4.shared.b16 {%0,%1,%2,%3}, [%4];"
                 : "=r"(r0), "=r"(r1), "=r"(r2), "=r"(r3) : "r"(addr));
}

__device__ __forceinline__ void mma16816(float* c, const uint32_t* a,
                                         uint32_t b0, uint32_t b1) {
    asm volatile("mma.sync.aligned.m16n8k16.row.col.f32.bf16.bf16.f32 "
                 "{%0,%1,%2,%3}, {%4,%5,%6,%7}, {%8,%9}, {%0,%1,%2,%3};"
                 : "+f"(c[0]), "+f"(c[1]), "+f"(c[2]), "+f"(c[3])
                 : "r"(a[0]), "r"(a[1]), "r"(a[2]), "r"(a[3]), "r"(b0), "r"(b1));
}

__device__ __forceinline__ void cpa16(uint32_t dst, const void* src) {
    asm volatile("cp.async.cg.shared.global [%0], [%1], 16;"
                 :: "r"(dst), "l"(src));
}

// =================== W transpose + hi/lo split ==============================
// W [512][512] row-major (k, n)  ->  T [n][1536]: [0:512)=hi, [512:1024)=hi, [1024:1536)=lo
__global__ __launch_bounds__(256)
void wsplit_kernel(const float* __restrict__ Wv, const float* __restrict__ Wp,
                   const float* __restrict__ Wo)
{
    const float* W; __nv_bfloat16* T;
    if (blockIdx.z == 0)      { W = Wv; T = g_WvT; }
    else if (blockIdx.z == 1) { W = Wp; T = g_WpT; }
    else                      { W = Wo; T = g_WoT; }
    int idx = blockIdx.x * 256 + threadIdx.x;   // 0..262143
    int k = idx >> 9, n = idx & 511;
    float x = W[idx];
    __nv_bfloat16 hi = __float2bfloat16_rn(x);
    __nv_bfloat16 lo = __float2bfloat16_rn(x - __bfloat162float(hi));
    T[(size_t)n*K3 + k]        = hi;
    T[(size_t)n*K3 + 512 + k]  = hi;
    T[(size_t)n*K3 + 1024 + k] = lo;
}

// A [16384][512] fp32 -> Asp [16384][1536] bf16: [hi|lo|hi]
__global__ __launch_bounds__(256)
void asplit_kernel(const float* __restrict__ A0, const float* __restrict__ A1,
                   const float* __restrict__ A2)
{
    const float* A; __nv_bfloat16* T;
    if (blockIdx.z == 0)      { A = A0; T = g_Asp0; }
    else if (blockIdx.z == 1) { A = A1; T = g_Asp1; }
    else                      { A = A2; T = g_Asp2; }
    size_t idx = (size_t)blockIdx.x * 256 + threadIdx.x;   // 0..8388607
    size_t m = idx >> 9; int k = (int)(idx & 511);
    float x = A[idx];
    __nv_bfloat16 hi = __float2bfloat16_rn(x);
    __nv_bfloat16 lo = __float2bfloat16_rn(x - __bfloat162float(hi));
    T[m*K3 + k]        = hi;
    T[m*K3 + 512 + k]  = lo;
    T[m*K3 + 1024 + k] = hi;
}

// =================== HMMA GEMM: C[16384x512] = Asp[16384x1536] * T[512x1536]^T
// Block tile 128x128, 256 thr (8 warps 2x4, warp tile 64x32), BK=32, 4 stages.
#define ASTR  40                        // smem row stride (elements): 80B
#define STG_B 20480                     // bytes per stage: A 10240 + B 10240
#define NSTG  4
#define SMEM_GEMM (NSTG*STG_B)

__global__ __launch_bounds__(256, 2)
void hmma_gemm_kernel(const __nv_bfloat16* A0, const __nv_bfloat16* A1, const __nv_bfloat16* A2,
                      const __nv_bfloat16* B0, const __nv_bfloat16* B1, const __nv_bfloat16* B2,
                      float* C0, float* C1, float* C2)
{
    const __nv_bfloat16* A; const __nv_bfloat16* Bt; float* C;
    if (blockIdx.z == 0)      { A = A0; Bt = B0; C = C0; }
    else if (blockIdx.z == 1) { A = A1; Bt = B1; C = C1; }
    else                      { A = A2; Bt = B2; C = C2; }

    extern __shared__ __align__(16) char smem[];
    const uint32_t sbase = (uint32_t)__cvta_generic_to_shared(smem);
    const int tid = threadIdx.x;
    const int lane = tid & 31, wid = tid >> 5;
    const int r0 = blockIdx.y * 128;
    const int n0 = blockIdx.x * 128;
    const int wm = wid >> 2, wn = wid & 3;       // 2 x 4 warps, warp tile 64x32

    const int lrow = tid >> 2;           // 0..63
    const int lchk = (tid & 3) * 8;      // element offset 0/8/16/24

    float acc[4][4][4];
#pragma unroll
    for (int mi = 0; mi < 4; mi++)
#pragma unroll
        for (int ni = 0; ni < 4; ni++)
#pragma unroll
            for (int q = 0; q < 4; q++) acc[mi][ni][q] = 0.0f;

    // loader: 2 A rows + 2 B rows per thread per stage
    const __nv_bfloat16* gA = A  + (size_t)(r0 + lrow) * K3 + lchk;
    const __nv_bfloat16* gB = Bt + (size_t)(n0 + lrow) * K3 + lchk;
    const uint32_t sAoff = (uint32_t)((lrow * ASTR + lchk) * 2);

    // prologue: stages 0,1,2
#pragma unroll
    for (int p = 0; p < 3; p++) {
        uint32_t sb = sbase + p * STG_B;
        cpa16(sb + sAoff,                     gA + p * 32);
        cpa16(sb + sAoff + 64 * ASTR * 2,     gA + (size_t)64 * K3 + p * 32);
        cpa16(sb + 10240 + sAoff,             gB + p * 32);
        cpa16(sb + 10240 + sAoff + 64 * ASTR * 2, gB + (size_t)64 * K3 + p * 32);
        asm volatile("cp.async.commit_group;" ::: "memory");
    }

    for (int kt = 0; kt < 48; kt++) {
        asm volatile("cp.async.wait_group 2;" ::: "memory");
        __syncthreads();
        if (kt + 3 < 48) {
            uint32_t sb = sbase + ((kt + 3) & 3) * STG_B;
            cpa16(sb + sAoff,                     gA + (kt + 3) * 32);
            cpa16(sb + sAoff + 64 * ASTR * 2,     gA + (size_t)64 * K3 + (kt + 3) * 32);
            cpa16(sb + 10240 + sAoff,             gB + (kt + 3) * 32);
            cpa16(sb + 10240 + sAoff + 64 * ASTR * 2, gB + (size_t)64 * K3 + (kt + 3) * 32);
            asm volatile("cp.async.commit_group;" ::: "memory");
        }
        const uint32_t stA = sbase + (kt & 3) * STG_B;
        const uint32_t stB = stA + 10240;
#pragma unroll
        for (int ks = 0; ks < 2; ks++) {
            const int ko = ks * 16;
            uint32_t a[4][4], b[2][4];
#pragma unroll
            for (int mi = 0; mi < 4; mi++)
                ldsm_x4(a[mi][0], a[mi][1], a[mi][2], a[mi][3],
                        stA + ((wm * 64 + mi * 16 + (lane & 15)) * ASTR
                               + ko + (lane >> 4) * 8) * 2);
#pragma unroll
            for (int pr = 0; pr < 2; pr++)
                ldsm_x4(b[pr][0], b[pr][1], b[pr][2], b[pr][3],
                        stB + ((wn * 32 + pr * 16 + ((lane >> 4) << 3) + (lane & 7)) * ASTR
                               + ko + ((lane >> 3) & 1) * 8) * 2);
#pragma unroll
            for (int mi = 0; mi < 4; mi++) {
                mma16816(acc[mi][0], a[mi], b[0][0], b[0][1]);
                mma16816(acc[mi][1], a[mi], b[0][2], b[0][3]);
                mma16816(acc[mi][2], a[mi], b[1][0], b[1][1]);
                mma16816(acc[mi][3], a[mi], b[1][2], b[1][3]);
            }
        }
    }

    // epilogue
#pragma unroll
    for (int mi = 0; mi < 4; mi++)
#pragma unroll
        for (int ni = 0; ni < 4; ni++) {
            const int row = r0 + wm * 64 + mi * 16 + (lane >> 2);
            const int col = n0 + wn * 32 + ni * 8 + (lane & 3) * 2;
            float2 v0 = make_float2(acc[mi][ni][0], acc[mi][ni][1]);
            float2 v1 = make_float2(acc[mi][ni][2], acc[mi][ni][3]);
            *(float2*)(C + (size_t)row * 512 + col)       = v0;
            *(float2*)(C + (size_t)(row + 8) * 512 + col) = v1;
        }
}

// ---------------- norms (+ zero g_kvs for the atomic reduction) ------------
__global__ __launch_bounds__(256)
void norms_kernel()
{
    const int t = blockIdx.x * 256 + threadIdx.x;   // 131072 threads total
    ((float4*)g_kvs)[t] = make_float4(0.f, 0.f, 0.f, 0.f);

    const float4* sp = (const float4*)(g_sproj + (size_t)t * 64);
    float acc = 0.0f;
#pragma unroll
    for (int i = 0; i < 16; i++) {
        float4 v = sp[i];
        acc = fmaf(v.x, v.x, acc);
        acc = fmaf(v.y, v.y, acc);
        acc = fmaf(v.z, v.z, acc);
        acc = fmaf(v.w, v.w, acc);
    }
    g_norms[t] = sqrtf(acc) * (1.0f / (float)Nv);
}

// ---------------- fourier features: GEMM [R,64]x[64,128] + sincos ----------
__global__ __launch_bounds__(256)
void fourier_kernel(const float* __restrict__ proj,
                    const float* __restrict__ scale,
                    const float* __restrict__ offs,
                    float* __restrict__ outq,
                    float* __restrict__ outk)
{
    __shared__ float As[8][128];
    __shared__ float Ps[8][128];
    const int tid = threadIdx.x;
    const int tx = tid & 15;
    const int ty = tid >> 4;
    const int r0 = blockIdx.y * 128;
    const bool is_k = (blockIdx.z != 0);
    float* outp = is_k ? outk : outq;

    const int arow = tid >> 1;
    const int akp  = (tid & 1) * 4;
    const int r    = r0 + arow;
    const int h    = r & 7;
    const float sc = scale[h] * DN_CONST;
    const float of = offs[h];

    float acc[8][8];
#pragma unroll
    for (int i = 0; i < 8; i++)
#pragma unroll
        for (int j = 0; j < 8; j++) acc[i][j] = 0.0f;

    for (int kk = 0; kk < 64; kk += 8) {
        float4 p4 = *(const float4*)(g_pproj + (size_t)r * 64 + kk + akp);
        float4 x4;
        if (is_k) {
            float4 s4 = *(const float4*)(g_sproj + (size_t)r * 64 + kk + akp);
            x4.x = sc * fmaf(of, s4.x, p4.x);
            x4.y = sc * fmaf(of, s4.y, p4.y);
            x4.z = sc * fmaf(of, s4.z, p4.z);
            x4.w = sc * fmaf(of, s4.w, p4.w);
        } else {
            x4.x = sc * p4.x; x4.y = sc * p4.y; x4.z = sc * p4.z; x4.w = sc * p4.w;
        }
        float4 pr4 = *(const float4*)(proj + (size_t)arow * 64 + kk + akp);
        __syncthreads();
        As[akp + 0][arow] = x4.x;
        As[akp + 1][arow] = x4.y;
        As[akp + 2][arow] = x4.z;
        As[akp + 3][arow] = x4.w;
        Ps[akp + 0][arow] = pr4.x;
        Ps[akp + 1][arow] = pr4.y;
        Ps[akp + 2][arow] = pr4.z;
        Ps[akp + 3][arow] = pr4.w;
        __syncthreads();
#pragma unroll
        for (int k = 0; k < 8; k++) {
            float a[8], b[8];
            *(float4*)(a)     = *(const float4*)&As[k][ty * 8];
            *(float4*)(a + 4) = *(const float4*)&As[k][ty * 8 + 4];
            *(float4*)(b)     = *(const float4*)&Ps[k][tx * 8];
            *(float4*)(b + 4) = *(const float4*)&Ps[k][tx * 8 + 4];
#pragma unroll
            for (int i = 0; i < 8; i++)
#pragma unroll
                for (int j = 0; j < 8; j++)
                    acc[i][j] = fmaf(a[i], b[j], acc[i][j]);
        }
    }
#pragma unroll
    for (int i = 0; i < 8; i++) {
        const int rr = r0 + ty * 8 + i;
        float* orow = outp + (size_t)rr * 256;
        float s[8], c[8];
#pragma unroll
        for (int j = 0; j < 8; j++) {
            sincosf(acc[i][j], &s[j], &c[j]);
            s[j] *= RATIO_CONST;
            c[j] *= RATIO_CONST;
        }
        *(float4*)(orow + tx * 8)           = *(float4*)&s[0];
        *(float4*)(orow + tx * 8 + 4)       = *(float4*)&s[4];
        *(float4*)(orow + 128 + tx * 8)     = *(float4*)&c[0];
        *(float4*)(orow + 128 + tx * 8 + 4) = *(float4*)&c[4];
    }
}

// ---------------- kvs: per (b,h) [256 x 4096] x [4096 x 64], split-K x16 ---
__global__ __launch_bounds__(256)
void kvs_kernel(const float* __restrict__ kprime)
{
    __shared__ float Ks[8][256];
    __shared__ float Vs[8][64];
    const int tid = threadIdx.x;
    const int bh = blockIdx.y;
    const int b = bh >> 3, h = bh & 7;
    const int n0 = blockIdx.x * 256;    // 16 chunks of 256
    const int tx = tid & 7;
    const int ty = tid >> 3;

    const int kni = tid >> 6;
    const int km4 = (tid & 63) * 4;
    const int vni = tid >> 4;
    const int vd4 = (tid & 15) * 4;

    float acc[8][8];
#pragma unroll
    for (int i = 0; i < 8; i++)
#pragma unroll
        for (int j = 0; j < 8; j++) acc[i][j] = 0.0f;

    for (int nn = 0; nn < 256; nn += 8) {
        const size_t nbase = (size_t)(b * Nv + n0 + nn);
        float4 k0 = *(const float4*)(kprime + ((nbase + kni)     * 8 + h) * 256 + km4);
        float4 k1 = *(const float4*)(kprime + ((nbase + kni + 4) * 8 + h) * 256 + km4);
        float4 v0 = make_float4(0.f, 0.f, 0.f, 0.f);
        if (tid < 128)
            v0 = *(const float4*)(g_value + (nbase + vni) * 512 + h * 64 + vd4);
        __syncthreads();
        *(float4*)&Ks[kni][km4]     = k0;
        *(float4*)&Ks[kni + 4][km4] = k1;
        if (tid < 128) *(float4*)&Vs[vni][vd4] = v0;
        __syncthreads();
#pragma unroll
        for (int ni = 0; ni < 8; ni++) {
            float a[8], v[8];
            *(float4*)(a)     = *(const float4*)&Ks[ni][ty * 8];
            *(float4*)(a + 4) = *(const float4*)&Ks[ni][ty * 8 + 4];
            *(float4*)(v)     = *(const float4*)&Vs[ni][tx * 8];
            *(float4*)(v + 4) = *(const float4*)&Vs[ni][tx * 8 + 4];
#pragma unroll
            for (int i = 0; i < 8; i++)
#pragma unroll
                for (int j = 0; j < 8; j++)
                    acc[i][j] = fmaf(a[i], v[j], acc[i][j]);
        }
    }
    float* dst = g_kvs + ((size_t)bh * 256 + ty * 8) * 64 + tx * 8;
#pragma unroll
    for (int i = 0; i < 8; i++)
#pragma unroll
        for (int j = 0; j < 8; j++)
            atomicAdd(dst + (size_t)i * 64 + j, acc[i][j]);
}

// ---------------- av: per (b,h) [4096 x 256] x [256 x 64] ------------------
// epilogue: multiply by norm, convert to bf16 hi/lo split into g_avsp.
__global__ __launch_bounds__(256)
void av_kernel(const float* __restrict__ qprime)
{
    __shared__ float As[16][128];
    __shared__ float Bs[16][64];
    const int tid = threadIdx.x;
    const int bh = blockIdx.y;
    const int b = bh >> 3, h = bh & 7;
    const int n0 = blockIdx.x * 128;
    const int tx = tid & 15;
    const int ty = tid >> 4;

    const int ar  = tid >> 2;
    const int ak4 = (tid & 3) * 4;
    const int bi  = tid >> 4;
    const int bj4 = (tid & 15) * 4;

    float acc[8][4];
#pragma unroll
    for (int i = 0; i < 8; i++)
#pragma unroll
        for (int j = 0; j < 4; j++) acc[i][j] = 0.0f;

    for (int kk = 0; kk < 256; kk += 16) {
        float4 a0 = *(const float4*)(qprime + ((size_t)(b * Nv + n0 + ar)      * 8 + h) * 256 + kk + ak4);
        float4 a1 = *(const float4*)(qprime + ((size_t)(b * Nv + n0 + ar + 64) * 8 + h) * 256 + kk + ak4);
        float4 b0 = *(const float4*)(g_kvs + ((size_t)bh * 256 + kk + bi) * 64 + bj4);
        __syncthreads();
        As[ak4 + 0][ar] = a0.x; As[ak4 + 1][ar] = a0.y;
        As[ak4 + 2][ar] = a0.z; As[ak4 + 3][ar] = a0.w;
        As[ak4 + 0][ar + 64] = a1.x; As[ak4 + 1][ar + 64] = a1.y;
        As[ak4 + 2][ar + 64] = a1.z; As[ak4 + 3][ar + 64] = a1.w;
        *(float4*)&Bs[bi][bj4] = b0;
        __syncthreads();
#pragma unroll
        for (int k = 0; k < 16; k++) {
            float a[8], bb[4];
            *(float4*)(a)     = *(const float4*)&As[k][ty * 8];
            *(float4*)(a + 4) = *(const float4*)&As[k][ty * 8 + 4];
            *(float4*)(bb)    = *(const float4*)&Bs[k][tx * 4];
#pragma unroll
            for (int i = 0; i < 8; i++)
#pragma unroll
                for (int j = 0; j < 4; j++)
                    acc[i][j] = fmaf(a[i], bb[j], acc[i][j]);
        }
    }
#pragma unroll
    for (int i = 0; i < 8; i++) {
        const int n = n0 + ty * 8 + i;
        const size_t m = (size_t)(b * Nv + n);
        const float nm = g_norms[m * 8 + h];
        const int kcol = h * 64 + tx * 4;
        __nv_bfloat16 hi4[4], lo4[4];
#pragma unroll
        for (int j = 0; j < 4; j++) {
            float v = acc[i][j] * nm;
            hi4[j] = __float2bfloat16_rn(v);
            lo4[j] = __float2bfloat16_rn(v - __bfloat162float(hi4[j]));
        }
        *(uint2*)(g_avsp + m * K3 + kcol)        = *(uint2*)hi4;
        *(uint2*)(g_avsp + m * K3 + 512 + kcol)  = *(uint2*)lo4;
        *(uint2*)(g_avsp + m * K3 + 1024 + kcol) = *(uint2*)hi4;
    }
}

// ---------------------------------------------------------------------------
extern "C" void kernel_launch(void* const* d_in, const int* in_sizes, int n_in,
                              void* d_out, int out_size)
{
    const float* src    = (const float*)d_in[0];
    const float* pos    = (const float*)d_in[1];
    const float* slopes = (const float*)d_in[2];
    const float* Wv     = (const float*)d_in[3];
    const float* Wp     = (const float*)d_in[4];
    const float* scale  = (const float*)d_in[5];
    const float* offs   = (const float*)d_in[6];
    const float* Wout   = (const float*)d_in[7];
    const float* proj   = (const float*)d_in[8];

    float* out = (float*)d_out;

    void* p;
    float *pvalue, *ppproj, *psproj;
    __nv_bfloat16 *pWvT, *pWpT, *pWoT, *pA0, *pA1, *pA2, *pAv;
    cudaGetSymbolAddress(&p, g_value); pvalue = (float*)p;
    cudaGetSymbolAddress(&p, g_pproj); ppproj = (float*)p;
    cudaGetSymbolAddress(&p, g_sproj); psproj = (float*)p;
    cudaGetSymbolAddress(&p, g_WvT);   pWvT   = (__nv_bfloat16*)p;
    cudaGetSymbolAddress(&p, g_WpT);   pWpT   = (__nv_bfloat16*)p;
    cudaGetSymbolAddress(&p, g_WoT);   pWoT   = (__nv_bfloat16*)p;
    cudaGetSymbolAddress(&p, g_Asp0);  pA0    = (__nv_bfloat16*)p;
    cudaGetSymbolAddress(&p, g_Asp1);  pA1    = (__nv_bfloat16*)p;
    cudaGetSymbolAddress(&p, g_Asp2);  pA2    = (__nv_bfloat16*)p;
    cudaGetSymbolAddress(&p, g_avsp);  pAv    = (__nv_bfloat16*)p;

    // tuple output: (out[BN*D], q'[R*2M], k'[R*2M]) flattened
    const size_t OUT0 = (size_t)BNv * Dv;
    const size_t QPN  = (size_t)Rv * M2v;
    float* qdst;
    float* kdst;
    if ((size_t)out_size >= OUT0 + 2 * QPN) {
        qdst = out + OUT0;
        kdst = out + OUT0 + QPN;
    } else {
        cudaGetSymbolAddress(&p, g_qp); qdst = (float*)p;
        cudaGetSymbolAddress(&p, g_kp); kdst = (float*)p;
    }

    static int smem_set = 0;
    if (!smem_set) {
        cudaFuncSetAttribute(hmma_gemm_kernel,
                             cudaFuncAttributeMaxDynamicSharedMemorySize, SMEM_GEMM);
        smem_set = 1;
    }

    wsplit_kernel<<<dim3(1024, 1, 3), 256>>>(Wv, Wp, Wout);
    asplit_kernel<<<dim3(32768, 1, 3), 256>>>(src, pos, slopes);
    hmma_gemm_kernel<<<dim3(4, 128, 3), 256, SMEM_GEMM>>>(
        pA0, pA1, pA2, pWvT, pWpT, pWpT, pvalue, ppproj, psproj);
    norms_kernel<<<Rv / 256, 256>>>();                       // also zeros g_kvs
    fourier_kernel<<<dim3(1, Rv / 128, 2), 256>>>(proj, scale, offs, qdst, kdst);
    kvs_kernel<<<dim3(16, Bv * Hv), 256>>>(kdst);
    av_kernel<<<dim3(Nv / 128, Bv * Hv), 256>>>(qdst);       // writes g_avsp
    hmma_gemm_kernel<<<dim3(4, 128, 1), 256, SMEM_GEMM>>>(
        pAv, pAv, pAv, pWoT, pWoT, pWoT, out, out, out);
}

// round 5
// speedup vs baseline: 1.5081x; 1.0241x over previous
#include <cuda_runtime.h>
#include <cuda_bf16.h>
#include <math.h>
#include <stdint.h>

// Problem dims (fixed by the reference)
#define Bv   4
#define Nv   4096
#define Dv   512
#define Hv   8
#define DHv  64
#define Mv   128
#define BNv  (Bv*Nv)       // 16384 rows
#define Rv   (BNv*Hv)      // 131072 (b,n,h) rows
#define M2v  (2*Mv)        // 256
#define K3   1536          // split K' = 3*512

#define DN_CONST    0.35355339059327373f   // 64^-0.25
#define RATIO_CONST 0.08838834764831845f   // 1/sqrt(128)

// ---------------- scratch (device globals: no allocation allowed) ----------
__device__ float g_value[(size_t)BNv*Dv];   // [bn][h*64+dh]
__device__ float g_pproj[(size_t)BNv*Dv];   // [r=bn*8+h][64]
__device__ float g_sproj[(size_t)BNv*Dv];
__device__ float g_norms[(size_t)Rv];
__device__ float g_kvs  [(size_t)Bv*Hv*M2v*DHv];   // [bh][m2][dh]
// split-transposed weights: [n=512][k'=1536] bf16 (= B^T row-major)
__device__ __nv_bfloat16 g_WvT[(size_t)Dv*K3];
__device__ __nv_bfloat16 g_WpT[(size_t)Dv*K3];
__device__ __nv_bfloat16 g_WoT[(size_t)Dv*K3];
// split A matrices: [m=16384][k'=1536] bf16  ([hi|lo|hi])
__device__ __nv_bfloat16 g_Asp0[(size_t)BNv*K3];
__device__ __nv_bfloat16 g_Asp1[(size_t)BNv*K3];
__device__ __nv_bfloat16 g_Asp2[(size_t)BNv*K3];
__device__ __nv_bfloat16 g_avsp[(size_t)BNv*K3];
// fallback q'/k' scratch if d_out only holds the first tuple element
__device__ float g_qp[(size_t)Rv*M2v];
__device__ float g_kp[(size_t)Rv*M2v];

// =================== HMMA helpers (sm_80-era PTX, valid on sm_103 base) ====
__device__ __forceinline__ void ldsm_x4(uint32_t& r0, uint32_t& r1,
                                        uint32_t& r2, uint32_t& r3, uint32_t addr) {
    asm volatile("ldmatrix.sync.aligned.m8n8.x4.shared.b16 {%0,%1,%2,%3}, [%4];"
                 : "=r"(r0), "=r"(r1), "=r"(r2), "=r"(r3) : "r"(addr));
}

__device__ __forceinline__ void mma16816(float* c, const uint32_t* a,
                                         uint32_t b0, uint32_t b1) {
    asm volatile("mma.sync.aligned.m16n8k16.row.col.f32.bf16.bf16.f32 "
                 "{%0,%1,%2,%3}, {%4,%5,%6,%7}, {%8,%9}, {%0,%1,%2,%3};"
                 : "+f"(c[0]), "+f"(c[1]), "+f"(c[2]), "+f"(c[3])
                 : "r"(a[0]), "r"(a[1]), "r"(a[2]), "r"(a[3]), "r"(b0), "r"(b1));
}

__device__ __forceinline__ void cpa16(uint32_t dst, const void* src) {
    asm volatile("cp.async.cg.shared.global [%0], [%1], 16;"
                 :: "r"(dst), "l"(src));
}

// =================== W transpose + hi/lo split ==============================
__global__ __launch_bounds__(256)
void wsplit_kernel(const float* __restrict__ Wv, const float* __restrict__ Wp,
                   const float* __restrict__ Wo)
{
    const float* W; __nv_bfloat16* T;
    if (blockIdx.z == 0)      { W = Wv; T = g_WvT; }
    else if (blockIdx.z == 1) { W = Wp; T = g_WpT; }
    else                      { W = Wo; T = g_WoT; }
    int idx = blockIdx.x * 256 + threadIdx.x;   // 0..262143
    int k = idx >> 9, n = idx & 511;
    float x = W[idx];
    __nv_bfloat16 hi = __float2bfloat16_rn(x);
    __nv_bfloat16 lo = __float2bfloat16_rn(x - __bfloat162float(hi));
    T[(size_t)n*K3 + k]        = hi;
    T[(size_t)n*K3 + 512 + k]  = hi;
    T[(size_t)n*K3 + 1024 + k] = lo;
}

// A [16384][512] fp32 -> Asp [16384][1536] bf16: [hi|lo|hi]
__global__ __launch_bounds__(256)
void asplit_kernel(const float* __restrict__ A0, const float* __restrict__ A1,
                   const float* __restrict__ A2)
{
    const float* A; __nv_bfloat16* T;
    if (blockIdx.z == 0)      { A = A0; T = g_Asp0; }
    else if (blockIdx.z == 1) { A = A1; T = g_Asp1; }
    else                      { A = A2; T = g_Asp2; }
    size_t idx = (size_t)blockIdx.x * 256 + threadIdx.x;   // 0..8388607
    size_t m = idx >> 9; int k = (int)(idx & 511);
    float x = A[idx];
    __nv_bfloat16 hi = __float2bfloat16_rn(x);
    __nv_bfloat16 lo = __float2bfloat16_rn(x - __bfloat162float(hi));
    T[m*K3 + k]        = hi;
    T[m*K3 + 512 + k]  = lo;
    T[m*K3 + 1024 + k] = hi;
}

// =================== HMMA GEMM: C[16384x512] = Asp[16384x1536] * T[512x1536]^T
// Block tile 128x128, 256 thr (8 warps 2x4, warp tile 64x32), BK=32,
// 5-stage cp.async ring, TWO stages consumed per __syncthreads (24 barriers).
#define ASTR  40                        // smem row stride (elements): 80B
#define STG_B 20480                     // bytes per stage: A 10240 + B 10240
#define NSTG  5
#define SMEM_GEMM (NSTG*STG_B)

__global__ __launch_bounds__(256, 2)
void hmma_gemm_kernel(const __nv_bfloat16* A0, const __nv_bfloat16* A1, const __nv_bfloat16* A2,
                      const __nv_bfloat16* B0, const __nv_bfloat16* B1, const __nv_bfloat16* B2,
                      float* C0, float* C1, float* C2)
{
    const __nv_bfloat16* A; const __nv_bfloat16* Bt; float* C;
    if (blockIdx.z == 0)      { A = A0; Bt = B0; C = C0; }
    else if (blockIdx.z == 1) { A = A1; Bt = B1; C = C1; }
    else                      { A = A2; Bt = B2; C = C2; }

    extern __shared__ __align__(16) char smem[];
    const uint32_t sbase = (uint32_t)__cvta_generic_to_shared(smem);
    const int tid = threadIdx.x;
    const int lane = tid & 31, wid = tid >> 5;
    const int r0 = blockIdx.y * 128;
    const int n0 = blockIdx.x * 128;
    const int wm = wid >> 2, wn = wid & 3;       // 2 x 4 warps, warp tile 64x32

    const int lrow = tid >> 2;           // 0..63
    const int lchk = (tid & 3) * 8;      // element offset 0/8/16/24

    float acc[4][4][4];
#pragma unroll
    for (int mi = 0; mi < 4; mi++)
#pragma unroll
        for (int ni = 0; ni < 4; ni++)
#pragma unroll
            for (int q = 0; q < 4; q++) acc[mi][ni][q] = 0.0f;

    const __nv_bfloat16* gA = A  + (size_t)(r0 + lrow) * K3 + lchk;
    const __nv_bfloat16* gB = Bt + (size_t)(n0 + lrow) * K3 + lchk;
    const uint32_t sAoff = (uint32_t)((lrow * ASTR + lchk) * 2);

    // per-stage loader (chunk c -> slot c % 5)
    #define LOAD_STAGE(c) do {                                                  \
        uint32_t sb_ = sbase + ((c) % NSTG) * STG_B;                            \
        cpa16(sb_ + sAoff,                         gA + (c) * 32);              \
        cpa16(sb_ + sAoff + 64 * ASTR * 2,         gA + (size_t)64 * K3 + (c) * 32); \
        cpa16(sb_ + 10240 + sAoff,                 gB + (c) * 32);              \
        cpa16(sb_ + 10240 + sAoff + 64 * ASTR * 2, gB + (size_t)64 * K3 + (c) * 32); \
        asm volatile("cp.async.commit_group;" ::: "memory");                    \
    } while (0)

    #define COMPUTE_STAGE(c) do {                                               \
        const uint32_t stA_ = sbase + ((c) % NSTG) * STG_B;                     \
        const uint32_t stB_ = stA_ + 10240;                                     \
        _Pragma("unroll")                                                       \
        for (int ks = 0; ks < 2; ks++) {                                        \
            const int ko = ks * 16;                                             \
            uint32_t a[4][4], b[2][4];                                          \
            _Pragma("unroll")                                                   \
            for (int mi = 0; mi < 4; mi++)                                      \
                ldsm_x4(a[mi][0], a[mi][1], a[mi][2], a[mi][3],                 \
                        stA_ + ((wm * 64 + mi * 16 + (lane & 15)) * ASTR        \
                               + ko + (lane >> 4) * 8) * 2);                    \
            _Pragma("unroll")                                                   \
            for (int pr = 0; pr < 2; pr++)                                      \
                ldsm_x4(b[pr][0], b[pr][1], b[pr][2], b[pr][3],                 \
                        stB_ + ((wn * 32 + pr * 16 + ((lane >> 4) << 3) + (lane & 7)) * ASTR \
                               + ko + ((lane >> 3) & 1) * 8) * 2);              \
            _Pragma("unroll")                                                   \
            for (int mi = 0; mi < 4; mi++) {                                    \
                mma16816(acc[mi][0], a[mi], b[0][0], b[0][1]);                  \
                mma16816(acc[mi][1], a[mi], b[0][2], b[0][3]);                  \
                mma16816(acc[mi][2], a[mi], b[1][0], b[1][1]);                  \
                mma16816(acc[mi][3], a[mi], b[1][2], b[1][3]);                  \
            }                                                                   \
        }                                                                       \
    } while (0)

    // prologue: stages 0,1,2
#pragma unroll
    for (int p = 0; p < 3; p++) LOAD_STAGE(p);

    for (int kt = 0; kt < 48; kt += 2) {
        if (kt + 2 >= 48) {
            asm volatile("cp.async.wait_group 0;" ::: "memory");
        } else {
            asm volatile("cp.async.wait_group 1;" ::: "memory");
        }
        __syncthreads();
        if (kt + 3 < 48) LOAD_STAGE(kt + 3);
        if (kt + 4 < 48) LOAD_STAGE(kt + 4);
        COMPUTE_STAGE(kt);
        COMPUTE_STAGE(kt + 1);
    }

    // epilogue
#pragma unroll
    for (int mi = 0; mi < 4; mi++)
#pragma unroll
        for (int ni = 0; ni < 4; ni++) {
            const int row = r0 + wm * 64 + mi * 16 + (lane >> 2);
            const int col = n0 + wn * 32 + ni * 8 + (lane & 3) * 2;
            float2 v0 = make_float2(acc[mi][ni][0], acc[mi][ni][1]);
            float2 v1 = make_float2(acc[mi][ni][2], acc[mi][ni][3]);
            *(float2*)(C + (size_t)row * 512 + col)       = v0;
            *(float2*)(C + (size_t)(row + 8) * 512 + col) = v1;
        }
    #undef LOAD_STAGE
    #undef COMPUTE_STAGE
}

// ---------------- norms (+ zero g_kvs for the atomic reduction) ------------
__global__ __launch_bounds__(256)
void norms_kernel()
{
    const int t = blockIdx.x * 256 + threadIdx.x;   // 131072 threads total
    ((float4*)g_kvs)[t] = make_float4(0.f, 0.f, 0.f, 0.f);

    const float4* sp = (const float4*)(g_sproj + (size_t)t * 64);
    float acc = 0.0f;
#pragma unroll
    for (int i = 0; i < 16; i++) {
        float4 v = sp[i];
        acc = fmaf(v.x, v.x, acc);
        acc = fmaf(v.y, v.y, acc);
        acc = fmaf(v.z, v.z, acc);
        acc = fmaf(v.w, v.w, acc);
    }
    g_norms[t] = sqrtf(acc) * (1.0f / (float)Nv);
}

// ---------------- fourier features: GEMM [R,64]x[64,128] + fast sincos -----
__global__ __launch_bounds__(256)
void fourier_kernel(const float* __restrict__ proj,
                    const float* __restrict__ scale,
                    const float* __restrict__ offs,
                    float* __restrict__ outq,
                    float* __restrict__ outk)
{
    __shared__ float As[8][128];
    __shared__ float Ps[8][128];
    const int tid = threadIdx.x;
    const int tx = tid & 15;
    const int ty = tid >> 4;
    const int r0 = blockIdx.y * 128;
    const bool is_k = (blockIdx.z != 0);
    float* outp = is_k ? outk : outq;

    const int arow = tid >> 1;
    const int akp  = (tid & 1) * 4;
    const int r    = r0 + arow;
    const int h    = r & 7;
    const float sc = scale[h] * DN_CONST;
    const float of = offs[h];

    float acc[8][8];
#pragma unroll
    for (int i = 0; i < 8; i++)
#pragma unroll
        for (int j = 0; j < 8; j++) acc[i][j] = 0.0f;

    for (int kk = 0; kk < 64; kk += 8) {
        float4 p4 = *(const float4*)(g_pproj + (size_t)r * 64 + kk + akp);
        float4 x4;
        if (is_k) {
            float4 s4 = *(const float4*)(g_sproj + (size_t)r * 64 + kk + akp);
            x4.x = sc * fmaf(of, s4.x, p4.x);
            x4.y = sc * fmaf(of, s4.y, p4.y);
            x4.z = sc * fmaf(of, s4.z, p4.z);
            x4.w = sc * fmaf(of, s4.w, p4.w);
        } else {
            x4.x = sc * p4.x; x4.y = sc * p4.y; x4.z = sc * p4.z; x4.w = sc * p4.w;
        }
        float4 pr4 = *(const float4*)(proj + (size_t)arow * 64 + kk + akp);
        __syncthreads();
        As[akp + 0][arow] = x4.x;
        As[akp + 1][arow] = x4.y;
        As[akp + 2][arow] = x4.z;
        As[akp + 3][arow] = x4.w;
        Ps[akp + 0][arow] = pr4.x;
        Ps[akp + 1][arow] = pr4.y;
        Ps[akp + 2][arow] = pr4.z;
        Ps[akp + 3][arow] = pr4.w;
        __syncthreads();
#pragma unroll
        for (int k = 0; k < 8; k++) {
            float a[8], b[8];
            *(float4*)(a)     = *(const float4*)&As[k][ty * 8];
            *(float4*)(a + 4) = *(const float4*)&As[k][ty * 8 + 4];
            *(float4*)(b)     = *(const float4*)&Ps[k][tx * 8];
            *(float4*)(b + 4) = *(const float4*)&Ps[k][tx * 8 + 4];
#pragma unroll
            for (int i = 0; i < 8; i++)
#pragma unroll
                for (int j = 0; j < 8; j++)
                    acc[i][j] = fmaf(a[i], b[j], acc[i][j]);
        }
    }
#pragma unroll
    for (int i = 0; i < 8; i++) {
        const int rr = r0 + ty * 8 + i;
        float* orow = outp + (size_t)rr * 256;
        float s[8], c[8];
#pragma unroll
        for (int j = 0; j < 8; j++) {
            __sincosf(acc[i][j], &s[j], &c[j]);
            s[j] *= RATIO_CONST;
            c[j] *= RATIO_CONST;
        }
        *(float4*)(orow + tx * 8)           = *(float4*)&s[0];
        *(float4*)(orow + tx * 8 + 4)       = *(float4*)&s[4];
        *(float4*)(orow + 128 + tx * 8)     = *(float4*)&c[0];
        *(float4*)(orow + 128 + tx * 8 + 4) = *(float4*)&c[4];
    }
}

// ---------------- kvs: per (b,h) [256 x 4096] x [4096 x 64], split-K x16 ---
__global__ __launch_bounds__(256)
void kvs_kernel(const float* __restrict__ kprime)
{
    __shared__ float Ks[8][256];
    __shared__ float Vs[8][64];
    const int tid = threadIdx.x;
    const int bh = blockIdx.y;
    const int b = bh >> 3, h = bh & 7;
    const int n0 = blockIdx.x * 256;    // 16 chunks of 256
    const int tx = tid & 7;
    const int ty = tid >> 3;

    const int kni = tid >> 6;
    const int km4 = (tid & 63) * 4;
    const int vni = tid >> 4;
    const int vd4 = (tid & 15) * 4;

    float acc[8][8];
#pragma unroll
    for (int i = 0; i < 8; i++)
#pragma unroll
        for (int j = 0; j < 8; j++) acc[i][j] = 0.0f;

    for (int nn = 0; nn < 256; nn += 8) {
        const size_t nbase = (size_t)(b * Nv + n0 + nn);
        float4 k0 = *(const float4*)(kprime + ((nbase + kni)     * 8 + h) * 256 + km4);
        float4 k1 = *(const float4*)(kprime + ((nbase + kni + 4) * 8 + h) * 256 + km4);
        float4 v0 = make_float4(0.f, 0.f, 0.f, 0.f);
        if (tid < 128)
            v0 = *(const float4*)(g_value + (nbase + vni) * 512 + h * 64 + vd4);
        __syncthreads();
        *(float4*)&Ks[kni][km4]     = k0;
        *(float4*)&Ks[kni + 4][km4] = k1;
        if (tid < 128) *(float4*)&Vs[vni][vd4] = v0;
        __syncthreads();
#pragma unroll
        for (int ni = 0; ni < 8; ni++) {
            float a[8], v[8];
            *(float4*)(a)     = *(const float4*)&Ks[ni][ty * 8];
            *(float4*)(a + 4) = *(const float4*)&Ks[ni][ty * 8 + 4];
            *(float4*)(v)     = *(const float4*)&Vs[ni][tx * 8];
            *(float4*)(v + 4) = *(const float4*)&Vs[ni][tx * 8 + 4];
#pragma unroll
            for (int i = 0; i < 8; i++)
#pragma unroll
                for (int j = 0; j < 8; j++)
                    acc[i][j] = fmaf(a[i], v[j], acc[i][j]);
        }
    }
    float* dst = g_kvs + ((size_t)bh * 256 + ty * 8) * 64 + tx * 8;
#pragma unroll
    for (int i = 0; i < 8; i++)
#pragma unroll
        for (int j = 0; j < 8; j++)
            atomicAdd(dst + (size_t)i * 64 + j, acc[i][j]);
}

// ---------------- av: per (b,h) [4096 x 256] x [256 x 64] ------------------
__global__ __launch_bounds__(256)
void av_kernel(const float* __restrict__ qprime)
{
    __shared__ float As[16][128];
    __shared__ float Bs[16][64];
    const int tid = threadIdx.x;
    const int bh = blockIdx.y;
    const int b = bh >> 3, h = bh & 7;
    const int n0 = blockIdx.x * 128;
    const int tx = tid & 15;
    const int ty = tid >> 4;

    const int ar  = tid >> 2;
    const int ak4 = (tid & 3) * 4;
    const int bi  = tid >> 4;
    const int bj4 = (tid & 15) * 4;

    float acc[8][4];
#pragma unroll
    for (int i = 0; i < 8; i++)
#pragma unroll
        for (int j = 0; j < 4; j++) acc[i][j] = 0.0f;

    for (int kk = 0; kk < 256; kk += 16) {
        float4 a0 = *(const float4*)(qprime + ((size_t)(b * Nv + n0 + ar)      * 8 + h) * 256 + kk + ak4);
        float4 a1 = *(const float4*)(qprime + ((size_t)(b * Nv + n0 + ar + 64) * 8 + h) * 256 + kk + ak4);
        float4 b0 = *(const float4*)(g_kvs + ((size_t)bh * 256 + kk + bi) * 64 + bj4);
        __syncthreads();
        As[ak4 + 0][ar] = a0.x; As[ak4 + 1][ar] = a0.y;
        As[ak4 + 2][ar] = a0.z; As[ak4 + 3][ar] = a0.w;
        As[ak4 + 0][ar + 64] = a1.x; As[ak4 + 1][ar + 64] = a1.y;
        As[ak4 + 2][ar + 64] = a1.z; As[ak4 + 3][ar + 64] = a1.w;
        *(float4*)&Bs[bi][bj4] = b0;
        __syncthreads();
#pragma unroll
        for (int k = 0; k < 16; k++) {
            float a[8], bb[4];
            *(float4*)(a)     = *(const float4*)&As[k][ty * 8];
            *(float4*)(a + 4) = *(const float4*)&As[k][ty * 8 + 4];
            *(float4*)(bb)    = *(const float4*)&Bs[k][tx * 4];
#pragma unroll
            for (int i = 0; i < 8; i++)
#pragma unroll
                for (int j = 0; j < 4; j++)
                    acc[i][j] = fmaf(a[i], bb[j], acc[i][j]);
        }
    }
#pragma unroll
    for (int i = 0; i < 8; i++) {
        const int n = n0 + ty * 8 + i;
        const size_t m = (size_t)(b * Nv + n);
        const float nm = g_norms[m * 8 + h];
        const int kcol = h * 64 + tx * 4;
        __nv_bfloat16 hi4[4], lo4[4];
#pragma unroll
        for (int j = 0; j < 4; j++) {
            float v = acc[i][j] * nm;
            hi4[j] = __float2bfloat16_rn(v);
            lo4[j] = __float2bfloat16_rn(v - __bfloat162float(hi4[j]));
        }
        *(uint2*)(g_avsp + m * K3 + kcol)        = *(uint2*)hi4;
        *(uint2*)(g_avsp + m * K3 + 512 + kcol)  = *(uint2*)lo4;
        *(uint2*)(g_avsp + m * K3 + 1024 + kcol) = *(uint2*)hi4;
    }
}

// ---------------------------------------------------------------------------
extern "C" void kernel_launch(void* const* d_in, const int* in_sizes, int n_in,
                              void* d_out, int out_size)
{
    const float* src    = (const float*)d_in[0];
    const float* pos    = (const float*)d_in[1];
    const float* slopes = (const float*)d_in[2];
    const float* Wv     = (const float*)d_in[3];
    const float* Wp     = (const float*)d_in[4];
    const float* scale  = (const float*)d_in[5];
    const float* offs   = (const float*)d_in[6];
    const float* Wout   = (const float*)d_in[7];
    const float* proj   = (const float*)d_in[8];

    float* out = (float*)d_out;

    void* p;
    float *pvalue, *ppproj, *psproj;
    __nv_bfloat16 *pWvT, *pWpT, *pWoT, *pA0, *pA1, *pA2, *pAv;
    cudaGetSymbolAddress(&p, g_value); pvalue = (float*)p;
    cudaGetSymbolAddress(&p, g_pproj); ppproj = (float*)p;
    cudaGetSymbolAddress(&p, g_sproj); psproj = (float*)p;
    cudaGetSymbolAddress(&p, g_WvT);   pWvT   = (__nv_bfloat16*)p;
    cudaGetSymbolAddress(&p, g_WpT);   pWpT   = (__nv_bfloat16*)p;
    cudaGetSymbolAddress(&p, g_WoT);   pWoT   = (__nv_bfloat16*)p;
    cudaGetSymbolAddress(&p, g_Asp0);  pA0    = (__nv_bfloat16*)p;
    cudaGetSymbolAddress(&p, g_Asp1);  pA1    = (__nv_bfloat16*)p;
    cudaGetSymbolAddress(&p, g_Asp2);  pA2    = (__nv_bfloat16*)p;
    cudaGetSymbolAddress(&p, g_avsp);  pAv    = (__nv_bfloat16*)p;

    // tuple output: (out[BN*D], q'[R*2M], k'[R*2M]) flattened
    const size_t OUT0 = (size_t)BNv * Dv;
    const size_t QPN  = (size_t)Rv * M2v;
    float* qdst;
    float* kdst;
    if ((size_t)out_size >= OUT0 + 2 * QPN) {
        qdst = out + OUT0;
        kdst = out + OUT0 + QPN;
    } else {
        cudaGetSymbolAddress(&p, g_qp); qdst = (float*)p;
        cudaGetSymbolAddress(&p, g_kp); kdst = (float*)p;
    }

    static int smem_set = 0;
    if (!smem_set) {
        cudaFuncSetAttribute(hmma_gemm_kernel,
                             cudaFuncAttributeMaxDynamicSharedMemorySize, SMEM_GEMM);
        smem_set = 1;
    }

    wsplit_kernel<<<dim3(1024, 1, 3), 256>>>(Wv, Wp, Wout);
    asplit_kernel<<<dim3(32768, 1, 3), 256>>>(src, pos, slopes);
    hmma_gemm_kernel<<<dim3(4, 128, 3), 256, SMEM_GEMM>>>(
        pA0, pA1, pA2, pWvT, pWpT, pWpT, pvalue, ppproj, psproj);
    norms_kernel<<<Rv / 256, 256>>>();                       // also zeros g_kvs
    fourier_kernel<<<dim3(1, Rv / 128, 2), 256>>>(proj, scale, offs, qdst, kdst);
    kvs_kernel<<<dim3(16, Bv * Hv), 256>>>(kdst);
    av_kernel<<<dim3(Nv / 128, Bv * Hv), 256>>>(qdst);       // writes g_avsp
    hmma_gemm_kernel<<<dim3(4, 128, 1), 256, SMEM_GEMM>>>(
        pAv, pAv, pAv, pWoT, pWoT, pWoT, out, out, out);
}

// round 8
// speedup vs baseline: 1.5441x; 1.0239x over previous
#include <cuda_runtime.h>
#include <cuda_bf16.h>
#include <math.h>
#include <stdint.h>

// Problem dims (fixed by the reference)
#define Bv   4
#define Nv   4096
#define Dv   512
#define Hv   8
#define DHv  64
#define Mv   128
#define BNv  (Bv*Nv)       // 16384 rows
#define Rv   (BNv*Hv)      // 131072 (b,n,h) rows
#define M2v  (2*Mv)        // 256
#define K3   1536          // B split K' = 3*512
#define K2   1024          // A split storage: [hi|lo]

#define DN_CONST    0.35355339059327373f   // 64^-0.25
#define RATIO_CONST 0.08838834764831845f   // 1/sqrt(128)

// ---------------- scratch (device globals: no allocation allowed) ----------
__device__ float g_value[(size_t)BNv*Dv];   // [bn][h*64+dh]
__device__ float g_pproj[(size_t)BNv*Dv];   // [r=bn*8+h][64]
__device__ float g_sproj[(size_t)BNv*Dv];
__device__ float g_norms[(size_t)Rv];
__device__ float g_kvs  [(size_t)Bv*Hv*M2v*DHv];   // [bh][m2][dh]
// split-transposed weights: [n=512][k'=1536] bf16 (= B^T row-major)
__device__ __nv_bfloat16 g_WvT[(size_t)Dv*K3];
__device__ __nv_bfloat16 g_WpT[(size_t)Dv*K3];
__device__ __nv_bfloat16 g_WoT[(size_t)Dv*K3];
// split A matrices: [m=16384][k2=1024] bf16  ([hi|lo]; GEMM remaps c>=32 -> hi)
__device__ __nv_bfloat16 g_Asp0[(size_t)BNv*K2];
__device__ __nv_bfloat16 g_Asp1[(size_t)BNv*K2];
__device__ __nv_bfloat16 g_Asp2[(size_t)BNv*K2];
__device__ __nv_bfloat16 g_avsp[(size_t)BNv*K2];
// fallback q'/k' scratch if d_out only holds the first tuple element
__device__ float g_qp[(size_t)Rv*M2v];
__device__ float g_kp[(size_t)Rv*M2v];

// =================== HMMA helpers (sm_80-era PTX, valid on sm_103 base) ====
__device__ __forceinline__ void ldsm_x4(uint32_t& r0, uint32_t& r1,
                                        uint32_t& r2, uint32_t& r3, uint32_t addr) {
    asm volatile("ldmatrix.sync.aligned.m8n8.x4.shared.b16 {%0,%1,%2,%3}, [%4];"
                 : "=r"(r0), "=r"(r1), "=r"(r2), "=r"(r3) : "r"(addr));
}

__device__ __forceinline__ void mma16816(float* c, const uint32_t* a,
                                         uint32_t b0, uint32_t b1) {
    asm volatile("mma.sync.aligned.m16n8k16.row.col.f32.bf16.bf16.f32 "
                 "{%0,%1,%2,%3}, {%4,%5,%6,%7}, {%8,%9}, {%0,%1,%2,%3};"
                 : "+f"(c[0]), "+f"(c[1]), "+f"(c[2]), "+f"(c[3])
                 : "r"(a[0]), "r"(a[1]), "r"(a[2]), "r"(a[3]), "r"(b0), "r"(b1));
}

__device__ __forceinline__ void cpa16(uint32_t dst, const void* src) {
    asm volatile("cp.async.cg.shared.global [%0], [%1], 16;"
                 :: "r"(dst), "l"(src));
}

// =================== W transpose + hi/lo split ==============================
__global__ __launch_bounds__(256)
void wsplit_kernel(const float* __restrict__ Wv, const float* __restrict__ Wp,
                   const float* __restrict__ Wo)
{
    const float* W; __nv_bfloat16* T;
    if (blockIdx.z == 0)      { W = Wv; T = g_WvT; }
    else if (blockIdx.z == 1) { W = Wp; T = g_WpT; }
    else                      { W = Wo; T = g_WoT; }
    int idx = blockIdx.x * 256 + threadIdx.x;   // 0..262143
    int k = idx >> 9, n = idx & 511;
    float x = W[idx];
    __nv_bfloat16 hi = __float2bfloat16_rn(x);
    __nv_bfloat16 lo = __float2bfloat16_rn(x - __bfloat162float(hi));
    T[(size_t)n*K3 + k]        = hi;
    T[(size_t)n*K3 + 512 + k]  = hi;
    T[(size_t)n*K3 + 1024 + k] = lo;
}

// A [16384][512] fp32 -> Asp [16384][1024] bf16: [hi|lo]; zbase selects matrix
__global__ __launch_bounds__(256)
void asplit_kernel(const float* __restrict__ A0, const float* __restrict__ A1,
                   const float* __restrict__ A2, int zbase)
{
    const int z = blockIdx.z + zbase;
    const float* A; __nv_bfloat16* T;
    if (z == 0)      { A = A0; T = g_Asp0; }
    else if (z == 1) { A = A1; T = g_Asp1; }
    else             { A = A2; T = g_Asp2; }
    size_t idx = (size_t)blockIdx.x * 256 + threadIdx.x;   // 0..8388607
    size_t m = idx >> 9; int k = (int)(idx & 511);
    float x = A[idx];
    __nv_bfloat16 hi = __float2bfloat16_rn(x);
    __nv_bfloat16 lo = __float2bfloat16_rn(x - __bfloat162float(hi));
    T[m*K2 + k]       = hi;
    T[m*K2 + 512 + k] = lo;
}

// =================== HMMA GEMM: C[16384x512] = Asp * T^T (3-term split) =====
// Block tile 128x128, 256 thr (8 warps 2x4, warp tile 64x32), BK=32,
// 5-stage cp.async ring, two stages per __syncthreads.
// BK=32 chunks c in [0,48): A-chunk = c<32 ? c : c-32   (terms:
//   c 0..15  : A.hi * W.hi   [K2 offset 0..511]
//   c 16..31 : A.lo * W.hi   [K2 offset 512..1023]
//   c 32..47 : A.hi * W.lo   [remap back to 0..511])
#define ASTR  40
#define STG_B 20480
#define NSTG  5
#define SMEM_GEMM (NSTG*STG_B)

__global__ __launch_bounds__(256, 2)
void hmma_gemm_kernel(const __nv_bfloat16* A0, const __nv_bfloat16* A1, const __nv_bfloat16* A2,
                      const __nv_bfloat16* B0, const __nv_bfloat16* B1, const __nv_bfloat16* B2,
                      float* C0, float* C1, float* C2, int zbase)
{
    const int z = blockIdx.z + zbase;
    const __nv_bfloat16* A; const __nv_bfloat16* Bt; float* C;
    if (z == 0)      { A = A0; Bt = B0; C = C0; }
    else if (z == 1) { A = A1; Bt = B1; C = C1; }
    else             { A = A2; Bt = B2; C = C2; }

    extern __shared__ __align__(16) char smem[];
    const uint32_t sbase = (uint32_t)__cvta_generic_to_shared(smem);
    const int tid = threadIdx.x;
    const int lane = tid & 31, wid = tid >> 5;
    const int r0 = blockIdx.y * 128;
    const int n0 = blockIdx.x * 128;
    const int wm = wid >> 2, wn = wid & 3;

    const int lrow = tid >> 2;           // 0..63
    const int lchk = (tid & 3) * 8;

    float acc[4][4][4];
#pragma unroll
    for (int mi = 0; mi < 4; mi++)
#pragma unroll
        for (int ni = 0; ni < 4; ni++)
#pragma unroll
            for (int q = 0; q < 4; q++) acc[mi][ni][q] = 0.0f;

    const __nv_bfloat16* gA = A  + (size_t)(r0 + lrow) * K2 + lchk;
    const __nv_bfloat16* gB = Bt + (size_t)(n0 + lrow) * K3 + lchk;
    const uint32_t sAoff = (uint32_t)((lrow * ASTR + lchk) * 2);

    #define LOAD_STAGE(c) do {                                                  \
        const int ca_ = ((c) < 32) ? (c) : ((c) - 32);                          \
        uint32_t sb_ = sbase + ((c) % NSTG) * STG_B;                            \
        cpa16(sb_ + sAoff,                         gA + ca_ * 32);              \
        cpa16(sb_ + sAoff + 64 * ASTR * 2,         gA + (size_t)64 * K2 + ca_ * 32); \
        cpa16(sb_ + 10240 + sAoff,                 gB + (c) * 32);              \
        cpa16(sb_ + 10240 + sAoff + 64 * ASTR * 2, gB + (size_t)64 * K3 + (c) * 32); \
        asm volatile("cp.async.commit_group;" ::: "memory");                    \
    } while (0)

    #define COMPUTE_STAGE(c) do {                                               \
        const uint32_t stA_ = sbase + ((c) % NSTG) * STG_B;                     \
        const uint32_t stB_ = stA_ + 10240;                                     \
        _Pragma("unroll")                                                       \
        for (int ks = 0; ks < 2; ks++) {                                        \
            const int ko = ks * 16;                                             \
            uint32_t a[4][4], b[2][4];                                          \
            _Pragma("unroll")                                                   \
            for (int mi = 0; mi < 4; mi++)                                      \
                ldsm_x4(a[mi][0], a[mi][1], a[mi][2], a[mi][3],                 \
                        stA_ + ((wm * 64 + mi * 16 + (lane & 15)) * ASTR        \
                               + ko + (lane >> 4) * 8) * 2);                    \
            _Pragma("unroll")                                                   \
            for (int pr = 0; pr < 2; pr++)                                      \
                ldsm_x4(b[pr][0], b[pr][1], b[pr][2], b[pr][3],                 \
                        stB_ + ((wn * 32 + pr * 16 + ((lane >> 4) << 3) + (lane & 7)) * ASTR \
                               + ko + ((lane >> 3) & 1) * 8) * 2);              \
            _Pragma("unroll")                                                   \
            for (int mi = 0; mi < 4; mi++) {                                    \
                mma16816(acc[mi][0], a[mi], b[0][0], b[0][1]);                  \
                mma16816(acc[mi][1], a[mi], b[0][2], b[0][3]);                  \
                mma16816(acc[mi][2], a[mi], b[1][0], b[1][1]);                  \
                mma16816(acc[mi][3], a[mi], b[1][2], b[1][3]);                  \
            }                                                                   \
        }                                                                       \
    } while (0)

#pragma unroll
    for (int p = 0; p < 3; p++) LOAD_STAGE(p);

    for (int kt = 0; kt < 48; kt += 2) {
        if (kt + 2 >= 48) {
            asm volatile("cp.async.wait_group 0;" ::: "memory");
        } else {
            asm volatile("cp.async.wait_group 1;" ::: "memory");
        }
        __syncthreads();
        if (kt + 3 < 48) LOAD_STAGE(kt + 3);
        if (kt + 4 < 48) LOAD_STAGE(kt + 4);
        COMPUTE_STAGE(kt);
        COMPUTE_STAGE(kt + 1);
    }

#pragma unroll
    for (int mi = 0; mi < 4; mi++)
#pragma unroll
        for (int ni = 0; ni < 4; ni++) {
            const int row = r0 + wm * 64 + mi * 16 + (lane >> 2);
            const int col = n0 + wn * 32 + ni * 8 + (lane & 3) * 2;
            float2 v0 = make_float2(acc[mi][ni][0], acc[mi][ni][1]);
            float2 v1 = make_float2(acc[mi][ni][2], acc[mi][ni][3]);
            *(float2*)(C + (size_t)row * 512 + col)       = v0;
            *(float2*)(C + (size_t)(row + 8) * 512 + col) = v1;
        }
    #undef LOAD_STAGE
    #undef COMPUTE_STAGE
}

// ---------------- norms (+ zero g_kvs for the atomic reduction) ------------
__global__ __launch_bounds__(256)
void norms_kernel()
{
    const int t = blockIdx.x * 256 + threadIdx.x;
    ((float4*)g_kvs)[t] = make_float4(0.f, 0.f, 0.f, 0.f);

    const float4* sp = (const float4*)(g_sproj + (size_t)t * 64);
    float acc = 0.0f;
#pragma unroll
    for (int i = 0; i < 16; i++) {
        float4 v = sp[i];
        acc = fmaf(v.x, v.x, acc);
        acc = fmaf(v.y, v.y, acc);
        acc = fmaf(v.z, v.z, acc);
        acc = fmaf(v.w, v.w, acc);
    }
    g_norms[t] = sqrtf(acc) * (1.0f / (float)Nv);
}

// ---------------- fourier features: GEMM [R,64]x[64,128] + fast sincos -----
__global__ __launch_bounds__(256)
void fourier_kernel(const float* __restrict__ proj,
                    const float* __restrict__ scale,
                    const float* __restrict__ offs,
                    float* __restrict__ outp, int kflag)
{
    __shared__ float As[8][128];
    __shared__ float Ps[8][128];
    const int tid = threadIdx.x;
    const int tx = tid & 15;
    const int ty = tid >> 4;
    const int r0 = blockIdx.y * 128;
    const bool is_k = (kflag != 0);

    const int arow = tid >> 1;
    const int akp  = (tid & 1) * 4;
    const int r    = r0 + arow;
    const int h    = r & 7;
    const float sc = scale[h] * DN_CONST;
    const float of = offs[h];

    float acc[8][8];
#pragma unroll
    for (int i = 0; i < 8; i++)
#pragma unroll
        for (int j = 0; j < 8; j++) acc[i][j] = 0.0f;

    for (int kk = 0; kk < 64; kk += 8) {
        float4 p4 = *(const float4*)(g_pproj + (size_t)r * 64 + kk + akp);
        float4 x4;
        if (is_k) {
            float4 s4 = *(const float4*)(g_sproj + (size_t)r * 64 + kk + akp);
            x4.x = sc * fmaf(of, s4.x, p4.x);
            x4.y = sc * fmaf(of, s4.y, p4.y);
            x4.z = sc * fmaf(of, s4.z, p4.z);
            x4.w = sc * fmaf(of, s4.w, p4.w);
        } else {
            x4.x = sc * p4.x; x4.y = sc * p4.y; x4.z = sc * p4.z; x4.w = sc * p4.w;
        }
        float4 pr4 = *(const float4*)(proj + (size_t)arow * 64 + kk + akp);
        __syncthreads();
        As[akp + 0][arow] = x4.x;
        As[akp + 1][arow] = x4.y;
        As[akp + 2][arow] = x4.z;
        As[akp + 3][arow] = x4.w;
        Ps[akp + 0][arow] = pr4.x;
        Ps[akp + 1][arow] = pr4.y;
        Ps[akp + 2][arow] = pr4.z;
        Ps[akp + 3][arow] = pr4.w;
        __syncthreads();
#pragma unroll
        for (int k = 0; k < 8; k++) {
            float a[8], b[8];
            *(float4*)(a)     = *(const float4*)&As[k][ty * 8];
            *(float4*)(a + 4) = *(const float4*)&As[k][ty * 8 + 4];
            *(float4*)(b)     = *(const float4*)&Ps[k][tx * 8];
            *(float4*)(b + 4) = *(const float4*)&Ps[k][tx * 8 + 4];
#pragma unroll
            for (int i = 0; i < 8; i++)
#pragma unroll
                for (int j = 0; j < 8; j++)
                    acc[i][j] = fmaf(a[i], b[j], acc[i][j]);
        }
    }
#pragma unroll
    for (int i = 0; i < 8; i++) {
        const int rr = r0 + ty * 8 + i;
        float* orow = outp + (size_t)rr * 256;
        float s[8], c[8];
#pragma unroll
        for (int j = 0; j < 8; j++) {
            __sincosf(acc[i][j], &s[j], &c[j]);
            s[j] *= RATIO_CONST;
            c[j] *= RATIO_CONST;
        }
        *(float4*)(orow + tx * 8)           = *(float4*)&s[0];
        *(float4*)(orow + tx * 8 + 4)       = *(float4*)&s[4];
        *(float4*)(orow + 128 + tx * 8)     = *(float4*)&c[0];
        *(float4*)(orow + 128 + tx * 8 + 4) = *(float4*)&c[4];
    }
}

// ---------------- kvs: per (b,h) [256 x 4096] x [4096 x 64], split-K x16 ---
__global__ __launch_bounds__(256)
void kvs_kernel(const float* __restrict__ kprime)
{
    __shared__ float Ks[8][256];
    __shared__ float Vs[8][64];
    const int tid = threadIdx.x;
    const int bh = blockIdx.y;
    const int b = bh >> 3, h = bh & 7;
    const int n0 = blockIdx.x * 256;
    const int tx = tid & 7;
    const int ty = tid >> 3;

    const int kni = tid >> 6;
    const int km4 = (tid & 63) * 4;
    const int vni = tid >> 4;
    const int vd4 = (tid & 15) * 4;

    float acc[8][8];
#pragma unroll
    for (int i = 0; i < 8; i++)
#pragma unroll
        for (int j = 0; j < 8; j++) acc[i][j] = 0.0f;

    for (int nn = 0; nn < 256; nn += 8) {
        const size_t nbase = (size_t)(b * Nv + n0 + nn);
        float4 k0 = *(const float4*)(kprime + ((nbase + kni)     * 8 + h) * 256 + km4);
        float4 k1 = *(const float4*)(kprime + ((nbase + kni + 4) * 8 + h) * 256 + km4);
        float4 v0 = make_float4(0.f, 0.f, 0.f, 0.f);
        if (tid < 128)
            v0 = *(const float4*)(g_value + (nbase + vni) * 512 + h * 64 + vd4);
        __syncthreads();
        *(float4*)&Ks[kni][km4]     = k0;
        *(float4*)&Ks[kni + 4][km4] = k1;
        if (tid < 128) *(float4*)&Vs[vni][vd4] = v0;
        __syncthreads();
#pragma unroll
        for (int ni = 0; ni < 8; ni++) {
            float a[8], v[8];
            *(float4*)(a)     = *(const float4*)&Ks[ni][ty * 8];
            *(float4*)(a + 4) = *(const float4*)&Ks[ni][ty * 8 + 4];
            *(float4*)(v)     = *(const float4*)&Vs[ni][tx * 8];
            *(float4*)(v + 4) = *(const float4*)&Vs[ni][tx * 8 + 4];
#pragma unroll
            for (int i = 0; i < 8; i++)
#pragma unroll
                for (int j = 0; j < 8; j++)
                    acc[i][j] = fmaf(a[i], v[j], acc[i][j]);
        }
    }
    float* dst = g_kvs + ((size_t)bh * 256 + ty * 8) * 64 + tx * 8;
#pragma unroll
    for (int i = 0; i < 8; i++)
#pragma unroll
        for (int j = 0; j < 8; j++)
            atomicAdd(dst + (size_t)i * 64 + j, acc[i][j]);
}

// ---------------- av: per (b,h) [4096 x 256] x [256 x 64] ------------------
__global__ __launch_bounds__(256)
void av_kernel(const float* __restrict__ qprime)
{
    __shared__ float As[16][128];
    __shared__ float Bs[16][64];
    const int tid = threadIdx.x;
    const int bh = blockIdx.y;
    const int b = bh >> 3, h = bh & 7;
    const int n0 = blockIdx.x * 128;
    const int tx = tid & 15;
    const int ty = tid >> 4;

    const int ar  = tid >> 2;
    const int ak4 = (tid & 3) * 4;
    const int bi  = tid >> 4;
    const int bj4 = (tid & 15) * 4;

    float acc[8][4];
#pragma unroll
    for (int i = 0; i < 8; i++)
#pragma unroll
        for (int j = 0; j < 4; j++) acc[i][j] = 0.0f;

    for (int kk = 0; kk < 256; kk += 16) {
        float4 a0 = *(const float4*)(qprime + ((size_t)(b * Nv + n0 + ar)      * 8 + h) * 256 + kk + ak4);
        float4 a1 = *(const float4*)(qprime + ((size_t)(b * Nv + n0 + ar + 64) * 8 + h) * 256 + kk + ak4);
        float4 b0 = *(const float4*)(g_kvs + ((size_t)bh * 256 + kk + bi) * 64 + bj4);
        __syncthreads();
        As[ak4 + 0][ar] = a0.x; As[ak4 + 1][ar] = a0.y;
        As[ak4 + 2][ar] = a0.z; As[ak4 + 3][ar] = a0.w;
        As[ak4 + 0][ar + 64] = a1.x; As[ak4 + 1][ar + 64] = a1.y;
        As[ak4 + 2][ar + 64] = a1.z; As[ak4 + 3][ar + 64] = a1.w;
        *(float4*)&Bs[bi][bj4] = b0;
        __syncthreads();
#pragma unroll
        for (int k = 0; k < 16; k++) {
            float a[8], bb[4];
            *(float4*)(a)     = *(const float4*)&As[k][ty * 8];
            *(float4*)(a + 4) = *(const float4*)&As[k][ty * 8 + 4];
            *(float4*)(bb)    = *(const float4*)&Bs[k][tx * 4];
#pragma unroll
            for (int i = 0; i < 8; i++)
#pragma unroll
                for (int j = 0; j < 4; j++)
                    acc[i][j] = fmaf(a[i], bb[j], acc[i][j]);
        }
    }
#pragma unroll
    for (int i = 0; i < 8; i++) {
        const int n = n0 + ty * 8 + i;
        const size_t m = (size_t)(b * Nv + n);
        const float nm = g_norms[m * 8 + h];
        const int kcol = h * 64 + tx * 4;
        __nv_bfloat16 hi4[4], lo4[4];
#pragma unroll
        for (int j = 0; j < 4; j++) {
            float v = acc[i][j] * nm;
            hi4[j] = __float2bfloat16_rn(v);
            lo4[j] = __float2bfloat16_rn(v - __bfloat162float(hi4[j]));
        }
        *(uint2*)(g_avsp + m * K2 + kcol)       = *(uint2*)hi4;
        *(uint2*)(g_avsp + m * K2 + 512 + kcol) = *(uint2*)lo4;
    }
}

// ---------------------------------------------------------------------------
extern "C" void kernel_launch(void* const* d_in, const int* in_sizes, int n_in,
                              void* d_out, int out_size)
{
    const float* src    = (const float*)d_in[0];
    const float* pos    = (const float*)d_in[1];
    const float* slopes = (const float*)d_in[2];
    const float* Wv     = (const float*)d_in[3];
    const float* Wp     = (const float*)d_in[4];
    const float* scale  = (const float*)d_in[5];
    const float* offs   = (const float*)d_in[6];
    const float* Wout   = (const float*)d_in[7];
    const float* proj   = (const float*)d_in[8];

    float* out = (float*)d_out;

    void* p;
    float *pvalue, *ppproj, *psproj;
    __nv_bfloat16 *pWvT, *pWpT, *pWoT, *pA0, *pA1, *pA2, *pAv;
    cudaGetSymbolAddress(&p, g_value); pvalue = (float*)p;
    cudaGetSymbolAddress(&p, g_pproj); ppproj = (float*)p;
    cudaGetSymbolAddress(&p, g_sproj); psproj = (float*)p;
    cudaGetSymbolAddress(&p, g_WvT);   pWvT   = (__nv_bfloat16*)p;
    cudaGetSymbolAddress(&p, g_WpT);   pWpT   = (__nv_bfloat16*)p;
    cudaGetSymbolAddress(&p, g_WoT);   pWoT   = (__nv_bfloat16*)p;
    cudaGetSymbolAddress(&p, g_Asp0);  pA0    = (__nv_bfloat16*)p;
    cudaGetSymbolAddress(&p, g_Asp1);  pA1    = (__nv_bfloat16*)p;
    cudaGetSymbolAddress(&p, g_Asp2);  pA2    = (__nv_bfloat16*)p;
    cudaGetSymbolAddress(&p, g_avsp);  pAv    = (__nv_bfloat16*)p;

    // tuple output: (out[BN*D], q'[R*2M], k'[R*2M]) flattened
    const size_t OUT0 = (size_t)BNv * Dv;
    const size_t QPN  = (size_t)Rv * M2v;
    float* qdst;
    float* kdst;
    if ((size_t)out_size >= OUT0 + 2 * QPN) {
        qdst = out + OUT0;
        kdst = out + OUT0 + QPN;
    } else {
        cudaGetSymbolAddress(&p, g_qp); qdst = (float*)p;
        cudaGetSymbolAddress(&p, g_kp); kdst = (float*)p;
    }

    // one-time setup: smem carveout + side stream + events (capturable fork/join)
    static cudaStream_t s1;
    static cudaEvent_t e_ws, e_s, e_k, e_kvs;
    static int init_done = 0;
    if (!init_done) {
        cudaFuncSetAttribute(hmma_gemm_kernel,
                             cudaFuncAttributeMaxDynamicSharedMemorySize, SMEM_GEMM);
        cudaStreamCreateWithFlags(&s1, cudaStreamNonBlocking);
        cudaEventCreateWithFlags(&e_ws,  cudaEventDisableTiming);
        cudaEventCreateWithFlags(&e_s,   cudaEventDisableTiming);
        cudaEventCreateWithFlags(&e_k,   cudaEventDisableTiming);
        cudaEventCreateWithFlags(&e_kvs, cudaEventDisableTiming);
        init_done = 1;
    }

    // ---- stream 0 (captured default stream) ----
    wsplit_kernel<<<dim3(1024, 1, 3), 256>>>(Wv, Wp, Wout);
    cudaEventRecord(e_ws, 0);                 // fork point: W splits done
    cudaStreamWaitEvent(s1, e_ws, 0);

    // s0: pos/slopes -> pproj/sproj -> k' -> q'
    asplit_kernel<<<dim3(32768, 1, 2), 256>>>(src, pos, slopes, 1);   // pos, slopes
    hmma_gemm_kernel<<<dim3(4, 128, 2), 256, SMEM_GEMM>>>(
        pA0, pA1, pA2, pWvT, pWpT, pWpT, pvalue, ppproj, psproj, 1);  // pproj, sproj
    cudaEventRecord(e_s, 0);                  // pproj+sproj ready
    fourier_kernel<<<dim3(1, Rv / 128, 1), 256>>>(proj, scale, offs, kdst, 1); // k'
    cudaEventRecord(e_k, 0);
    fourier_kernel<<<dim3(1, Rv / 128, 1), 256>>>(proj, scale, offs, qdst, 0); // q'

    // ---- stream 1: value path + norms + kvs ----
    asplit_kernel<<<dim3(32768, 1, 1), 256, 0, s1>>>(src, pos, slopes, 0);     // src
    hmma_gemm_kernel<<<dim3(4, 128, 1), 256, SMEM_GEMM, s1>>>(
        pA0, pA1, pA2, pWvT, pWpT, pWpT, pvalue, ppproj, psproj, 0);           // value
    cudaStreamWaitEvent(s1, e_s, 0);
    norms_kernel<<<Rv / 256, 256, 0, s1>>>();             // needs sproj; zeros g_kvs
    cudaStreamWaitEvent(s1, e_k, 0);
    kvs_kernel<<<dim3(16, Bv * Hv), 256, 0, s1>>>(kdst);  // needs k', value, zeroed kvs
    cudaEventRecord(e_kvs, s1);

    // ---- join on stream 0 ----
    cudaStreamWaitEvent(0, e_kvs, 0);
    av_kernel<<<dim3(Nv / 128, Bv * Hv), 256>>>(qdst);    // needs q', kvs, norms
    hmma_gemm_kernel<<<dim3(4, 128, 1), 256, SMEM_GEMM>>>(
        pAv, pAv, pAv, pWoT, pWoT, pWoT, out, out, out, 0);
}

// round 9
// speedup vs baseline: 1.5801x; 1.0233x over previous
#include <cuda_runtime.h>
#include <cuda_bf16.h>
#include <math.h>
#include <stdint.h>

// Problem dims (fixed by the reference)
#define Bv   4
#define Nv   4096
#define Dv   512
#define Hv   8
#define DHv  64
#define Mv   128
#define BNv  (Bv*Nv)       // 16384 rows
#define Rv   (BNv*Hv)      // 131072 (b,n,h) rows
#define M2v  (2*Mv)        // 256
#define K3   1536          // B split K' = 3*512
#define K2   1024          // A split storage: [hi|lo]

#define DN_CONST    0.35355339059327373f   // 64^-0.25
#define RATIO_CONST 0.08838834764831845f   // 1/sqrt(128)

// ---------------- scratch (device globals: no allocation allowed) ----------
__device__ float g_value[(size_t)BNv*Dv];   // [bn][h*64+dh]
__device__ float g_pproj[(size_t)BNv*Dv];   // [r=bn*8+h][64]
__device__ float g_sproj[(size_t)BNv*Dv];
__device__ float g_norms[(size_t)Rv];
__device__ float g_kvs  [(size_t)Bv*Hv*M2v*DHv];   // [bh][m2][dh]
// split-transposed weights: [n=512][k'=1536] bf16 (= B^T row-major)
__device__ __nv_bfloat16 g_WvT[(size_t)Dv*K3];
__device__ __nv_bfloat16 g_WpT[(size_t)Dv*K3];
__device__ __nv_bfloat16 g_WoT[(size_t)Dv*K3];
// split A matrices: [m=16384][k2=1024] bf16  ([hi|lo]; GEMM remaps c>=32 -> hi)
__device__ __nv_bfloat16 g_Asp0[(size_t)BNv*K2];
__device__ __nv_bfloat16 g_Asp1[(size_t)BNv*K2];
__device__ __nv_bfloat16 g_Asp2[(size_t)BNv*K2];
__device__ __nv_bfloat16 g_avsp[(size_t)BNv*K2];
// fallback q'/k' scratch if d_out only holds the first tuple element
__device__ float g_qp[(size_t)Rv*M2v];
__device__ float g_kp[(size_t)Rv*M2v];

// =================== HMMA helpers (sm_80-era PTX, valid on sm_103 base) ====
__device__ __forceinline__ void ldsm_x4(uint32_t& r0, uint32_t& r1,
                                        uint32_t& r2, uint32_t& r3, uint32_t addr) {
    asm volatile("ldmatrix.sync.aligned.m8n8.x4.shared.b16 {%0,%1,%2,%3}, [%4];"
                 : "=r"(r0), "=r"(r1), "=r"(r2), "=r"(r3) : "r"(addr));
}

__device__ __forceinline__ void mma16816(float* c, const uint32_t* a,
                                         uint32_t b0, uint32_t b1) {
    asm volatile("mma.sync.aligned.m16n8k16.row.col.f32.bf16.bf16.f32 "
                 "{%0,%1,%2,%3}, {%4,%5,%6,%7}, {%8,%9}, {%0,%1,%2,%3};"
                 : "+f"(c[0]), "+f"(c[1]), "+f"(c[2]), "+f"(c[3])
                 : "r"(a[0]), "r"(a[1]), "r"(a[2]), "r"(a[3]), "r"(b0), "r"(b1));
}

__device__ __forceinline__ void cpa16(uint32_t dst, const void* src) {
    asm volatile("cp.async.cg.shared.global [%0], [%1], 16;"
                 :: "r"(dst), "l"(src));
}

// =================== W transpose + hi/lo split ==============================
__global__ __launch_bounds__(256)
void wsplit_kernel(const float* __restrict__ Wv, const float* __restrict__ Wp,
                   const float* __restrict__ Wo)
{
    const float* W; __nv_bfloat16* T;
    if (blockIdx.z == 0)      { W = Wv; T = g_WvT; }
    else if (blockIdx.z == 1) { W = Wp; T = g_WpT; }
    else                      { W = Wo; T = g_WoT; }
    int idx = blockIdx.x * 256 + threadIdx.x;   // 0..262143
    int k = idx >> 9, n = idx & 511;
    float x = W[idx];
    __nv_bfloat16 hi = __float2bfloat16_rn(x);
    __nv_bfloat16 lo = __float2bfloat16_rn(x - __bfloat162float(hi));
    T[(size_t)n*K3 + k]        = hi;
    T[(size_t)n*K3 + 512 + k]  = hi;
    T[(size_t)n*K3 + 1024 + k] = lo;
}

// A [16384][512] fp32 -> Asp [16384][1024] bf16: [hi|lo]; zbase selects matrix
__global__ __launch_bounds__(256)
void asplit_kernel(const float* __restrict__ A0, const float* __restrict__ A1,
                   const float* __restrict__ A2, int zbase)
{
    const int z = blockIdx.z + zbase;
    const float* A; __nv_bfloat16* T;
    if (z == 0)      { A = A0; T = g_Asp0; }
    else if (z == 1) { A = A1; T = g_Asp1; }
    else             { A = A2; T = g_Asp2; }
    size_t idx = (size_t)blockIdx.x * 256 + threadIdx.x;   // 0..8388607
    size_t m = idx >> 9; int k = (int)(idx & 511);
    float x = A[idx];
    __nv_bfloat16 hi = __float2bfloat16_rn(x);
    __nv_bfloat16 lo = __float2bfloat16_rn(x - __bfloat162float(hi));
    T[m*K2 + k]       = hi;
    T[m*K2 + 512 + k] = lo;
}

// =================== HMMA GEMM: C[16384x512] = Asp * T^T (3-term split) =====
// Block tile 128x128, 256 thr (8 warps 2x4, warp tile 64x32), BK=32,
// 5-stage cp.async ring, two stages per __syncthreads.
// BK=32 chunks c in [0,48): A-chunk = c<32 ? c : c-32
#define ASTR  40
#define STG_B 20480
#define NSTG  5
#define SMEM_GEMM (NSTG*STG_B)

__global__ __launch_bounds__(256, 2)
void hmma_gemm_kernel(const __nv_bfloat16* A0, const __nv_bfloat16* A1, const __nv_bfloat16* A2,
                      const __nv_bfloat16* B0, const __nv_bfloat16* B1, const __nv_bfloat16* B2,
                      float* C0, float* C1, float* C2, int zbase)
{
    const int z = blockIdx.z + zbase;
    const __nv_bfloat16* A; const __nv_bfloat16* Bt; float* C;
    if (z == 0)      { A = A0; Bt = B0; C = C0; }
    else if (z == 1) { A = A1; Bt = B1; C = C1; }
    else             { A = A2; Bt = B2; C = C2; }

    extern __shared__ __align__(16) char smem[];
    const uint32_t sbase = (uint32_t)__cvta_generic_to_shared(smem);
    const int tid = threadIdx.x;
    const int lane = tid & 31, wid = tid >> 5;
    const int r0 = blockIdx.y * 128;
    const int n0 = blockIdx.x * 128;
    const int wm = wid >> 2, wn = wid & 3;

    const int lrow = tid >> 2;           // 0..63
    const int lchk = (tid & 3) * 8;

    float acc[4][4][4];
#pragma unroll
    for (int mi = 0; mi < 4; mi++)
#pragma unroll
        for (int ni = 0; ni < 4; ni++)
#pragma unroll
            for (int q = 0; q < 4; q++) acc[mi][ni][q] = 0.0f;

    const __nv_bfloat16* gA = A  + (size_t)(r0 + lrow) * K2 + lchk;
    const __nv_bfloat16* gB = Bt + (size_t)(n0 + lrow) * K3 + lchk;
    const uint32_t sAoff = (uint32_t)((lrow * ASTR + lchk) * 2);

    #define LOAD_STAGE(c) do {                                                  \
        const int ca_ = ((c) < 32) ? (c) : ((c) - 32);                          \
        uint32_t sb_ = sbase + ((c) % NSTG) * STG_B;                            \
        cpa16(sb_ + sAoff,                         gA + ca_ * 32);              \
        cpa16(sb_ + sAoff + 64 * ASTR * 2,         gA + (size_t)64 * K2 + ca_ * 32); \
        cpa16(sb_ + 10240 + sAoff,                 gB + (c) * 32);              \
        cpa16(sb_ + 10240 + sAoff + 64 * ASTR * 2, gB + (size_t)64 * K3 + (c) * 32); \
        asm volatile("cp.async.commit_group;" ::: "memory");                    \
    } while (0)

    #define COMPUTE_STAGE(c) do {                                               \
        const uint32_t stA_ = sbase + ((c) % NSTG) * STG_B;                     \
        const uint32_t stB_ = stA_ + 10240;                                     \
        _Pragma("unroll")                                                       \
        for (int ks = 0; ks < 2; ks++) {                                        \
            const int ko = ks * 16;                                             \
            uint32_t a[4][4], b[2][4];                                          \
            _Pragma("unroll")                                                   \
            for (int mi = 0; mi < 4; mi++)                                      \
                ldsm_x4(a[mi][0], a[mi][1], a[mi][2], a[mi][3],                 \
                        stA_ + ((wm * 64 + mi * 16 + (lane & 15)) * ASTR        \
                               + ko + (lane >> 4) * 8) * 2);                    \
            _Pragma("unroll")                                                   \
            for (int pr = 0; pr < 2; pr++)                                      \
                ldsm_x4(b[pr][0], b[pr][1], b[pr][2], b[pr][3],                 \
                        stB_ + ((wn * 32 + pr * 16 + ((lane >> 4) << 3) + (lane & 7)) * ASTR \
                               + ko + ((lane >> 3) & 1) * 8) * 2);              \
            _Pragma("unroll")                                                   \
            for (int mi = 0; mi < 4; mi++) {                                    \
                mma16816(acc[mi][0], a[mi], b[0][0], b[0][1]);                  \
                mma16816(acc[mi][1], a[mi], b[0][2], b[0][3]);                  \
                mma16816(acc[mi][2], a[mi], b[1][0], b[1][1]);                  \
                mma16816(acc[mi][3], a[mi], b[1][2], b[1][3]);                  \
            }                                                                   \
        }                                                                       \
    } while (0)

#pragma unroll
    for (int p = 0; p < 3; p++) LOAD_STAGE(p);

    for (int kt = 0; kt < 48; kt += 2) {
        if (kt + 2 >= 48) {
            asm volatile("cp.async.wait_group 0;" ::: "memory");
        } else {
            asm volatile("cp.async.wait_group 1;" ::: "memory");
        }
        __syncthreads();
        if (kt + 3 < 48) LOAD_STAGE(kt + 3);
        if (kt + 4 < 48) LOAD_STAGE(kt + 4);
        COMPUTE_STAGE(kt);
        COMPUTE_STAGE(kt + 1);
    }

#pragma unroll
    for (int mi = 0; mi < 4; mi++)
#pragma unroll
        for (int ni = 0; ni < 4; ni++) {
            const int row = r0 + wm * 64 + mi * 16 + (lane >> 2);
            const int col = n0 + wn * 32 + ni * 8 + (lane & 3) * 2;
            float2 v0 = make_float2(acc[mi][ni][0], acc[mi][ni][1]);
            float2 v1 = make_float2(acc[mi][ni][2], acc[mi][ni][3]);
            *(float2*)(C + (size_t)row * 512 + col)       = v0;
            *(float2*)(C + (size_t)(row + 8) * 512 + col) = v1;
        }
    #undef LOAD_STAGE
    #undef COMPUTE_STAGE
}

// ---------------- norms (+ zero g_kvs for the atomic reduction) ------------
__global__ __launch_bounds__(256)
void norms_kernel()
{
    const int t = blockIdx.x * 256 + threadIdx.x;
    ((float4*)g_kvs)[t] = make_float4(0.f, 0.f, 0.f, 0.f);

    const float4* sp = (const float4*)(g_sproj + (size_t)t * 64);
    float acc = 0.0f;
#pragma unroll
    for (int i = 0; i < 16; i++) {
        float4 v = sp[i];
        acc = fmaf(v.x, v.x, acc);
        acc = fmaf(v.y, v.y, acc);
        acc = fmaf(v.z, v.z, acc);
        acc = fmaf(v.w, v.w, acc);
    }
    g_norms[t] = sqrtf(acc) * (1.0f / (float)Nv);
}

// ---------------- fused fourier: q' AND k' in one pass ---------------------
// Block 64 rows x 64 m, per-thread 4x4 per acc (acc_p, acc_s).
// Loader pre-scales: Ap = sc*pproj, Asl = sc*of*sproj
//   => dd_q = acc_p ; dd_k = acc_p + acc_s.
__global__ __launch_bounds__(256, 3)
void fourier_qk_kernel(const float* __restrict__ proj,
                       const float* __restrict__ scale,
                       const float* __restrict__ offs,
                       float* __restrict__ outq,
                       float* __restrict__ outk)
{
    __shared__ float Ap [8][64];
    __shared__ float Asl[8][64];
    __shared__ float Ps [8][64];
    const int tid = threadIdx.x;
    const int tx = tid & 15;          // m group: 16 x 4
    const int ty = tid >> 4;          // row group: 16 x 4
    const int r0 = blockIdx.y * 64;
    const int m0 = blockIdx.x * 64;

    // A loader: 256 threads -> 64 rows x 2 k-halves x {p,s}
    const int arow  = tid >> 2;           // 0..63
    const int aslot = tid & 3;            // 0,1: Ap halves; 2,3: Asl halves
    const int akp   = (aslot & 1) * 4;
    const bool is_s = (aslot >= 2);
    const int ah    = arow & 7;           // r0 multiple of 64 -> h = arow&7
    const float sc  = scale[ah] * DN_CONST;
    const float ascale = is_s ? (sc * offs[ah]) : sc;
    const float* asrc = (is_s ? g_sproj : g_pproj) + (size_t)(r0 + arow) * 64 + akp;

    // Ps loader: tid<128 -> 64 m-rows x 2 k-halves
    const int mrow = tid >> 1;            // 0..127 (used when tid<128)
    const int mkp  = (tid & 1) * 4;

    float acc_p[4][4], acc_s[4][4];
#pragma unroll
    for (int i = 0; i < 4; i++)
#pragma unroll
        for (int j = 0; j < 4; j++) { acc_p[i][j] = 0.0f; acc_s[i][j] = 0.0f; }

    for (int kk = 0; kk < 64; kk += 8) {
        float4 a4 = *(const float4*)(asrc + kk);
        float4 p4 = make_float4(0.f, 0.f, 0.f, 0.f);
        if (tid < 128)
            p4 = *(const float4*)(proj + (size_t)(m0 + mrow) * 64 + kk + mkp);
        __syncthreads();
        float* adst = (is_s ? &Asl[0][0] : &Ap[0][0]);
        adst[(akp + 0) * 64 + arow] = ascale * a4.x;
        adst[(akp + 1) * 64 + arow] = ascale * a4.y;
        adst[(akp + 2) * 64 + arow] = ascale * a4.z;
        adst[(akp + 3) * 64 + arow] = ascale * a4.w;
        if (tid < 128) {
            Ps[mkp + 0][mrow] = p4.x;
            Ps[mkp + 1][mrow] = p4.y;
            Ps[mkp + 2][mrow] = p4.z;
            Ps[mkp + 3][mrow] = p4.w;
        }
        __syncthreads();
#pragma unroll
        for (int k = 0; k < 8; k++) {
            float ap[4], as[4], b[4];
            *(float4*)(ap) = *(const float4*)&Ap [k][ty * 4];
            *(float4*)(as) = *(const float4*)&Asl[k][ty * 4];
            *(float4*)(b)  = *(const float4*)&Ps [k][tx * 4];
#pragma unroll
            for (int i = 0; i < 4; i++)
#pragma unroll
                for (int j = 0; j < 4; j++) {
                    acc_p[i][j] = fmaf(ap[i], b[j], acc_p[i][j]);
                    acc_s[i][j] = fmaf(as[i], b[j], acc_s[i][j]);
                }
        }
    }

#pragma unroll
    for (int i = 0; i < 4; i++) {
        const int rr = r0 + ty * 4 + i;
        float* qrow = outq + (size_t)rr * 256 + m0 + tx * 4;
        float* krow = outk + (size_t)rr * 256 + m0 + tx * 4;
        float qs[4], qc[4], ks[4], kc[4];
#pragma unroll
        for (int j = 0; j < 4; j++) {
            float dq = acc_p[i][j];
            float dk = dq + acc_s[i][j];
            __sincosf(dq, &qs[j], &qc[j]);
            __sincosf(dk, &ks[j], &kc[j]);
            qs[j] *= RATIO_CONST; qc[j] *= RATIO_CONST;
            ks[j] *= RATIO_CONST; kc[j] *= RATIO_CONST;
        }
        *(float4*)(qrow)       = *(float4*)qs;
        *(float4*)(qrow + 128) = *(float4*)qc;
        *(float4*)(krow)       = *(float4*)ks;
        *(float4*)(krow + 128) = *(float4*)kc;
    }
}

// ---------------- kvs: per (b,h) [256 x 4096] x [4096 x 64], split-K x16 ---
__global__ __launch_bounds__(256)
void kvs_kernel(const float* __restrict__ kprime)
{
    __shared__ float Ks[8][256];
    __shared__ float Vs[8][64];
    const int tid = threadIdx.x;
    const int bh = blockIdx.y;
    const int b = bh >> 3, h = bh & 7;
    const int n0 = blockIdx.x * 256;
    const int tx = tid & 7;
    const int ty = tid >> 3;

    const int kni = tid >> 6;
    const int km4 = (tid & 63) * 4;
    const int vni = tid >> 4;
    const int vd4 = (tid & 15) * 4;

    float acc[8][8];
#pragma unroll
    for (int i = 0; i < 8; i++)
#pragma unroll
        for (int j = 0; j < 8; j++) acc[i][j] = 0.0f;

    for (int nn = 0; nn < 256; nn += 8) {
        const size_t nbase = (size_t)(b * Nv + n0 + nn);
        float4 k0 = *(const float4*)(kprime + ((nbase + kni)     * 8 + h) * 256 + km4);
        float4 k1 = *(const float4*)(kprime + ((nbase + kni + 4) * 8 + h) * 256 + km4);
        float4 v0 = make_float4(0.f, 0.f, 0.f, 0.f);
        if (tid < 128)
            v0 = *(const float4*)(g_value + (nbase + vni) * 512 + h * 64 + vd4);
        __syncthreads();
        *(float4*)&Ks[kni][km4]     = k0;
        *(float4*)&Ks[kni + 4][km4] = k1;
        if (tid < 128) *(float4*)&Vs[vni][vd4] = v0;
        __syncthreads();
#pragma unroll
        for (int ni = 0; ni < 8; ni++) {
            float a[8], v[8];
            *(float4*)(a)     = *(const float4*)&Ks[ni][ty * 8];
            *(float4*)(a + 4) = *(const float4*)&Ks[ni][ty * 8 + 4];
            *(float4*)(v)     = *(const float4*)&Vs[ni][tx * 8];
            *(float4*)(v + 4) = *(const float4*)&Vs[ni][tx * 8 + 4];
#pragma unroll
            for (int i = 0; i < 8; i++)
#pragma unroll
                for (int j = 0; j < 8; j++)
                    acc[i][j] = fmaf(a[i], v[j], acc[i][j]);
        }
    }
    float* dst = g_kvs + ((size_t)bh * 256 + ty * 8) * 64 + tx * 8;
#pragma unroll
    for (int i = 0; i < 8; i++)
#pragma unroll
        for (int j = 0; j < 8; j++)
            atomicAdd(dst + (size_t)i * 64 + j, acc[i][j]);
}

// ---------------- av: per (b,h) [4096 x 256] x [256 x 64] ------------------
__global__ __launch_bounds__(256)
void av_kernel(const float* __restrict__ qprime)
{
    __shared__ float As[16][128];
    __shared__ float Bs[16][64];
    const int tid = threadIdx.x;
    const int bh = blockIdx.y;
    const int b = bh >> 3, h = bh & 7;
    const int n0 = blockIdx.x * 128;
    const int tx = tid & 15;
    const int ty = tid >> 4;

    const int ar  = tid >> 2;
    const int ak4 = (tid & 3) * 4;
    const int bi  = tid >> 4;
    const int bj4 = (tid & 15) * 4;

    float acc[8][4];
#pragma unroll
    for (int i = 0; i < 8; i++)
#pragma unroll
        for (int j = 0; j < 4; j++) acc[i][j] = 0.0f;

    for (int kk = 0; kk < 256; kk += 16) {
        float4 a0 = *(const float4*)(qprime + ((size_t)(b * Nv + n0 + ar)      * 8 + h) * 256 + kk + ak4);
        float4 a1 = *(const float4*)(qprime + ((size_t)(b * Nv + n0 + ar + 64) * 8 + h) * 256 + kk + ak4);
        float4 b0 = *(const float4*)(g_kvs + ((size_t)bh * 256 + kk + bi) * 64 + bj4);
        __syncthreads();
        As[ak4 + 0][ar] = a0.x; As[ak4 + 1][ar] = a0.y;
        As[ak4 + 2][ar] = a0.z; As[ak4 + 3][ar] = a0.w;
        As[ak4 + 0][ar + 64] = a1.x; As[ak4 + 1][ar + 64] = a1.y;
        As[ak4 + 2][ar + 64] = a1.z; As[ak4 + 3][ar + 64] = a1.w;
        *(float4*)&Bs[bi][bj4] = b0;
        __syncthreads();
#pragma unroll
        for (int k = 0; k < 16; k++) {
            float a[8], bb[4];
            *(float4*)(a)     = *(const float4*)&As[k][ty * 8];
            *(float4*)(a + 4) = *(const float4*)&As[k][ty * 8 + 4];
            *(float4*)(bb)    = *(const float4*)&Bs[k][tx * 4];
#pragma unroll
            for (int i = 0; i < 8; i++)
#pragma unroll
                for (int j = 0; j < 4; j++)
                    acc[i][j] = fmaf(a[i], bb[j], acc[i][j]);
        }
    }
#pragma unroll
    for (int i = 0; i < 8; i++) {
        const int n = n0 + ty * 8 + i;
        const size_t m = (size_t)(b * Nv + n);
        const float nm = g_norms[m * 8 + h];
        const int kcol = h * 64 + tx * 4;
        __nv_bfloat16 hi4[4], lo4[4];
#pragma unroll
        for (int j = 0; j < 4; j++) {
            float v = acc[i][j] * nm;
            hi4[j] = __float2bfloat16_rn(v);
            lo4[j] = __float2bfloat16_rn(v - __bfloat162float(hi4[j]));
        }
        *(uint2*)(g_avsp + m * K2 + kcol)       = *(uint2*)hi4;
        *(uint2*)(g_avsp + m * K2 + 512 + kcol) = *(uint2*)lo4;
    }
}

// ---------------------------------------------------------------------------
extern "C" void kernel_launch(void* const* d_in, const int* in_sizes, int n_in,
                              void* d_out, int out_size)
{
    const float* src    = (const float*)d_in[0];
    const float* pos    = (const float*)d_in[1];
    const float* slopes = (const float*)d_in[2];
    const float* Wv     = (const float*)d_in[3];
    const float* Wp     = (const float*)d_in[4];
    const float* scale  = (const float*)d_in[5];
    const float* offs   = (const float*)d_in[6];
    const float* Wout   = (const float*)d_in[7];
    const float* proj   = (const float*)d_in[8];

    float* out = (float*)d_out;

    void* p;
    float *pvalue, *ppproj, *psproj;
    __nv_bfloat16 *pWvT, *pWpT, *pWoT, *pA0, *pA1, *pA2, *pAv;
    cudaGetSymbolAddress(&p, g_value); pvalue = (float*)p;
    cudaGetSymbolAddress(&p, g_pproj); ppproj = (float*)p;
    cudaGetSymbolAddress(&p, g_sproj); psproj = (float*)p;
    cudaGetSymbolAddress(&p, g_WvT);   pWvT   = (__nv_bfloat16*)p;
    cudaGetSymbolAddress(&p, g_WpT);   pWpT   = (__nv_bfloat16*)p;
    cudaGetSymbolAddress(&p, g_WoT);   pWoT   = (__nv_bfloat16*)p;
    cudaGetSymbolAddress(&p, g_Asp0);  pA0    = (__nv_bfloat16*)p;
    cudaGetSymbolAddress(&p, g_Asp1);  pA1    = (__nv_bfloat16*)p;
    cudaGetSymbolAddress(&p, g_Asp2);  pA2    = (__nv_bfloat16*)p;
    cudaGetSymbolAddress(&p, g_avsp);  pAv    = (__nv_bfloat16*)p;

    // tuple output: (out[BN*D], q'[R*2M], k'[R*2M]) flattened
    const size_t OUT0 = (size_t)BNv * Dv;
    const size_t QPN  = (size_t)Rv * M2v;
    float* qdst;
    float* kdst;
    if ((size_t)out_size >= OUT0 + 2 * QPN) {
        qdst = out + OUT0;
        kdst = out + OUT0 + QPN;
    } else {
        cudaGetSymbolAddress(&p, g_qp); qdst = (float*)p;
        cudaGetSymbolAddress(&p, g_kp); kdst = (float*)p;
    }

    // one-time setup: smem carveout + side stream + events (capturable fork/join)
    static cudaStream_t s1;
    static cudaEvent_t e_ws, e_s, e_qk, e_kvs;
    static int init_done = 0;
    if (!init_done) {
        cudaFuncSetAttribute(hmma_gemm_kernel,
                             cudaFuncAttributeMaxDynamicSharedMemorySize, SMEM_GEMM);
        cudaStreamCreateWithFlags(&s1, cudaStreamNonBlocking);
        cudaEventCreateWithFlags(&e_ws,  cudaEventDisableTiming);
        cudaEventCreateWithFlags(&e_s,   cudaEventDisableTiming);
        cudaEventCreateWithFlags(&e_qk,  cudaEventDisableTiming);
        cudaEventCreateWithFlags(&e_kvs, cudaEventDisableTiming);
        init_done = 1;
    }

    // ---- stream 0 (captured default stream) ----
    wsplit_kernel<<<dim3(1024, 1, 3), 256>>>(Wv, Wp, Wout);
    cudaEventRecord(e_ws, 0);                 // fork point: W splits done
    cudaStreamWaitEvent(s1, e_ws, 0);

    // s0: pos/slopes -> pproj/sproj -> fused q'+k'
    asplit_kernel<<<dim3(32768, 1, 2), 256>>>(src, pos, slopes, 1);   // pos, slopes
    hmma_gemm_kernel<<<dim3(4, 128, 2), 256, SMEM_GEMM>>>(
        pA0, pA1, pA2, pWvT, pWpT, pWpT, pvalue, ppproj, psproj, 1);  // pproj, sproj
    cudaEventRecord(e_s, 0);                  // pproj+sproj ready
    fourier_qk_kernel<<<dim3(2, Rv / 64), 256>>>(proj, scale, offs, qdst, kdst);
    cudaEventRecord(e_qk, 0);

    // ---- stream 1: value path + norms + kvs ----
    asplit_kernel<<<dim3(32768, 1, 1), 256, 0, s1>>>(src, pos, slopes, 0);     // src
    hmma_gemm_kernel<<<dim3(4, 128, 1), 256, SMEM_GEMM, s1>>>(
        pA0, pA1, pA2, pWvT, pWpT, pWpT, pvalue, ppproj, psproj, 0);           // value
    cudaStreamWaitEvent(s1, e_s, 0);
    norms_kernel<<<Rv / 256, 256, 0, s1>>>();             // needs sproj; zeros g_kvs
    cudaStreamWaitEvent(s1, e_qk, 0);
    kvs_kernel<<<dim3(16, Bv * Hv), 256, 0, s1>>>(kdst);  // needs k', value, zeroed kvs
    cudaEventRecord(e_kvs, s1);

    // ---- join on stream 0 ----
    cudaStreamWaitEvent(0, e_kvs, 0);
    av_kernel<<<dim3(Nv / 128, Bv * Hv), 256>>>(qdst);    // needs q', kvs, norms
    hmma_gemm_kernel<<<dim3(4, 128, 1), 256, SMEM_GEMM>>>(
        pAv, pAv, pAv, pWoT, pWoT, pWoT, out, out, out, 0);
}

// round 10
// speedup vs baseline: 1.6452x; 1.0412x over previous
#include <cuda_runtime.h>
#include <cuda_bf16.h>
#include <math.h>
#include <stdint.h>

#define Bv   4
#define Nv   4096
#define Dv   512
#define Hv   8
#define DHv  64
#define Mv   128
#define BNv  (Bv*Nv)       // 16384 rows
#define Rv   (BNv*Hv)      // 131072 (b,n,h) rows
#define M2v  (2*Mv)        // 256
#define K3   1536          // B split K' = 3*512
#define K2   1024          // A split storage: [hi|lo]

#define DN_CONST    0.35355339059327373f   // 64^-0.25
#define RATIO_CONST 0.08838834764831845f   // 1/sqrt(128)

// ---------------- scratch (device globals) ---------------------------------
__device__ float g_value[(size_t)BNv*Dv];
__device__ float g_pproj[(size_t)BNv*Dv];
__device__ float g_sproj[(size_t)BNv*Dv];
__device__ float g_norms[(size_t)Rv];
__device__ float g_kvs  [(size_t)Bv*Hv*M2v*DHv];     // [bh][m2][dh]
__device__ __nv_bfloat16 g_kvsT[(size_t)Bv*Hv*DHv*768]; // [bh][d][hi256|hi256|lo256]
__device__ __nv_bfloat16 g_WvT[(size_t)Dv*K3];
__device__ __nv_bfloat16 g_WpT[(size_t)Dv*K3];
__device__ __nv_bfloat16 g_WoT[(size_t)Dv*K3];
__device__ __nv_bfloat16 g_Asp0[(size_t)BNv*K2];
__device__ __nv_bfloat16 g_Asp1[(size_t)BNv*K2];
__device__ __nv_bfloat16 g_Asp2[(size_t)BNv*K2];
__device__ __nv_bfloat16 g_avsp[(size_t)BNv*K2];
__device__ __nv_bfloat16 g_qsp [(size_t)Rv*512];     // [r][q'hi 256 | q'lo 256]
__device__ float g_qp[(size_t)Rv*M2v];
__device__ float g_kp[(size_t)Rv*M2v];

// =================== HMMA helpers ==========================================
__device__ __forceinline__ void ldsm_x4(uint32_t& r0, uint32_t& r1,
                                        uint32_t& r2, uint32_t& r3, uint32_t addr) {
    asm volatile("ldmatrix.sync.aligned.m8n8.x4.shared.b16 {%0,%1,%2,%3}, [%4];"
                 : "=r"(r0), "=r"(r1), "=r"(r2), "=r"(r3) : "r"(addr));
}
__device__ __forceinline__ void mma16816(float* c, const uint32_t* a,
                                         uint32_t b0, uint32_t b1) {
    asm volatile("mma.sync.aligned.m16n8k16.row.col.f32.bf16.bf16.f32 "
                 "{%0,%1,%2,%3}, {%4,%5,%6,%7}, {%8,%9}, {%0,%1,%2,%3};"
                 : "+f"(c[0]), "+f"(c[1]), "+f"(c[2]), "+f"(c[3])
                 : "r"(a[0]), "r"(a[1]), "r"(a[2]), "r"(a[3]), "r"(b0), "r"(b1));
}
__device__ __forceinline__ void cpa16(uint32_t dst, const void* src) {
    asm volatile("cp.async.cg.shared.global [%0], [%1], 16;"
                 :: "r"(dst), "l"(src));
}

// =================== W transpose + hi/lo split ==============================
__global__ __launch_bounds__(256)
void wsplit_kernel(const float* __restrict__ Wv, const float* __restrict__ Wp,
                   const float* __restrict__ Wo)
{
    const float* W; __nv_bfloat16* T;
    if (blockIdx.z == 0)      { W = Wv; T = g_WvT; }
    else if (blockIdx.z == 1) { W = Wp; T = g_WpT; }
    else                      { W = Wo; T = g_WoT; }
    int idx = blockIdx.x * 256 + threadIdx.x;
    int k = idx >> 9, n = idx & 511;
    float x = W[idx];
    __nv_bfloat16 hi = __float2bfloat16_rn(x);
    __nv_bfloat16 lo = __float2bfloat16_rn(x - __bfloat162float(hi));
    T[(size_t)n*K3 + k]        = hi;
    T[(size_t)n*K3 + 512 + k]  = hi;
    T[(size_t)n*K3 + 1024 + k] = lo;
}

__global__ __launch_bounds__(256)
void asplit_kernel(const float* __restrict__ A0, const float* __restrict__ A1,
                   const float* __restrict__ A2, int zbase)
{
    const int z = blockIdx.z + zbase;
    const float* A; __nv_bfloat16* T;
    if (z == 0)      { A = A0; T = g_Asp0; }
    else if (z == 1) { A = A1; T = g_Asp1; }
    else             { A = A2; T = g_Asp2; }
    size_t idx = (size_t)blockIdx.x * 256 + threadIdx.x;
    size_t m = idx >> 9; int k = (int)(idx & 511);
    float x = A[idx];
    __nv_bfloat16 hi = __float2bfloat16_rn(x);
    __nv_bfloat16 lo = __float2bfloat16_rn(x - __bfloat162float(hi));
    T[m*K2 + k]       = hi;
    T[m*K2 + 512 + k] = lo;
}

// =================== main HMMA GEMM (unchanged from R9 pass) ================
#define ASTR  40
#define STG_B 20480
#define NSTG  5
#define SMEM_GEMM (NSTG*STG_B)

__global__ __launch_bounds__(256, 2)
void hmma_gemm_kernel(const __nv_bfloat16* A0, const __nv_bfloat16* A1, const __nv_bfloat16* A2,
                      const __nv_bfloat16* B0, const __nv_bfloat16* B1, const __nv_bfloat16* B2,
                      float* C0, float* C1, float* C2, int zbase)
{
    const int z = blockIdx.z + zbase;
    const __nv_bfloat16* A; const __nv_bfloat16* Bt; float* C;
    if (z == 0)      { A = A0; Bt = B0; C = C0; }
    else if (z == 1) { A = A1; Bt = B1; C = C1; }
    else             { A = A2; Bt = B2; C = C2; }

    extern __shared__ __align__(16) char smem[];
    const uint32_t sbase = (uint32_t)__cvta_generic_to_shared(smem);
    const int tid = threadIdx.x;
    const int lane = tid & 31, wid = tid >> 5;
    const int r0 = blockIdx.y * 128;
    const int n0 = blockIdx.x * 128;
    const int wm = wid >> 2, wn = wid & 3;
    const int lrow = tid >> 2;
    const int lchk = (tid & 3) * 8;

    float acc[4][4][4];
#pragma unroll
    for (int mi = 0; mi < 4; mi++)
#pragma unroll
        for (int ni = 0; ni < 4; ni++)
#pragma unroll
            for (int q = 0; q < 4; q++) acc[mi][ni][q] = 0.0f;

    const __nv_bfloat16* gA = A  + (size_t)(r0 + lrow) * K2 + lchk;
    const __nv_bfloat16* gB = Bt + (size_t)(n0 + lrow) * K3 + lchk;
    const uint32_t sAoff = (uint32_t)((lrow * ASTR + lchk) * 2);

    #define LOAD_STAGE(c) do {                                                  \
        const int ca_ = ((c) < 32) ? (c) : ((c) - 32);                          \
        uint32_t sb_ = sbase + ((c) % NSTG) * STG_B;                            \
        cpa16(sb_ + sAoff,                         gA + ca_ * 32);              \
        cpa16(sb_ + sAoff + 64 * ASTR * 2,         gA + (size_t)64 * K2 + ca_ * 32); \
        cpa16(sb_ + 10240 + sAoff,                 gB + (c) * 32);              \
        cpa16(sb_ + 10240 + sAoff + 64 * ASTR * 2, gB + (size_t)64 * K3 + (c) * 32); \
        asm volatile("cp.async.commit_group;" ::: "memory");                    \
    } while (0)

    #define COMPUTE_STAGE(c) do {                                               \
        const uint32_t stA_ = sbase + ((c) % NSTG) * STG_B;                     \
        const uint32_t stB_ = stA_ + 10240;                                     \
        _Pragma("unroll")                                                       \
        for (int ks = 0; ks < 2; ks++) {                                        \
            const int ko = ks * 16;                                             \
            uint32_t a[4][4], b[2][4];                                          \
            _Pragma("unroll")                                                   \
            for (int mi = 0; mi < 4; mi++)                                      \
                ldsm_x4(a[mi][0], a[mi][1], a[mi][2], a[mi][3],                 \
                        stA_ + ((wm * 64 + mi * 16 + (lane & 15)) * ASTR        \
                               + ko + (lane >> 4) * 8) * 2);                    \
            _Pragma("unroll")                                                   \
            for (int pr = 0; pr < 2; pr++)                                      \
                ldsm_x4(b[pr][0], b[pr][1], b[pr][2], b[pr][3],                 \
                        stB_ + ((wn * 32 + pr * 16 + ((lane >> 4) << 3) + (lane & 7)) * ASTR \
                               + ko + ((lane >> 3) & 1) * 8) * 2);              \
            _Pragma("unroll")                                                   \
            for (int mi = 0; mi < 4; mi++) {                                    \
                mma16816(acc[mi][0], a[mi], b[0][0], b[0][1]);                  \
                mma16816(acc[mi][1], a[mi], b[0][2], b[0][3]);                  \
                mma16816(acc[mi][2], a[mi], b[1][0], b[1][1]);                  \
                mma16816(acc[mi][3], a[mi], b[1][2], b[1][3]);                  \
            }                                                                   \
        }                                                                       \
    } while (0)

#pragma unroll
    for (int p = 0; p < 3; p++) LOAD_STAGE(p);

    for (int kt = 0; kt < 48; kt += 2) {
        if (kt + 2 >= 48) {
            asm volatile("cp.async.wait_group 0;" ::: "memory");
        } else {
            asm volatile("cp.async.wait_group 1;" ::: "memory");
        }
        __syncthreads();
        if (kt + 3 < 48) LOAD_STAGE(kt + 3);
        if (kt + 4 < 48) LOAD_STAGE(kt + 4);
        COMPUTE_STAGE(kt);
        COMPUTE_STAGE(kt + 1);
    }

#pragma unroll
    for (int mi = 0; mi < 4; mi++)
#pragma unroll
        for (int ni = 0; ni < 4; ni++) {
            const int row = r0 + wm * 64 + mi * 16 + (lane >> 2);
            const int col = n0 + wn * 32 + ni * 8 + (lane & 3) * 2;
            float2 v0 = make_float2(acc[mi][ni][0], acc[mi][ni][1]);
            float2 v1 = make_float2(acc[mi][ni][2], acc[mi][ni][3]);
            *(float2*)(C + (size_t)row * 512 + col)       = v0;
            *(float2*)(C + (size_t)(row + 8) * 512 + col) = v1;
        }
    #undef LOAD_STAGE
    #undef COMPUTE_STAGE
}

// ---------------- norms (+ zero g_kvs) -------------------------------------
__global__ __launch_bounds__(256)
void norms_kernel()
{
    const int t = blockIdx.x * 256 + threadIdx.x;
    ((float4*)g_kvs)[t] = make_float4(0.f, 0.f, 0.f, 0.f);
    const float4* sp = (const float4*)(g_sproj + (size_t)t * 64);
    float acc = 0.0f;
#pragma unroll
    for (int i = 0; i < 16; i++) {
        float4 v = sp[i];
        acc = fmaf(v.x, v.x, acc);
        acc = fmaf(v.y, v.y, acc);
        acc = fmaf(v.z, v.z, acc);
        acc = fmaf(v.w, v.w, acc);
    }
    g_norms[t] = sqrtf(acc) * (1.0f / (float)Nv);
}

// ---------------- fused fourier: q' + k' + q'-split ------------------------
__global__ __launch_bounds__(256, 3)
void fourier_qk_kernel(const float* __restrict__ proj,
                       const float* __restrict__ scale,
                       const float* __restrict__ offs,
                       float* __restrict__ outq,
                       float* __restrict__ outk)
{
    __shared__ float Ap [8][64];
    __shared__ float Asl[8][64];
    __shared__ float Ps [8][64];
    const int tid = threadIdx.x;
    const int tx = tid & 15;
    const int ty = tid >> 4;
    const int r0 = blockIdx.y * 64;
    const int m0 = blockIdx.x * 64;

    const int arow  = tid >> 2;
    const int aslot = tid & 3;
    const int akp   = (aslot & 1) * 4;
    const bool is_s = (aslot >= 2);
    const int ah    = arow & 7;
    const float sc  = scale[ah] * DN_CONST;
    const float ascale = is_s ? (sc * offs[ah]) : sc;
    const float* asrc = (is_s ? g_sproj : g_pproj) + (size_t)(r0 + arow) * 64 + akp;

    const int mrow = tid >> 1;
    const int mkp  = (tid & 1) * 4;

    float acc_p[4][4], acc_s[4][4];
#pragma unroll
    for (int i = 0; i < 4; i++)
#pragma unroll
        for (int j = 0; j < 4; j++) { acc_p[i][j] = 0.0f; acc_s[i][j] = 0.0f; }

    for (int kk = 0; kk < 64; kk += 8) {
        float4 a4 = *(const float4*)(asrc + kk);
        float4 p4 = make_float4(0.f, 0.f, 0.f, 0.f);
        if (tid < 128)
            p4 = *(const float4*)(proj + (size_t)(m0 + mrow) * 64 + kk + mkp);
        __syncthreads();
        float* adst = (is_s ? &Asl[0][0] : &Ap[0][0]);
        adst[(akp + 0) * 64 + arow] = ascale * a4.x;
        adst[(akp + 1) * 64 + arow] = ascale * a4.y;
        adst[(akp + 2) * 64 + arow] = ascale * a4.z;
        adst[(akp + 3) * 64 + arow] = ascale * a4.w;
        if (tid < 128) {
            Ps[mkp + 0][mrow] = p4.x;
            Ps[mkp + 1][mrow] = p4.y;
            Ps[mkp + 2][mrow] = p4.z;
            Ps[mkp + 3][mrow] = p4.w;
        }
        __syncthreads();
#pragma unroll
        for (int k = 0; k < 8; k++) {
            float ap[4], as[4], b[4];
            *(float4*)(ap) = *(const float4*)&Ap [k][ty * 4];
            *(float4*)(as) = *(const float4*)&Asl[k][ty * 4];
            *(float4*)(b)  = *(const float4*)&Ps [k][tx * 4];
#pragma unroll
            for (int i = 0; i < 4; i++)
#pragma unroll
                for (int j = 0; j < 4; j++) {
                    acc_p[i][j] = fmaf(ap[i], b[j], acc_p[i][j]);
                    acc_s[i][j] = fmaf(as[i], b[j], acc_s[i][j]);
                }
        }
    }

#pragma unroll
    for (int i = 0; i < 4; i++) {
        const int rr = r0 + ty * 4 + i;
        float* qrow = outq + (size_t)rr * 256 + m0 + tx * 4;
        float* krow = outk + (size_t)rr * 256 + m0 + tx * 4;
        __nv_bfloat16* qsp = g_qsp + (size_t)rr * 512 + m0 + tx * 4;
        float qs[4], qc[4], ks[4], kc[4];
        __nv_bfloat16 h4[4], l4[4];
#pragma unroll
        for (int j = 0; j < 4; j++) {
            float dq = acc_p[i][j];
            float dk = dq + acc_s[i][j];
            __sincosf(dq, &qs[j], &qc[j]);
            __sincosf(dk, &ks[j], &kc[j]);
            qs[j] *= RATIO_CONST; qc[j] *= RATIO_CONST;
            ks[j] *= RATIO_CONST; kc[j] *= RATIO_CONST;
        }
        *(float4*)(qrow)       = *(float4*)qs;
        *(float4*)(qrow + 128) = *(float4*)qc;
        *(float4*)(krow)       = *(float4*)ks;
        *(float4*)(krow + 128) = *(float4*)kc;
        // q' bf16 hi/lo split for av-HMMA: [hi sin|hi cos | lo sin|lo cos]
#pragma unroll
        for (int j = 0; j < 4; j++) {
            h4[j] = __float2bfloat16_rn(qs[j]);
            l4[j] = __float2bfloat16_rn(qs[j] - __bfloat162float(h4[j]));
        }
        *(uint2*)(qsp)       = *(uint2*)h4;
        *(uint2*)(qsp + 256) = *(uint2*)l4;
#pragma unroll
        for (int j = 0; j < 4; j++) {
            h4[j] = __float2bfloat16_rn(qc[j]);
            l4[j] = __float2bfloat16_rn(qc[j] - __bfloat162float(h4[j]));
        }
        *(uint2*)(qsp + 128) = *(uint2*)h4;
        *(uint2*)(qsp + 384) = *(uint2*)l4;
    }
}

// ---------------- kvs: per (b,h) [256 x 4096] x [4096 x 64] ----------------
__global__ __launch_bounds__(256)
void kvs_kernel(const float* __restrict__ kprime)
{
    __shared__ float Ks[8][256];
    __shared__ float Vs[8][64];
    const int tid = threadIdx.x;
    const int bh = blockIdx.y;
    const int b = bh >> 3, h = bh & 7;
    const int n0 = blockIdx.x * 256;
    const int tx = tid & 7;
    const int ty = tid >> 3;
    const int kni = tid >> 6;
    const int km4 = (tid & 63) * 4;
    const int vni = tid >> 4;
    const int vd4 = (tid & 15) * 4;

    float acc[8][8];
#pragma unroll
    for (int i = 0; i < 8; i++)
#pragma unroll
        for (int j = 0; j < 8; j++) acc[i][j] = 0.0f;

    for (int nn = 0; nn < 256; nn += 8) {
        const size_t nbase = (size_t)(b * Nv + n0 + nn);
        float4 k0 = *(const float4*)(kprime + ((nbase + kni)     * 8 + h) * 256 + km4);
        float4 k1 = *(const float4*)(kprime + ((nbase + kni + 4) * 8 + h) * 256 + km4);
        float4 v0 = make_float4(0.f, 0.f, 0.f, 0.f);
        if (tid < 128)
            v0 = *(const float4*)(g_value + (nbase + vni) * 512 + h * 64 + vd4);
        __syncthreads();
        *(float4*)&Ks[kni][km4]     = k0;
        *(float4*)&Ks[kni + 4][km4] = k1;
        if (tid < 128) *(float4*)&Vs[vni][vd4] = v0;
        __syncthreads();
#pragma unroll
        for (int ni = 0; ni < 8; ni++) {
            float a[8], v[8];
            *(float4*)(a)     = *(const float4*)&Ks[ni][ty * 8];
            *(float4*)(a + 4) = *(const float4*)&Ks[ni][ty * 8 + 4];
            *(float4*)(v)     = *(const float4*)&Vs[ni][tx * 8];
            *(float4*)(v + 4) = *(const float4*)&Vs[ni][tx * 8 + 4];
#pragma unroll
            for (int i = 0; i < 8; i++)
#pragma unroll
                for (int j = 0; j < 8; j++)
                    acc[i][j] = fmaf(a[i], v[j], acc[i][j]);
        }
    }
    float* dst = g_kvs + ((size_t)bh * 256 + ty * 8) * 64 + tx * 8;
#pragma unroll
    for (int i = 0; i < 8; i++)
#pragma unroll
        for (int j = 0; j < 8; j++)
            atomicAdd(dst + (size_t)i * 64 + j, acc[i][j]);
}

// ---------------- kvs transpose + hi/lo split for av-HMMA ------------------
// g_kvs [bh][k=256][d=64] fp32 -> g_kvsT [bh][d][ hi(k) | hi(k) | lo(k) ] bf16
__global__ __launch_bounds__(256)
void kvsT_kernel()
{
    int idx = blockIdx.x * 256 + threadIdx.x;   // 0..524287
    int bh = idx >> 14;
    int d  = (idx >> 8) & 63;
    int k  = idx & 255;
    float v = g_kvs[(size_t)bh * 16384 + k * 64 + d];
    __nv_bfloat16 hi = __float2bfloat16_rn(v);
    __nv_bfloat16 lo = __float2bfloat16_rn(v - __bfloat162float(hi));
    __nv_bfloat16* o = g_kvsT + (size_t)bh * 49152 + d * 768;
    o[k]       = hi;
    o[256 + k] = hi;
    o[512 + k] = lo;
}

// ---------------- av via HMMA: per bh [4096 x 768] x [768 x 64] ------------
// A = g_qsp (rows r=bn*8+h, [hi|lo], chunk remap c>=16 -> c-16)
// B = g_kvsT. Tile 128x64, 8 warps (4x2, warp 32x32), BK=32, 5-stage ring.
#define AV_STG 15360    // A 10240 + B 5120
#define SMEM_AV (NSTG*AV_STG)

__global__ __launch_bounds__(256, 2)
void av_hmma_kernel()
{
    extern __shared__ __align__(16) char smem[];
    const uint32_t sbase = (uint32_t)__cvta_generic_to_shared(smem);
    const int tid = threadIdx.x;
    const int lane = tid & 31, wid = tid >> 5;
    const int bh = blockIdx.y;
    const int b = bh >> 3, h = bh & 7;
    const int n0 = blockIdx.x * 128;
    const int wm = wid >> 1, wn = wid & 1;     // 4 x 2 warps, warp tile 32x32

    const int lrow = tid >> 2;                 // 0..63
    const int lchk = (tid & 3) * 8;

    float acc[2][4][4];
#pragma unroll
    for (int mi = 0; mi < 2; mi++)
#pragma unroll
        for (int ni = 0; ni < 4; ni++)
#pragma unroll
            for (int q = 0; q < 4; q++) acc[mi][ni][q] = 0.0f;

    const __nv_bfloat16* gA = g_qsp
        + ((size_t)(b * Nv + n0 + lrow) * 8 + h) * 512 + lchk;
    const __nv_bfloat16* gB = g_kvsT + (size_t)bh * 49152 + lrow * 768 + lchk;
    const uint32_t sAoff = (uint32_t)((lrow * ASTR + lchk) * 2);
    const size_t arowstep = (size_t)64 * 8 * 512;   // +64 rows in A

    #define AV_LOAD(c) do {                                                     \
        const int ca_ = ((c) < 16) ? (c) : ((c) - 16);                          \
        uint32_t sb_ = sbase + ((c) % NSTG) * AV_STG;                           \
        cpa16(sb_ + sAoff,                 gA + ca_ * 32);                      \
        cpa16(sb_ + sAoff + 64 * ASTR * 2, gA + arowstep + ca_ * 32);           \
        cpa16(sb_ + 10240 + sAoff,         gB + (c) * 32);                      \
        asm volatile("cp.async.commit_group;" ::: "memory");                    \
    } while (0)

    #define AV_COMPUTE(c) do {                                                  \
        const uint32_t stA_ = sbase + ((c) % NSTG) * AV_STG;                    \
        const uint32_t stB_ = stA_ + 10240;                                     \
        _Pragma("unroll")                                                       \
        for (int ks = 0; ks < 2; ks++) {                                        \
            const int ko = ks * 16;                                             \
            uint32_t a[2][4], bb[2][4];                                         \
            _Pragma("unroll")                                                   \
            for (int mi = 0; mi < 2; mi++)                                      \
                ldsm_x4(a[mi][0], a[mi][1], a[mi][2], a[mi][3],                 \
                        stA_ + ((wm * 32 + mi * 16 + (lane & 15)) * ASTR        \
                               + ko + (lane >> 4) * 8) * 2);                    \
            _Pragma("unroll")                                                   \
            for (int pr = 0; pr < 2; pr++)                                      \
                ldsm_x4(bb[pr][0], bb[pr][1], bb[pr][2], bb[pr][3],             \
                        stB_ + ((wn * 32 + pr * 16 + ((lane >> 4) << 3) + (lane & 7)) * ASTR \
                               + ko + ((lane >> 3) & 1) * 8) * 2);              \
            _Pragma("unroll")                                                   \
            for (int mi = 0; mi < 2; mi++) {                                    \
                mma16816(acc[mi][0], a[mi], bb[0][0], bb[0][1]);                \
                mma16816(acc[mi][1], a[mi], bb[0][2], bb[0][3]);                \
                mma16816(acc[mi][2], a[mi], bb[1][0], bb[1][1]);                \
                mma16816(acc[mi][3], a[mi], bb[1][2], bb[1][3]);                \
            }                                                                   \
        }                                                                       \
    } while (0)

#pragma unroll
    for (int p = 0; p < 3; p++) AV_LOAD(p);

    for (int kt = 0; kt < 24; kt += 2) {
        if (kt + 2 >= 24) {
            asm volatile("cp.async.wait_group 0;" ::: "memory");
        } else {
            asm volatile("cp.async.wait_group 1;" ::: "memory");
        }
        __syncthreads();
        if (kt + 3 < 24) AV_LOAD(kt + 3);
        if (kt + 4 < 24) AV_LOAD(kt + 4);
        AV_COMPUTE(kt);
        AV_COMPUTE(kt + 1);
    }

    // epilogue: norms multiply + avsp hi/lo pack
#pragma unroll
    for (int mi = 0; mi < 2; mi++)
#pragma unroll
        for (int ni = 0; ni < 4; ni++) {
            const int nrow = n0 + wm * 32 + mi * 16 + (lane >> 2);
            const int d    = wn * 32 + ni * 8 + (lane & 3) * 2;
#pragma unroll
            for (int half = 0; half < 2; half++) {
                const int nr = nrow + half * 8;
                const size_t m = (size_t)(b * Nv + nr);
                const float nm = g_norms[m * 8 + h];
                float v0 = acc[mi][ni][half * 2 + 0] * nm;
                float v1 = acc[mi][ni][half * 2 + 1] * nm;
                __nv_bfloat16 h2[2], l2[2];
                h2[0] = __float2bfloat16_rn(v0);
                l2[0] = __float2bfloat16_rn(v0 - __bfloat162float(h2[0]));
                h2[1] = __float2bfloat16_rn(v1);
                l2[1] = __float2bfloat16_rn(v1 - __bfloat162float(h2[1]));
                *(uint32_t*)(g_avsp + m * K2 + h * 64 + d)       = *(uint32_t*)h2;
                *(uint32_t*)(g_avsp + m * K2 + 512 + h * 64 + d) = *(uint32_t*)l2;
            }
        }
    #undef AV_LOAD
    #undef AV_COMPUTE
}

// ---------------------------------------------------------------------------
extern "C" void kernel_launch(void* const* d_in, const int* in_sizes, int n_in,
                              void* d_out, int out_size)
{
    const float* src    = (const float*)d_in[0];
    const float* pos    = (const float*)d_in[1];
    const float* slopes = (const float*)d_in[2];
    const float* Wv     = (const float*)d_in[3];
    const float* Wp     = (const float*)d_in[4];
    const float* scale  = (const float*)d_in[5];
    const float* offs   = (const float*)d_in[6];
    const float* Wout   = (const float*)d_in[7];
    const float* proj   = (const float*)d_in[8];

    float* out = (float*)d_out;

    void* p;
    float *pvalue, *ppproj, *psproj;
    __nv_bfloat16 *pWvT, *pWpT, *pWoT, *pA0, *pA1, *pA2, *pAv;
    cudaGetSymbolAddress(&p, g_value); pvalue = (float*)p;
    cudaGetSymbolAddress(&p, g_pproj); ppproj = (float*)p;
    cudaGetSymbolAddress(&p, g_sproj); psproj = (float*)p;
    cudaGetSymbolAddress(&p, g_WvT);   pWvT   = (__nv_bfloat16*)p;
    cudaGetSymbolAddress(&p, g_WpT);   pWpT   = (__nv_bfloat16*)p;
    cudaGetSymbolAddress(&p, g_WoT);   pWoT   = (__nv_bfloat16*)p;
    cudaGetSymbolAddress(&p, g_Asp0);  pA0    = (__nv_bfloat16*)p;
    cudaGetSymbolAddress(&p, g_Asp1);  pA1    = (__nv_bfloat16*)p;
    cudaGetSymbolAddress(&p, g_Asp2);  pA2    = (__nv_bfloat16*)p;
    cudaGetSymbolAddress(&p, g_avsp);  pAv    = (__nv_bfloat16*)p;

    const size_t OUT0 = (size_t)BNv * Dv;
    const size_t QPN  = (size_t)Rv * M2v;
    float* qdst;
    float* kdst;
    if ((size_t)out_size >= OUT0 + 2 * QPN) {
        qdst = out + OUT0;
        kdst = out + OUT0 + QPN;
    } else {
        cudaGetSymbolAddress(&p, g_qp); qdst = (float*)p;
        cudaGetSymbolAddress(&p, g_kp); kdst = (float*)p;
    }

    static cudaStream_t s1;
    static cudaEvent_t e_ws, e_s, e_qk, e_kvs;
    static int init_done = 0;
    if (!init_done) {
        cudaFuncSetAttribute(hmma_gemm_kernel,
                             cudaFuncAttributeMaxDynamicSharedMemorySize, SMEM_GEMM);
        cudaFuncSetAttribute(av_hmma_kernel,
                             cudaFuncAttributeMaxDynamicSharedMemorySize, SMEM_AV);
        cudaStreamCreateWithFlags(&s1, cudaStreamNonBlocking);
        cudaEventCreateWithFlags(&e_ws,  cudaEventDisableTiming);
        cudaEventCreateWithFlags(&e_s,   cudaEventDisableTiming);
        cudaEventCreateWithFlags(&e_qk,  cudaEventDisableTiming);
        cudaEventCreateWithFlags(&e_kvs, cudaEventDisableTiming);
        init_done = 1;
    }

    // submission order tuned: big GEMM is harness launch #5 for ncu
    wsplit_kernel<<<dim3(1024, 1, 3), 256>>>(Wv, Wp, Wout);              // #2
    cudaEventRecord(e_ws, 0);
    cudaStreamWaitEvent(s1, e_ws, 0);
    asplit_kernel<<<dim3(32768, 1, 2), 256>>>(src, pos, slopes, 1);      // #3 pos,slopes
    asplit_kernel<<<dim3(32768, 1, 1), 256, 0, s1>>>(src, pos, slopes, 0); // #4 src
    hmma_gemm_kernel<<<dim3(4, 128, 2), 256, SMEM_GEMM>>>(               // #5 pproj,sproj
        pA0, pA1, pA2, pWvT, pWpT, pWpT, pvalue, ppproj, psproj, 1);
    cudaEventRecord(e_s, 0);
    fourier_qk_kernel<<<dim3(2, Rv / 64), 256>>>(proj, scale, offs, qdst, kdst);
    cudaEventRecord(e_qk, 0);

    // stream 1: value + norms + kvs + kvsT
    hmma_gemm_kernel<<<dim3(4, 128, 1), 256, SMEM_GEMM, s1>>>(
        pA0, pA1, pA2, pWvT, pWpT, pWpT, pvalue, ppproj, psproj, 0);     // value
    cudaStreamWaitEvent(s1, e_s, 0);
    norms_kernel<<<Rv / 256, 256, 0, s1>>>();
    cudaStreamWaitEvent(s1, e_qk, 0);
    kvs_kernel<<<dim3(16, Bv * Hv), 256, 0, s1>>>(kdst);
    kvsT_kernel<<<2048, 256, 0, s1>>>();
    cudaEventRecord(e_kvs, s1);

    // join on stream 0
    cudaStreamWaitEvent(0, e_kvs, 0);
    av_hmma_kernel<<<dim3(Nv / 128, Bv * Hv), 256, SMEM_AV>>>();
    hmma_gemm_kernel<<<dim3(4, 128, 1), 256, SMEM_GEMM>>>(
        pAv, pAv, pAv, pWoT, pWoT, pWoT, out, out, out, 0);
}

// round 11
// speedup vs baseline: 1.6475x; 1.0014x over previous
#include <cuda_runtime.h>
#include <cuda_bf16.h>
#include <math.h>
#include <stdint.h>

#define Bv   4
#define Nv   4096
#define Dv   512
#define Hv   8
#define DHv  64
#define Mv   128
#define BNv  (Bv*Nv)       // 16384 rows
#define Rv   (BNv*Hv)      // 131072 (b,n,h) rows
#define M2v  (2*Mv)        // 256
#define K3   1536          // B split K' = 3*512
#define K2   1024          // A split storage: [hi|lo]

#define DN_CONST    0.35355339059327373f   // 64^-0.25
#define RATIO_CONST 0.08838834764831845f   // 1/sqrt(128)

// ---------------- scratch (device globals) ---------------------------------
__device__ float g_value[(size_t)BNv*Dv];
__device__ float g_pproj[(size_t)BNv*Dv];
__device__ float g_sproj[(size_t)BNv*Dv];
__device__ float g_norms[(size_t)Rv];
__device__ float g_kvs  [(size_t)Bv*Hv*M2v*DHv];        // [bh][m2][dh]
__device__ __nv_bfloat16 g_kvsT[(size_t)Bv*Hv*DHv*768]; // [bh][d][hi|hi|lo]
__device__ __nv_bfloat16 g_WvT[(size_t)Dv*K3];
__device__ __nv_bfloat16 g_WpT[(size_t)Dv*K3];
__device__ __nv_bfloat16 g_WoT[(size_t)Dv*K3];
__device__ __nv_bfloat16 g_Asp0[(size_t)BNv*K2];
__device__ __nv_bfloat16 g_Asp1[(size_t)BNv*K2];
__device__ __nv_bfloat16 g_Asp2[(size_t)BNv*K2];
__device__ __nv_bfloat16 g_avsp[(size_t)BNv*K2];
__device__ __nv_bfloat16 g_qsp [(size_t)Rv*512];     // [r][hi sin|hi cos|lo sin|lo cos]
// fourier-HMMA operands
__device__ __nv_bfloat16 g_Aq[(size_t)Rv*128];       // [r][hi64|lo64]
__device__ __nv_bfloat16 g_Ak[(size_t)Rv*128];
__device__ __nv_bfloat16 g_projsp[128*192];          // [m][hi64|hi64|lo64]
// fallback q'/k' if d_out only holds first tuple element
__device__ float g_qp[(size_t)Rv*M2v];
__device__ float g_kp[(size_t)Rv*M2v];

// =================== HMMA helpers ==========================================
__device__ __forceinline__ void ldsm_x4(uint32_t& r0, uint32_t& r1,
                                        uint32_t& r2, uint32_t& r3, uint32_t addr) {
    asm volatile("ldmatrix.sync.aligned.m8n8.x4.shared.b16 {%0,%1,%2,%3}, [%4];"
                 : "=r"(r0), "=r"(r1), "=r"(r2), "=r"(r3) : "r"(addr));
}
__device__ __forceinline__ void mma16816(float* c, const uint32_t* a,
                                         uint32_t b0, uint32_t b1) {
    asm volatile("mma.sync.aligned.m16n8k16.row.col.f32.bf16.bf16.f32 "
                 "{%0,%1,%2,%3}, {%4,%5,%6,%7}, {%8,%9}, {%0,%1,%2,%3};"
                 : "+f"(c[0]), "+f"(c[1]), "+f"(c[2]), "+f"(c[3])
                 : "r"(a[0]), "r"(a[1]), "r"(a[2]), "r"(a[3]), "r"(b0), "r"(b1));
}
__device__ __forceinline__ void cpa16(uint32_t dst, const void* src) {
    asm volatile("cp.async.cg.shared.global [%0], [%1], 16;"
                 :: "r"(dst), "l"(src));
}

// =================== W transpose + hi/lo split ==============================
__global__ __launch_bounds__(256)
void wsplit_kernel(const float* __restrict__ Wv, const float* __restrict__ Wp,
                   const float* __restrict__ Wo)
{
    const float* W; __nv_bfloat16* T;
    if (blockIdx.z == 0)      { W = Wv; T = g_WvT; }
    else if (blockIdx.z == 1) { W = Wp; T = g_WpT; }
    else                      { W = Wo; T = g_WoT; }
    int idx = blockIdx.x * 256 + threadIdx.x;
    int k = idx >> 9, n = idx & 511;
    float x = W[idx];
    __nv_bfloat16 hi = __float2bfloat16_rn(x);
    __nv_bfloat16 lo = __float2bfloat16_rn(x - __bfloat162float(hi));
    T[(size_t)n*K3 + k]        = hi;
    T[(size_t)n*K3 + 512 + k]  = hi;
    T[(size_t)n*K3 + 1024 + k] = lo;
}

__global__ __launch_bounds__(256)
void asplit_kernel(const float* __restrict__ A0, const float* __restrict__ A1,
                   const float* __restrict__ A2, int zbase)
{
    const int z = blockIdx.z + zbase;
    const float* A; __nv_bfloat16* T;
    if (z == 0)      { A = A0; T = g_Asp0; }
    else if (z == 1) { A = A1; T = g_Asp1; }
    else             { A = A2; T = g_Asp2; }
    size_t idx = (size_t)blockIdx.x * 256 + threadIdx.x;
    size_t m = idx >> 9; int k = (int)(idx & 511);
    float x = A[idx];
    __nv_bfloat16 hi = __float2bfloat16_rn(x);
    __nv_bfloat16 lo = __float2bfloat16_rn(x - __bfloat162float(hi));
    T[m*K2 + k]       = hi;
    T[m*K2 + 512 + k] = lo;
}

// =================== main HMMA GEMM =========================================
#define ASTR  40
#define STG_B 20480
#define NSTG  5
#define SMEM_GEMM (NSTG*STG_B)

__global__ __launch_bounds__(256, 2)
void hmma_gemm_kernel(const __nv_bfloat16* A0, const __nv_bfloat16* A1, const __nv_bfloat16* A2,
                      const __nv_bfloat16* B0, const __nv_bfloat16* B1, const __nv_bfloat16* B2,
                      float* C0, float* C1, float* C2, int zbase)
{
    const int z = blockIdx.z + zbase;
    const __nv_bfloat16* A; const __nv_bfloat16* Bt; float* C;
    if (z == 0)      { A = A0; Bt = B0; C = C0; }
    else if (z == 1) { A = A1; Bt = B1; C = C1; }
    else             { A = A2; Bt = B2; C = C2; }

    extern __shared__ __align__(16) char smem[];
    const uint32_t sbase = (uint32_t)__cvta_generic_to_shared(smem);
    const int tid = threadIdx.x;
    const int lane = tid & 31, wid = tid >> 5;
    const int r0 = blockIdx.y * 128;
    const int n0 = blockIdx.x * 128;
    const int wm = wid >> 2, wn = wid & 3;
    const int lrow = tid >> 2;
    const int lchk = (tid & 3) * 8;

    float acc[4][4][4];
#pragma unroll
    for (int mi = 0; mi < 4; mi++)
#pragma unroll
        for (int ni = 0; ni < 4; ni++)
#pragma unroll
            for (int q = 0; q < 4; q++) acc[mi][ni][q] = 0.0f;

    const __nv_bfloat16* gA = A  + (size_t)(r0 + lrow) * K2 + lchk;
    const __nv_bfloat16* gB = Bt + (size_t)(n0 + lrow) * K3 + lchk;
    const uint32_t sAoff = (uint32_t)((lrow * ASTR + lchk) * 2);

    #define LOAD_STAGE(c) do {                                                  \
        const int ca_ = ((c) < 32) ? (c) : ((c) - 32);                          \
        uint32_t sb_ = sbase + ((c) % NSTG) * STG_B;                            \
        cpa16(sb_ + sAoff,                         gA + ca_ * 32);              \
        cpa16(sb_ + sAoff + 64 * ASTR * 2,         gA + (size_t)64 * K2 + ca_ * 32); \
        cpa16(sb_ + 10240 + sAoff,                 gB + (c) * 32);              \
        cpa16(sb_ + 10240 + sAoff + 64 * ASTR * 2, gB + (size_t)64 * K3 + (c) * 32); \
        asm volatile("cp.async.commit_group;" ::: "memory");                    \
    } while (0)

    #define COMPUTE_STAGE(c) do {                                               \
        const uint32_t stA_ = sbase + ((c) % NSTG) * STG_B;                     \
        const uint32_t stB_ = stA_ + 10240;                                     \
        _Pragma("unroll")                                                       \
        for (int ks = 0; ks < 2; ks++) {                                        \
            const int ko = ks * 16;                                             \
            uint32_t a[4][4], b[2][4];                                          \
            _Pragma("unroll")                                                   \
            for (int mi = 0; mi < 4; mi++)                                      \
                ldsm_x4(a[mi][0], a[mi][1], a[mi][2], a[mi][3],                 \
                        stA_ + ((wm * 64 + mi * 16 + (lane & 15)) * ASTR        \
                               + ko + (lane >> 4) * 8) * 2);                    \
            _Pragma("unroll")                                                   \
            for (int pr = 0; pr < 2; pr++)                                      \
                ldsm_x4(b[pr][0], b[pr][1], b[pr][2], b[pr][3],                 \
                        stB_ + ((wn * 32 + pr * 16 + ((lane >> 4) << 3) + (lane & 7)) * ASTR \
                               + ko + ((lane >> 3) & 1) * 8) * 2);              \
            _Pragma("unroll")                                                   \
            for (int mi = 0; mi < 4; mi++) {                                    \
                mma16816(acc[mi][0], a[mi], b[0][0], b[0][1]);                  \
                mma16816(acc[mi][1], a[mi], b[0][2], b[0][3]);                  \
                mma16816(acc[mi][2], a[mi], b[1][0], b[1][1]);                  \
                mma16816(acc[mi][3], a[mi], b[1][2], b[1][3]);                  \
            }                                                                   \
        }                                                                       \
    } while (0)

#pragma unroll
    for (int p = 0; p < 3; p++) LOAD_STAGE(p);

    for (int kt = 0; kt < 48; kt += 2) {
        if (kt + 2 >= 48) {
            asm volatile("cp.async.wait_group 0;" ::: "memory");
        } else {
            asm volatile("cp.async.wait_group 1;" ::: "memory");
        }
        __syncthreads();
        if (kt + 3 < 48) LOAD_STAGE(kt + 3);
        if (kt + 4 < 48) LOAD_STAGE(kt + 4);
        COMPUTE_STAGE(kt);
        COMPUTE_STAGE(kt + 1);
    }

#pragma unroll
    for (int mi = 0; mi < 4; mi++)
#pragma unroll
        for (int ni = 0; ni < 4; ni++) {
            const int row = r0 + wm * 64 + mi * 16 + (lane >> 2);
            const int col = n0 + wn * 32 + ni * 8 + (lane & 3) * 2;
            float2 v0 = make_float2(acc[mi][ni][0], acc[mi][ni][1]);
            float2 v1 = make_float2(acc[mi][ni][2], acc[mi][ni][3]);
            *(float2*)(C + (size_t)row * 512 + col)       = v0;
            *(float2*)(C + (size_t)(row + 8) * 512 + col) = v1;
        }
    #undef LOAD_STAGE
    #undef COMPUTE_STAGE
}

// ---------------- norms (+ zero g_kvs) -------------------------------------
__global__ __launch_bounds__(256)
void norms_kernel()
{
    const int t = blockIdx.x * 256 + threadIdx.x;
    ((float4*)g_kvs)[t] = make_float4(0.f, 0.f, 0.f, 0.f);
    const float4* sp = (const float4*)(g_sproj + (size_t)t * 64);
    float acc = 0.0f;
#pragma unroll
    for (int i = 0; i < 16; i++) {
        float4 v = sp[i];
        acc = fmaf(v.x, v.x, acc);
        acc = fmaf(v.y, v.y, acc);
        acc = fmaf(v.z, v.z, acc);
        acc = fmaf(v.w, v.w, acc);
    }
    g_norms[t] = sqrtf(acc) * (1.0f / (float)Nv);
}

// ---------------- fourier prep: Aq/Ak bf16 splits + proj split -------------
__global__ __launch_bounds__(256)
void qkprep_kernel(const float* __restrict__ scale, const float* __restrict__ offs)
{
    size_t idx = (size_t)blockIdx.x * 256 + threadIdx.x;   // Rv*64 = 8388608
    size_t r = idx >> 6; int k = (int)(idx & 63);
    int h = (int)(r & 7);
    float sc = scale[h] * DN_CONST;
    float of = offs[h];
    float pv = g_pproj[r * 64 + k];
    float sv = g_sproj[r * 64 + k];
    float aq = sc * pv;
    float ak = sc * fmaf(of, sv, pv);
    __nv_bfloat16 hq = __float2bfloat16_rn(aq);
    __nv_bfloat16 lq = __float2bfloat16_rn(aq - __bfloat162float(hq));
    __nv_bfloat16 hk = __float2bfloat16_rn(ak);
    __nv_bfloat16 lk = __float2bfloat16_rn(ak - __bfloat162float(hk));
    g_Aq[r * 128 + k]      = hq;
    g_Aq[r * 128 + 64 + k] = lq;
    g_Ak[r * 128 + k]      = hk;
    g_Ak[r * 128 + 64 + k] = lk;
}

__global__ __launch_bounds__(256)
void projsplit_kernel(const float* __restrict__ proj)
{
    int idx = blockIdx.x * 256 + threadIdx.x;   // 8192
    int m = idx >> 6, k = idx & 63;
    float x = proj[m * 64 + k];
    __nv_bfloat16 hi = __float2bfloat16_rn(x);
    __nv_bfloat16 lo = __float2bfloat16_rn(x - __bfloat162float(hi));
    g_projsp[m * 192 + k]       = hi;
    g_projsp[m * 192 + 64 + k]  = hi;
    g_projsp[m * 192 + 128 + k] = lo;
}

// ---------------- fourier via HMMA: [Rv x 192] x [192 x 128] + sincos ------
// z=0: A=g_Aq -> outq (+g_qsp) ; z=1: A=g_Ak -> outk.
// Tile 128x128, 6 BK=32 chunks, A chunk remap c>=4 -> c-4.
__global__ __launch_bounds__(256, 2)
void fourier_hmma_kernel(float* __restrict__ outq, float* __restrict__ outk)
{
    const int z = blockIdx.z;
    const __nv_bfloat16* A = z ? g_Ak : g_Aq;
    float* outp = z ? outk : outq;

    extern __shared__ __align__(16) char smem[];
    const uint32_t sbase = (uint32_t)__cvta_generic_to_shared(smem);
    const int tid = threadIdx.x;
    const int lane = tid & 31, wid = tid >> 5;
    const int r0 = blockIdx.y * 128;
    const int wm = wid >> 2, wn = wid & 3;
    const int lrow = tid >> 2;
    const int lchk = (tid & 3) * 8;

    float acc[4][4][4];
#pragma unroll
    for (int mi = 0; mi < 4; mi++)
#pragma unroll
        for (int ni = 0; ni < 4; ni++)
#pragma unroll
            for (int q = 0; q < 4; q++) acc[mi][ni][q] = 0.0f;

    const __nv_bfloat16* gA = A + (size_t)(r0 + lrow) * 128 + lchk;
    const __nv_bfloat16* gB = g_projsp + lrow * 192 + lchk;
    const uint32_t sAoff = (uint32_t)((lrow * ASTR + lchk) * 2);

    #define F_LOAD(c) do {                                                      \
        const int ca_ = ((c) < 4) ? (c) : ((c) - 4);                            \
        uint32_t sb_ = sbase + ((c) % NSTG) * STG_B;                            \
        cpa16(sb_ + sAoff,                         gA + ca_ * 32);              \
        cpa16(sb_ + sAoff + 64 * ASTR * 2,         gA + (size_t)64 * 128 + ca_ * 32); \
        cpa16(sb_ + 10240 + sAoff,                 gB + (c) * 32);              \
        cpa16(sb_ + 10240 + sAoff + 64 * ASTR * 2, gB + 64 * 192 + (c) * 32);   \
        asm volatile("cp.async.commit_group;" ::: "memory");                    \
    } while (0)

    #define F_COMPUTE(c) do {                                                   \
        const uint32_t stA_ = sbase + ((c) % NSTG) * STG_B;                     \
        const uint32_t stB_ = stA_ + 10240;                                     \
        _Pragma("unroll")                                                       \
        for (int ks = 0; ks < 2; ks++) {                                        \
            const int ko = ks * 16;                                             \
            uint32_t a[4][4], b[2][4];                                          \
            _Pragma("unroll")                                                   \
            for (int mi = 0; mi < 4; mi++)                                      \
                ldsm_x4(a[mi][0], a[mi][1], a[mi][2], a[mi][3],                 \
                        stA_ + ((wm * 64 + mi * 16 + (lane & 15)) * ASTR        \
                               + ko + (lane >> 4) * 8) * 2);                    \
            _Pragma("unroll")                                                   \
            for (int pr = 0; pr < 2; pr++)                                      \
                ldsm_x4(b[pr][0], b[pr][1], b[pr][2], b[pr][3],                 \
                        stB_ + ((wn * 32 + pr * 16 + ((lane >> 4) << 3) + (lane & 7)) * ASTR \
                               + ko + ((lane >> 3) & 1) * 8) * 2);              \
            _Pragma("unroll")                                                   \
            for (int mi = 0; mi < 4; mi++) {                                    \
                mma16816(acc[mi][0], a[mi], b[0][0], b[0][1]);                  \
                mma16816(acc[mi][1], a[mi], b[0][2], b[0][3]);                  \
                mma16816(acc[mi][2], a[mi], b[1][0], b[1][1]);                  \
                mma16816(acc[mi][3], a[mi], b[1][2], b[1][3]);                  \
            }                                                                   \
        }                                                                       \
    } while (0)

#pragma unroll
    for (int p = 0; p < 3; p++) F_LOAD(p);

    for (int kt = 0; kt < 6; kt += 2) {
        if (kt + 2 >= 6) {
            asm volatile("cp.async.wait_group 0;" ::: "memory");
        } else {
            asm volatile("cp.async.wait_group 1;" ::: "memory");
        }
        __syncthreads();
        if (kt + 3 < 6) F_LOAD(kt + 3);
        if (kt + 4 < 6) F_LOAD(kt + 4);
        F_COMPUTE(kt);
        F_COMPUTE(kt + 1);
    }

    // epilogue: sincos + writes
#pragma unroll
    for (int mi = 0; mi < 4; mi++)
#pragma unroll
        for (int ni = 0; ni < 4; ni++) {
            const int row = r0 + wm * 64 + mi * 16 + (lane >> 2);
            const int col = wn * 32 + ni * 8 + (lane & 3) * 2;
#pragma unroll
            for (int half = 0; half < 2; half++) {
                const int r = row + half * 8;
                float d0 = acc[mi][ni][half * 2 + 0];
                float d1 = acc[mi][ni][half * 2 + 1];
                float s0, c0, s1, c1;
                __sincosf(d0, &s0, &c0);
                __sincosf(d1, &s1, &c1);
                s0 *= RATIO_CONST; c0 *= RATIO_CONST;
                s1 *= RATIO_CONST; c1 *= RATIO_CONST;
                float* orow = outp + (size_t)r * 256;
                *(float2*)(orow + col)       = make_float2(s0, s1);
                *(float2*)(orow + 128 + col) = make_float2(c0, c1);
                if (z == 0) {
                    __nv_bfloat16 t2[2];
                    __nv_bfloat16* qsp = g_qsp + (size_t)r * 512;
                    t2[0] = __float2bfloat16_rn(s0);
                    t2[1] = __float2bfloat16_rn(s1);
                    *(uint32_t*)(qsp + col) = *(uint32_t*)t2;
                    __nv_bfloat16 ls0 = __float2bfloat16_rn(s0 - __bfloat162float(t2[0]));
                    __nv_bfloat16 ls1 = __float2bfloat16_rn(s1 - __bfloat162float(t2[1]));
                    t2[0] = ls0; t2[1] = ls1;
                    *(uint32_t*)(qsp + 256 + col) = *(uint32_t*)t2;
                    t2[0] = __float2bfloat16_rn(c0);
                    t2[1] = __float2bfloat16_rn(c1);
                    *(uint32_t*)(qsp + 128 + col) = *(uint32_t*)t2;
                    __nv_bfloat16 lc0 = __float2bfloat16_rn(c0 - __bfloat162float(t2[0]));
                    __nv_bfloat16 lc1 = __float2bfloat16_rn(c1 - __bfloat162float(t2[1]));
                    t2[0] = lc0; t2[1] = lc1;
                    *(uint32_t*)(qsp + 384 + col) = *(uint32_t*)t2;
                }
            }
        }
    #undef F_LOAD
    #undef F_COMPUTE
}

// ---------------- kvs: per (b,h) [256 x 4096] x [4096 x 64] ----------------
__global__ __launch_bounds__(256)
void kvs_kernel(const float* __restrict__ kprime)
{
    __shared__ float Ks[8][256];
    __shared__ float Vs[8][64];
    const int tid = threadIdx.x;
    const int bh = blockIdx.y;
    const int b = bh >> 3, h = bh & 7;
    const int n0 = blockIdx.x * 256;
    const int tx = tid & 7;
    const int ty = tid >> 3;
    const int kni = tid >> 6;
    const int km4 = (tid & 63) * 4;
    const int vni = tid >> 4;
    const int vd4 = (tid & 15) * 4;

    float acc[8][8];
#pragma unroll
    for (int i = 0; i < 8; i++)
#pragma unroll
        for (int j = 0; j < 8; j++) acc[i][j] = 0.0f;

    for (int nn = 0; nn < 256; nn += 8) {
        const size_t nbase = (size_t)(b * Nv + n0 + nn);
        float4 k0 = *(const float4*)(kprime + ((nbase + kni)     * 8 + h) * 256 + km4);
        float4 k1 = *(const float4*)(kprime + ((nbase + kni + 4) * 8 + h) * 256 + km4);
        float4 v0 = make_float4(0.f, 0.f, 0.f, 0.f);
        if (tid < 128)
            v0 = *(const float4*)(g_value + (nbase + vni) * 512 + h * 64 + vd4);
        __syncthreads();
        *(float4*)&Ks[kni][km4]     = k0;
        *(float4*)&Ks[kni + 4][km4] = k1;
        if (tid < 128) *(float4*)&Vs[vni][vd4] = v0;
        __syncthreads();
#pragma unroll
        for (int ni = 0; ni < 8; ni++) {
            float a[8], v[8];
            *(float4*)(a)     = *(const float4*)&Ks[ni][ty * 8];
            *(float4*)(a + 4) = *(const float4*)&Ks[ni][ty * 8 + 4];
            *(float4*)(v)     = *(const float4*)&Vs[ni][tx * 8];
            *(float4*)(v + 4) = *(const float4*)&Vs[ni][tx * 8 + 4];
#pragma unroll
            for (int i = 0; i < 8; i++)
#pragma unroll
                for (int j = 0; j < 8; j++)
                    acc[i][j] = fmaf(a[i], v[j], acc[i][j]);
        }
    }
    float* dst = g_kvs + ((size_t)bh * 256 + ty * 8) * 64 + tx * 8;
#pragma unroll
    for (int i = 0; i < 8; i++)
#pragma unroll
        for (int j = 0; j < 8; j++)
            atomicAdd(dst + (size_t)i * 64 + j, acc[i][j]);
}

// ---------------- kvs transpose + hi/lo split for av-HMMA ------------------
__global__ __launch_bounds__(256)
void kvsT_kernel()
{
    int idx = blockIdx.x * 256 + threadIdx.x;   // 0..524287
    int bh = idx >> 14;
    int d  = (idx >> 8) & 63;
    int k  = idx & 255;
    float v = g_kvs[(size_t)bh * 16384 + k * 64 + d];
    __nv_bfloat16 hi = __float2bfloat16_rn(v);
    __nv_bfloat16 lo = __float2bfloat16_rn(v - __bfloat162float(hi));
    __nv_bfloat16* o = g_kvsT + (size_t)bh * 49152 + d * 768;
    o[k]       = hi;
    o[256 + k] = hi;
    o[512 + k] = lo;
}

// ---------------- av via HMMA: per bh [4096 x 768] x [768 x 64] ------------
#define AV_STG 15360    // A 10240 + B 5120
#define SMEM_AV (NSTG*AV_STG)

__global__ __launch_bounds__(256, 2)
void av_hmma_kernel()
{
    extern __shared__ __align__(16) char smem[];
    const uint32_t sbase = (uint32_t)__cvta_generic_to_shared(smem);
    const int tid = threadIdx.x;
    const int lane = tid & 31, wid = tid >> 5;
    const int bh = blockIdx.y;
    const int b = bh >> 3, h = bh & 7;
    const int n0 = blockIdx.x * 128;
    const int wm = wid >> 1, wn = wid & 1;

    const int lrow = tid >> 2;
    const int lchk = (tid & 3) * 8;

    float acc[2][4][4];
#pragma unroll
    for (int mi = 0; mi < 2; mi++)
#pragma unroll
        for (int ni = 0; ni < 4; ni++)
#pragma unroll
            for (int q = 0; q < 4; q++) acc[mi][ni][q] = 0.0f;

    const __nv_bfloat16* gA = g_qsp
        + ((size_t)(b * Nv + n0 + lrow) * 8 + h) * 512 + lchk;
    const __nv_bfloat16* gB = g_kvsT + (size_t)bh * 49152 + lrow * 768 + lchk;
    const uint32_t sAoff = (uint32_t)((lrow * ASTR + lchk) * 2);
    const size_t arowstep = (size_t)64 * 8 * 512;

    #define AV_LOAD(c) do {                                                     \
        const int ca_ = ((c) < 16) ? (c) : ((c) - 16);                          \
        uint32_t sb_ = sbase + ((c) % NSTG) * AV_STG;                           \
        cpa16(sb_ + sAoff,                 gA + ca_ * 32);                      \
        cpa16(sb_ + sAoff + 64 * ASTR * 2, gA + arowstep + ca_ * 32);           \
        cpa16(sb_ + 10240 + sAoff,         gB + (c) * 32);                      \
        asm volatile("cp.async.commit_group;" ::: "memory");                    \
    } while (0)

    #define AV_COMPUTE(c) do {                                                  \
        const uint32_t stA_ = sbase + ((c) % NSTG) * AV_STG;                    \
        const uint32_t stB_ = stA_ + 10240;                                     \
        _Pragma("unroll")                                                       \
        for (int ks = 0; ks < 2; ks++) {                                        \
            const int ko = ks * 16;                                             \
            uint32_t a[2][4], bb[2][4];                                         \
            _Pragma("unroll")                                                   \
            for (int mi = 0; mi < 2; mi++)                                      \
                ldsm_x4(a[mi][0], a[mi][1], a[mi][2], a[mi][3],                 \
                        stA_ + ((wm * 32 + mi * 16 + (lane & 15)) * ASTR        \
                               + ko + (lane >> 4) * 8) * 2);                    \
            _Pragma("unroll")                                                   \
            for (int pr = 0; pr < 2; pr++)                                      \
                ldsm_x4(bb[pr][0], bb[pr][1], bb[pr][2], bb[pr][3],             \
                        stB_ + ((wn * 32 + pr * 16 + ((lane >> 4) << 3) + (lane & 7)) * ASTR \
                               + ko + ((lane >> 3) & 1) * 8) * 2);              \
            _Pragma("unroll")                                                   \
            for (int mi = 0; mi < 2; mi++) {                                    \
                mma16816(acc[mi][0], a[mi], bb[0][0], bb[0][1]);                \
                mma16816(acc[mi][1], a[mi], bb[0][2], bb[0][3]);                \
                mma16816(acc[mi][2], a[mi], bb[1][0], bb[1][1]);                \
                mma16816(acc[mi][3], a[mi], bb[1][2], bb[1][3]);                \
            }                                                                   \
        }                                                                       \
    } while (0)

#pragma unroll
    for (int p = 0; p < 3; p++) AV_LOAD(p);

    for (int kt = 0; kt < 24; kt += 2) {
        if (kt + 2 >= 24) {
            asm volatile("cp.async.wait_group 0;" ::: "memory");
        } else {
            asm volatile("cp.async.wait_group 1;" ::: "memory");
        }
        __syncthreads();
        if (kt + 3 < 24) AV_LOAD(kt + 3);
        if (kt + 4 < 24) AV_LOAD(kt + 4);
        AV_COMPUTE(kt);
        AV_COMPUTE(kt + 1);
    }

#pragma unroll
    for (int mi = 0; mi < 2; mi++)
#pragma unroll
        for (int ni = 0; ni < 4; ni++) {
            const int nrow = n0 + wm * 32 + mi * 16 + (lane >> 2);
            const int d    = wn * 32 + ni * 8 + (lane & 3) * 2;
#pragma unroll
            for (int half = 0; half < 2; half++) {
                const int nr = nrow + half * 8;
                const size_t m = (size_t)(b * Nv + nr);
                const float nm = g_norms[m * 8 + h];
                float v0 = acc[mi][ni][half * 2 + 0] * nm;
                float v1 = acc[mi][ni][half * 2 + 1] * nm;
                __nv_bfloat16 h2[2], l2[2];
                h2[0] = __float2bfloat16_rn(v0);
                l2[0] = __float2bfloat16_rn(v0 - __bfloat162float(h2[0]));
                h2[1] = __float2bfloat16_rn(v1);
                l2[1] = __float2bfloat16_rn(v1 - __bfloat162float(h2[1]));
                *(uint32_t*)(g_avsp + m * K2 + h * 64 + d)       = *(uint32_t*)h2;
                *(uint32_t*)(g_avsp + m * K2 + 512 + h * 64 + d) = *(uint32_t*)l2;
            }
        }
    #undef AV_LOAD
    #undef AV_COMPUTE
}

// ---------------------------------------------------------------------------
extern "C" void kernel_launch(void* const* d_in, const int* in_sizes, int n_in,
                              void* d_out, int out_size)
{
    const float* src    = (const float*)d_in[0];
    const float* pos    = (const float*)d_in[1];
    const float* slopes = (const float*)d_in[2];
    const float* Wv     = (const float*)d_in[3];
    const float* Wp     = (const float*)d_in[4];
    const float* scale  = (const float*)d_in[5];
    const float* offs   = (const float*)d_in[6];
    const float* Wout   = (const float*)d_in[7];
    const float* proj   = (const float*)d_in[8];

    float* out = (float*)d_out;

    void* p;
    float *pvalue, *ppproj, *psproj;
    __nv_bfloat16 *pWvT, *pWpT, *pWoT, *pA0, *pA1, *pA2, *pAv;
    cudaGetSymbolAddress(&p, g_value); pvalue = (float*)p;
    cudaGetSymbolAddress(&p, g_pproj); ppproj = (float*)p;
    cudaGetSymbolAddress(&p, g_sproj); psproj = (float*)p;
    cudaGetSymbolAddress(&p, g_WvT);   pWvT   = (__nv_bfloat16*)p;
    cudaGetSymbolAddress(&p, g_WpT);   pWpT   = (__nv_bfloat16*)p;
    cudaGetSymbolAddress(&p, g_WoT);   pWoT   = (__nv_bfloat16*)p;
    cudaGetSymbolAddress(&p, g_Asp0);  pA0    = (__nv_bfloat16*)p;
    cudaGetSymbolAddress(&p, g_Asp1);  pA1    = (__nv_bfloat16*)p;
    cudaGetSymbolAddress(&p, g_Asp2);  pA2    = (__nv_bfloat16*)p;
    cudaGetSymbolAddress(&p, g_avsp);  pAv    = (__nv_bfloat16*)p;

    const size_t OUT0 = (size_t)BNv * Dv;
    const size_t QPN  = (size_t)Rv * M2v;
    float* qdst;
    float* kdst;
    if ((size_t)out_size >= OUT0 + 2 * QPN) {
        qdst = out + OUT0;
        kdst = out + OUT0 + QPN;
    } else {
        cudaGetSymbolAddress(&p, g_qp); qdst = (float*)p;
        cudaGetSymbolAddress(&p, g_kp); kdst = (float*)p;
    }

    static cudaStream_t s1;
    static cudaEvent_t e_ws, e_s, e_qk, e_kvs;
    static int init_done = 0;
    if (!init_done) {
        cudaFuncSetAttribute(hmma_gemm_kernel,
                             cudaFuncAttributeMaxDynamicSharedMemorySize, SMEM_GEMM);
        cudaFuncSetAttribute(fourier_hmma_kernel,
                             cudaFuncAttributeMaxDynamicSharedMemorySize, SMEM_GEMM);
        cudaFuncSetAttribute(av_hmma_kernel,
                             cudaFuncAttributeMaxDynamicSharedMemorySize, SMEM_AV);
        cudaStreamCreateWithFlags(&s1, cudaStreamNonBlocking);
        cudaEventCreateWithFlags(&e_ws,  cudaEventDisableTiming);
        cudaEventCreateWithFlags(&e_s,   cudaEventDisableTiming);
        cudaEventCreateWithFlags(&e_qk,  cudaEventDisableTiming);
        cudaEventCreateWithFlags(&e_kvs, cudaEventDisableTiming);
        init_done = 1;
    }

    // ---- stream 0 ----
    wsplit_kernel<<<dim3(1024, 1, 3), 256>>>(Wv, Wp, Wout);
    cudaEventRecord(e_ws, 0);
    cudaStreamWaitEvent(s1, e_ws, 0);
    asplit_kernel<<<dim3(32768, 1, 2), 256>>>(src, pos, slopes, 1);        // pos,slopes
    asplit_kernel<<<dim3(32768, 1, 1), 256, 0, s1>>>(src, pos, slopes, 0); // src (s1)
    hmma_gemm_kernel<<<dim3(4, 128, 2), 256, SMEM_GEMM>>>(                 // pproj,sproj
        pA0, pA1, pA2, pWvT, pWpT, pWpT, pvalue, ppproj, psproj, 1);
    cudaEventRecord(e_s, 0);
    projsplit_kernel<<<32, 256>>>(proj);
    qkprep_kernel<<<32768, 256>>>(scale, offs);
    fourier_hmma_kernel<<<dim3(1, Rv / 128, 2), 256, SMEM_GEMM>>>(qdst, kdst);
    cudaEventRecord(e_qk, 0);

    // ---- stream 1: value + norms + kvs + kvsT ----
    hmma_gemm_kernel<<<dim3(4, 128, 1), 256, SMEM_GEMM, s1>>>(
        pA0, pA1, pA2, pWvT, pWpT, pWpT, pvalue, ppproj, psproj, 0);       // value
    cudaStreamWaitEvent(s1, e_s, 0);
    norms_kernel<<<Rv / 256, 256, 0, s1>>>();
    cudaStreamWaitEvent(s1, e_qk, 0);
    kvs_kernel<<<dim3(16, Bv * Hv), 256, 0, s1>>>(kdst);
    kvsT_kernel<<<2048, 256, 0, s1>>>();
    cudaEventRecord(e_kvs, s1);

    // ---- join ----
    cudaStreamWaitEvent(0, e_kvs, 0);
    av_hmma_kernel<<<dim3(Nv / 128, Bv * Hv), 256, SMEM_AV>>>();
    hmma_gemm_kernel<<<dim3(4, 128, 1), 256, SMEM_GEMM>>>(
        pAv, pAv, pAv, pWoT, pWoT, pWoT, out, out, out, 0);
}